// round 1
// baseline (speedup 1.0000x reference)
#include <cuda_runtime.h>
#include <math.h>

// Problem constants
#define BATCH   2
#define SEQ     2048
#define HID     1024
#define NH      16
#define HD      64
#define BH      (BATCH*NH)     // 32
#define MTOK    (BATCH*SEQ)    // 4096
#define QKV_N   (3*HID)        // 3072

// Scratch (device globals; no allocation allowed)
static __device__ float g_qkv[MTOK * QKV_N];                 // 50 MB
static __device__ float g_q[BH * SEQ * HD];                  // 16 MB
static __device__ float g_k[BH * SEQ * HD];                  // 16 MB
static __device__ float g_v[BH * SEQ * HD];                  // 16 MB
static __device__ float g_scores[(size_t)BH * SEQ * SEQ];    // 537 MB
static __device__ float g_nc[BH * SEQ];
static __device__ float g_invnc[BH * SEQ];
static __device__ float g_oh[MTOK * HID];                    // 16 MB

// ---------------------------------------------------------------------------
// Generic fp32 GEMM:  C[M,N] = A[M,K] @ B[N,K]^T + bias[N]
// BM=BN=128, BK=8, 256 threads, 8x8 per thread.
// Requires M%128==0, N%128==0, K%8==0 (true for all our shapes).
// ---------------------------------------------------------------------------
__global__ __launch_bounds__(256)
void sgemm_nt_kernel(const float* __restrict__ A,
                     const float* __restrict__ B,
                     const float* __restrict__ bias,
                     float* __restrict__ C,
                     int Mdim, int Ndim, int Kdim)
{
    __shared__ float As[8][128];
    __shared__ float Bs[8][128];
    const int tid  = threadIdx.x;
    const int lrow = tid >> 1;           // 0..127
    const int lk   = (tid & 1) * 4;      // 0 or 4
    const int ty   = tid >> 4;           // 0..15
    const int tx   = tid & 15;           // 0..15

    const float* Ap = A + (size_t)(blockIdx.y * 128 + lrow) * Kdim + lk;
    const float* Bp = B + (size_t)(blockIdx.x * 128 + lrow) * Kdim + lk;

    float acc[8][8];
    #pragma unroll
    for (int i = 0; i < 8; i++)
        #pragma unroll
        for (int j = 0; j < 8; j++) acc[i][j] = 0.f;

    for (int k0 = 0; k0 < Kdim; k0 += 8) {
        float4 av = *(const float4*)(Ap + k0);
        float4 bv = *(const float4*)(Bp + k0);
        As[lk+0][lrow] = av.x; As[lk+1][lrow] = av.y;
        As[lk+2][lrow] = av.z; As[lk+3][lrow] = av.w;
        Bs[lk+0][lrow] = bv.x; Bs[lk+1][lrow] = bv.y;
        Bs[lk+2][lrow] = bv.z; Bs[lk+3][lrow] = bv.w;
        __syncthreads();
        #pragma unroll
        for (int kk = 0; kk < 8; kk++) {
            float4 a0 = *(const float4*)&As[kk][ty*8];
            float4 a1 = *(const float4*)&As[kk][ty*8+4];
            float4 b0 = *(const float4*)&Bs[kk][tx*8];
            float4 b1 = *(const float4*)&Bs[kk][tx*8+4];
            float am[8] = {a0.x,a0.y,a0.z,a0.w,a1.x,a1.y,a1.z,a1.w};
            float bn[8] = {b0.x,b0.y,b0.z,b0.w,b1.x,b1.y,b1.z,b1.w};
            #pragma unroll
            for (int i = 0; i < 8; i++)
                #pragma unroll
                for (int j = 0; j < 8; j++)
                    acc[i][j] += am[i] * bn[j];
        }
        __syncthreads();
    }

    const int crow = blockIdx.y * 128 + ty * 8;
    const int ccol = blockIdx.x * 128 + tx * 8;
    #pragma unroll
    for (int i = 0; i < 8; i++) {
        float* cp = C + (size_t)(crow + i) * Ndim + ccol;
        #pragma unroll
        for (int j = 0; j < 8; j++) cp[j] = acc[i][j] + bias[ccol + j];
    }
}

// ---------------------------------------------------------------------------
// Per-(token, head) l2-normalize q and k, split into head-major [BH,S,HD].
// One block per token (4096), 16 warps = 16 heads, 2 elems/lane.
// ---------------------------------------------------------------------------
__global__ __launch_bounds__(512)
void norm_split_kernel()
{
    const int token = blockIdx.x;            // 0..4095
    const int h     = threadIdx.x >> 5;      // warp -> head
    const int lane  = threadIdx.x & 31;
    const int b     = token >> 11;
    const int sidx  = token & (SEQ - 1);

    const float* row = g_qkv + (size_t)token * QKV_N;
    const size_t obase = ((size_t)(b * NH + h) * SEQ + sidx) * HD;

    // q
    {
        float2 v = *(const float2*)(row + h * HD + lane * 2);
        float ss = v.x * v.x + v.y * v.y;
        #pragma unroll
        for (int o = 16; o > 0; o >>= 1) ss += __shfl_xor_sync(0xffffffffu, ss, o);
        float inv = 1.f / fmaxf(sqrtf(ss), 1e-12f);
        *(float2*)(g_q + obase + lane * 2) = make_float2(v.x * inv, v.y * inv);
    }
    // k
    {
        float2 v = *(const float2*)(row + HID + h * HD + lane * 2);
        float ss = v.x * v.x + v.y * v.y;
        #pragma unroll
        for (int o = 16; o > 0; o >>= 1) ss += __shfl_xor_sync(0xffffffffu, ss, o);
        float inv = 1.f / fmaxf(sqrtf(ss), 1e-12f);
        *(float2*)(g_k + obase + lane * 2) = make_float2(v.x * inv, v.y * inv);
    }
    // v (copy only)
    {
        float2 v = *(const float2*)(row + 2 * HID + h * HD + lane * 2);
        *(float2*)(g_v + obase + lane * 2) = v;
    }
}

__global__ void zero_nc_kernel()
{
    g_nc[blockIdx.x * 256 + threadIdx.x] = 0.f;
}

__global__ void invnc_kernel()
{
    const int i = blockIdx.x * 256 + threadIdx.x;
    g_invnc[i] = 1.f / g_nc[i];
}

// ---------------------------------------------------------------------------
// Pass A: per (bh, s-tile, t-tile) compute 128x128 score tile:
//   score = (1 + acos(clip(q.k)))^{-3.2}
// Store to g_scores, atomically accumulate column sums into g_nc.
// BK=16 over HD=64. 256 threads, 8x8 per thread.
// ---------------------------------------------------------------------------
__global__ __launch_bounds__(256)
void score_kernel()
{
    const int bh = blockIdx.z;
    const int s0 = blockIdx.y * 128;
    const int t0 = blockIdx.x * 128;
    const float* Q  = g_q + (size_t)bh * SEQ * HD;
    const float* Kp = g_k + (size_t)bh * SEQ * HD;

    __shared__ float Qs[16][128];
    __shared__ float Ks[16][128];
    __shared__ float csum[128];

    const int tid = threadIdx.x;
    const int ty = tid >> 4, tx = tid & 15;

    if (tid < 128) csum[tid] = 0.f;

    float acc[8][8];
    #pragma unroll
    for (int i = 0; i < 8; i++)
        #pragma unroll
        for (int j = 0; j < 8; j++) acc[i][j] = 0.f;

    for (int k0 = 0; k0 < HD; k0 += 16) {
        #pragma unroll
        for (int q = 0; q < 2; q++) {
            int f  = tid * 2 + q;         // 0..511
            int r  = f >> 2;              // 0..127
            int kq = (f & 3) * 4;         // 0,4,8,12
            float4 qv = *(const float4*)(Q  + (size_t)(s0 + r) * HD + k0 + kq);
            float4 kv = *(const float4*)(Kp + (size_t)(t0 + r) * HD + k0 + kq);
            Qs[kq+0][r] = qv.x; Qs[kq+1][r] = qv.y; Qs[kq+2][r] = qv.z; Qs[kq+3][r] = qv.w;
            Ks[kq+0][r] = kv.x; Ks[kq+1][r] = kv.y; Ks[kq+2][r] = kv.z; Ks[kq+3][r] = kv.w;
        }
        __syncthreads();
        #pragma unroll
        for (int kk = 0; kk < 16; kk++) {
            float4 a0 = *(const float4*)&Qs[kk][ty*8];
            float4 a1 = *(const float4*)&Qs[kk][ty*8+4];
            float4 b0 = *(const float4*)&Ks[kk][tx*8];
            float4 b1 = *(const float4*)&Ks[kk][tx*8+4];
            float am[8] = {a0.x,a0.y,a0.z,a0.w,a1.x,a1.y,a1.z,a1.w};
            float bn[8] = {b0.x,b0.y,b0.z,b0.w,b1.x,b1.y,b1.z,b1.w};
            #pragma unroll
            for (int i = 0; i < 8; i++)
                #pragma unroll
                for (int j = 0; j < 8; j++)
                    acc[i][j] += am[i] * bn[j];
        }
        __syncthreads();
    }

    float colpart[8];
    #pragma unroll
    for (int j = 0; j < 8; j++) colpart[j] = 0.f;

    float* srow = g_scores + (size_t)bh * SEQ * SEQ;
    #pragma unroll
    for (int i = 0; i < 8; i++) {
        float sc[8];
        #pragma unroll
        for (int j = 0; j < 8; j++) {
            float c = acc[i][j];
            c = fminf(fmaxf(c, -1.f + 1e-7f), 1.f - 1e-7f);
            float g = acosf(c);
            float s = __powf(1.f + g, -3.2f);   // exp2(-3.2*log2(1+g)) via MUFU
            sc[j] = s;
            colpart[j] += s;
        }
        float* p = srow + (size_t)(s0 + ty * 8 + i) * SEQ + t0 + tx * 8;
        *(float4*)(p)     = make_float4(sc[0], sc[1], sc[2], sc[3]);
        *(float4*)(p + 4) = make_float4(sc[4], sc[5], sc[6], sc[7]);
    }

    // reduce column partials: shared atomics then one global atomic per column
    #pragma unroll
    for (int j = 0; j < 8; j++)
        atomicAdd(&csum[tx * 8 + j], colpart[j]);
    __syncthreads();
    if (tid < 128)
        atomicAdd(&g_nc[bh * SEQ + t0 + tid], csum[tid]);
}

// ---------------------------------------------------------------------------
// Pass B: per (bh, s-tile of 128):
//   num[s,d]  = sum_t score[s,t]*invnc[t]*v[t,d]
//   den[s]    = sum_t score[s,t]*invnc[t]
//   oh[b,s,h*64+d] = num/den
// K-tiles of 32. 256 threads: 8 rows x 4 cols per thread.
// ---------------------------------------------------------------------------
__global__ __launch_bounds__(256)
void pv_kernel()
{
    const int s0 = blockIdx.x * 128;
    const int bh = blockIdx.y;
    const int b  = bh >> 4, h = bh & 15;

    __shared__ float Ss[32][128];
    __shared__ float Vs[32][64];
    __shared__ float ws[32];
    __shared__ float rs[128];

    const int tid = threadIdx.x;
    const int ty = tid >> 4, tx = tid & 15;
    if (tid < 128) rs[tid] = 0.f;

    const float* sbase = g_scores + (size_t)bh * SEQ * SEQ;
    const float* vbase = g_v + (size_t)bh * SEQ * HD;
    const float* wbase = g_invnc + bh * SEQ;

    float acc[8][4];
    #pragma unroll
    for (int i = 0; i < 8; i++)
        #pragma unroll
        for (int j = 0; j < 4; j++) acc[i][j] = 0.f;

    for (int kt = 0; kt < SEQ; kt += 32) {
        if (tid < 32) ws[tid] = wbase[kt + tid];
        {   // scores tile: 128 rows x 32 cols, transposed into Ss[k][row]
            int r  = tid >> 1;
            int ks = (tid & 1) * 16;
            const float* p = sbase + (size_t)(s0 + r) * SEQ + kt + ks;
            float4 v0 = *(const float4*)(p);
            float4 v1 = *(const float4*)(p + 4);
            float4 v2 = *(const float4*)(p + 8);
            float4 v3 = *(const float4*)(p + 12);
            Ss[ks+0 ][r] = v0.x; Ss[ks+1 ][r] = v0.y; Ss[ks+2 ][r] = v0.z; Ss[ks+3 ][r] = v0.w;
            Ss[ks+4 ][r] = v1.x; Ss[ks+5 ][r] = v1.y; Ss[ks+6 ][r] = v1.z; Ss[ks+7 ][r] = v1.w;
            Ss[ks+8 ][r] = v2.x; Ss[ks+9 ][r] = v2.y; Ss[ks+10][r] = v2.z; Ss[ks+11][r] = v2.w;
            Ss[ks+12][r] = v3.x; Ss[ks+13][r] = v3.y; Ss[ks+14][r] = v3.z; Ss[ks+15][r] = v3.w;
        }
        {   // V tile: 32 rows x 64 cols
            int r  = tid >> 3;
            int d0 = (tid & 7) * 8;
            const float* p = vbase + (size_t)(kt + r) * HD + d0;
            *(float4*)&Vs[r][d0]     = *(const float4*)(p);
            *(float4*)&Vs[r][d0 + 4] = *(const float4*)(p + 4);
        }
        __syncthreads();

        if (tid < 128) {
            float r = 0.f;
            #pragma unroll
            for (int k = 0; k < 32; k++) r += Ss[k][tid] * ws[k];
            rs[tid] += r;
        }
        #pragma unroll
        for (int k = 0; k < 32; k++) {
            float w = ws[k];
            float4 a0 = *(const float4*)&Ss[k][ty*8];
            float4 a1 = *(const float4*)&Ss[k][ty*8+4];
            float4 b0 = *(const float4*)&Vs[k][tx*4];
            float am[8] = {a0.x,a0.y,a0.z,a0.w,a1.x,a1.y,a1.z,a1.w};
            float bw[4] = {b0.x*w, b0.y*w, b0.z*w, b0.w*w};
            #pragma unroll
            for (int i = 0; i < 8; i++)
                #pragma unroll
                for (int j = 0; j < 4; j++)
                    acc[i][j] += am[i] * bw[j];
        }
        __syncthreads();
    }

    #pragma unroll
    for (int i = 0; i < 8; i++) {
        int srow = s0 + ty * 8 + i;
        float inv = 1.f / fmaxf(rs[ty * 8 + i], 1e-12f);
        float* op = g_oh + (size_t)(b * SEQ + srow) * HID + h * HD + tx * 4;
        #pragma unroll
        for (int j = 0; j < 4; j++) op[j] = acc[i][j] * inv;
    }
}

// ---------------------------------------------------------------------------
extern "C" void kernel_launch(void* const* d_in, const int* in_sizes, int n_in,
                              void* d_out, int out_size)
{
    const float* x      = (const float*)d_in[0];
    const float* w_qkv  = (const float*)d_in[1];
    const float* b_qkv  = (const float*)d_in[2];
    const float* w_out  = (const float*)d_in[3];
    const float* b_out  = (const float*)d_in[4];
    float* out = (float*)d_out;

    void* p_qkv = nullptr;
    void* p_oh  = nullptr;
    cudaGetSymbolAddress(&p_qkv, g_qkv);
    cudaGetSymbolAddress(&p_oh,  g_oh);

    // 1) qkv = x @ w_qkv^T + b_qkv      [4096,3072]
    sgemm_nt_kernel<<<dim3(QKV_N/128, MTOK/128), 256>>>(
        x, w_qkv, b_qkv, (float*)p_qkv, MTOK, QKV_N, HID);

    // 2) l2norm + head split
    norm_split_kernel<<<MTOK, 512>>>();

    // 3) scores + column sums
    zero_nc_kernel<<<(BH*SEQ)/256, 256>>>();
    score_kernel<<<dim3(SEQ/128, SEQ/128, BH), 256>>>();

    // 4) invert column sums
    invnc_kernel<<<(BH*SEQ)/256, 256>>>();

    // 5) normalized PV contraction -> out_heads [B,S,H]
    pv_kernel<<<dim3(SEQ/128, BH), 256>>>();

    // 6) out = oh @ w_out^T + b_out
    sgemm_nt_kernel<<<dim3(HID/128, MTOK/128), 256>>>(
        (const float*)p_oh, w_out, b_out, out, MTOK, HID, HID);
}

// round 3
// speedup vs baseline: 1.7858x; 1.7858x over previous
#include <cuda_runtime.h>
#include <math.h>
#include <stdint.h>

// Problem constants
#define BATCH   2
#define SEQ     2048
#define HID     1024
#define NH      16
#define HD      64
#define BH      (BATCH*NH)     // 32
#define MTOK    (BATCH*SEQ)    // 4096
#define QKV_N   (3*HID)        // 3072

// Scratch (device globals; no allocation allowed)
static __device__ float g_qkv[MTOK * QKV_N];                 // 50 MB
static __device__ float g_q[BH * SEQ * HD];                  // 16 MB
static __device__ float g_k[BH * SEQ * HD];                  // 16 MB
static __device__ float g_v[BH * SEQ * HD];                  // 16 MB
static __device__ float g_scores[(size_t)BH * SEQ * SEQ];    // 537 MB
static __device__ float g_nc[BH * SEQ];
static __device__ float g_invnc[BH * SEQ];
static __device__ float g_oh[MTOK * HID];                    // 16 MB

// ---------------------------------------------------------------------------
// mma.sync tf32 primitives (legacy HMMA path; works on plain sm_100 target)
// ---------------------------------------------------------------------------
__device__ __forceinline__ uint32_t f2tf(float x) {
    uint32_t r;
    asm("cvt.rna.tf32.f32 %0, %1;" : "=r"(r) : "f"(x));
    return r;
}

// D += A(16x8) @ B(8x8);  A row-major, B col-major. Fragment layout (lane l,
// g=l>>2, c=l&3): a0=(g,c) a1=(g+8,c) a2=(g,c+4) a3=(g+8,c+4);
// b0=(k=c,n=g) b1=(k=c+4,n=g); d0=(g,2c) d1=(g,2c+1) d2=(g+8,2c) d3=(g+8,2c+1)
__device__ __forceinline__ void mma8(float* d, const uint32_t* a, const uint32_t* b) {
    asm volatile(
        "mma.sync.aligned.m16n8k8.row.col.f32.tf32.tf32.f32 "
        "{%0,%1,%2,%3}, {%4,%5,%6,%7}, {%8,%9}, {%0,%1,%2,%3};"
        : "+f"(d[0]), "+f"(d[1]), "+f"(d[2]), "+f"(d[3])
        : "r"(a[0]), "r"(a[1]), "r"(a[2]), "r"(a[3]), "r"(b[0]), "r"(b[1]));
}

__device__ __forceinline__ uint32_t smem_u32(const void* p) {
    uint32_t a;
    asm("{ .reg .u64 t; cvta.to.shared.u64 t, %1; cvt.u32.u64 %0, t; }"
        : "=r"(a) : "l"(p));
    return a;
}
__device__ __forceinline__ void cp16(uint32_t s, const void* g) {
    asm volatile("cp.async.cg.shared.global [%0], [%1], 16;" :: "r"(s), "l"(g));
}
#define CP_COMMIT() asm volatile("cp.async.commit_group;" ::: "memory")
#define CP_WAIT1()  asm volatile("cp.async.wait_group 1;" ::: "memory")
#define CP_WAIT0()  asm volatile("cp.async.wait_group 0;" ::: "memory")

// ---------------------------------------------------------------------------
// Projection GEMM:  C[M,N] = A[M,K] @ B[N,K]^T + bias[N]
// Block tile 128x128, BK=32, 8 warps (2x4), warp tile 64x32.
// Blocks with blockIdx.x >= split_from use tf32x2 (split-A) for precision.
// smem: A0[128][36] B0 A1 B1 + bias  (pitch 36 -> conflict-free frag LDS)
// ---------------------------------------------------------------------------
#define GP 36
__global__ __launch_bounds__(256)
void mma_gemm_kernel(const float* __restrict__ A, const float* __restrict__ B,
                     const float* __restrict__ bias, float* __restrict__ C,
                     int Ndim, int Kdim, int split_from)
{
    extern __shared__ float sm[];
    float* smAbuf[2] = { sm,        sm + 9216 };
    float* smBbuf[2] = { sm + 4608, sm + 13824 };
    float* sbias = sm + 18432;

    const int tid = threadIdx.x, wid = tid >> 5, lane = tid & 31;
    const int g = lane >> 2, c = lane & 3;
    const int wm = (wid >> 2) * 64, wn = (wid & 3) * 32;
    const bool split = (int)blockIdx.x >= split_from;

    if (tid < 128) sbias[tid] = bias[blockIdx.x * 128 + tid];

    const float* Ab = A + (size_t)(blockIdx.y * 128) * Kdim;
    const float* Bb = B + (size_t)(blockIdx.x * 128) * Kdim;
    const uint32_t uA[2] = { smem_u32(smAbuf[0]), smem_u32(smAbuf[1]) };
    const uint32_t uB[2] = { smem_u32(smBbuf[0]), smem_u32(smBbuf[1]) };
    const int nk = Kdim >> 5;

    auto load = [&](int k, int bf) {
        const int k0 = k * 32;
        #pragma unroll
        for (int it = 0; it < 4; it++) {
            int idx = it * 256 + tid;     // 1024 float4s
            int r = idx >> 3, c4 = idx & 7;
            cp16(uA[bf] + (uint32_t)(r * GP + c4 * 4) * 4,
                 Ab + (size_t)r * Kdim + k0 + c4 * 4);
        }
        #pragma unroll
        for (int it = 0; it < 4; it++) {
            int idx = it * 256 + tid;
            int r = idx >> 3, c4 = idx & 7;
            cp16(uB[bf] + (uint32_t)(r * GP + c4 * 4) * 4,
                 Bb + (size_t)r * Kdim + k0 + c4 * 4);
        }
    };

    float acc[4][4][4];
    #pragma unroll
    for (int i = 0; i < 4; i++)
        #pragma unroll
        for (int j = 0; j < 4; j++)
            #pragma unroll
            for (int v = 0; v < 4; v++) acc[i][j][v] = 0.f;

    load(0, 0); CP_COMMIT();
    load(1, 1); CP_COMMIT();

    for (int k = 0; k < nk; k++) {
        CP_WAIT1();
        __syncthreads();
        const float* a_ = smAbuf[k & 1];
        const float* b_ = smBbuf[k & 1];
        #pragma unroll
        for (int s = 0; s < 4; s++) {
            uint32_t ah[4][4], al[4][4], bb[4][2];
            #pragma unroll
            for (int mt = 0; mt < 4; mt++) {
                #pragma unroll
                for (int i = 0; i < 4; i++) {
                    int row = wm + mt * 16 + g + (i & 1) * 8;
                    int col = s * 8 + c + (i >> 1) * 4;
                    float v = a_[row * GP + col];
                    ah[mt][i] = f2tf(v);
                    if (split) al[mt][i] = f2tf(v - __uint_as_float(ah[mt][i]));
                }
            }
            #pragma unroll
            for (int nt = 0; nt < 4; nt++) {
                int n = wn + nt * 8 + g;
                bb[nt][0] = f2tf(b_[n * GP + s * 8 + c]);
                bb[nt][1] = f2tf(b_[n * GP + s * 8 + c + 4]);
            }
            #pragma unroll
            for (int mt = 0; mt < 4; mt++)
                #pragma unroll
                for (int nt = 0; nt < 4; nt++) {
                    mma8(acc[mt][nt], ah[mt], bb[nt]);
                    if (split) mma8(acc[mt][nt], al[mt], bb[nt]);
                }
        }
        __syncthreads();
        if (k + 2 < nk) load(k + 2, k & 1);
        CP_COMMIT();
    }

    #pragma unroll
    for (int mt = 0; mt < 4; mt++) {
        int r0 = blockIdx.y * 128 + wm + mt * 16 + g;
        #pragma unroll
        for (int nt = 0; nt < 4; nt++) {
            int lc = wn + nt * 8 + 2 * c;
            int col = blockIdx.x * 128 + lc;
            float b0 = sbias[lc], b1 = sbias[lc + 1];
            float* p0 = C + (size_t)r0 * Ndim + col;
            float* p1 = C + (size_t)(r0 + 8) * Ndim + col;
            p0[0] = acc[mt][nt][0] + b0; p0[1] = acc[mt][nt][1] + b1;
            p1[0] = acc[mt][nt][2] + b0; p1[1] = acc[mt][nt][3] + b1;
        }
    }
}

// ---------------------------------------------------------------------------
// l2-normalize q,k per (token,head); split to head-major [BH,S,HD]
// ---------------------------------------------------------------------------
__global__ __launch_bounds__(512)
void norm_split_kernel()
{
    const int token = blockIdx.x;
    const int h     = threadIdx.x >> 5;
    const int lane  = threadIdx.x & 31;
    const int b     = token >> 11;
    const int sidx  = token & (SEQ - 1);

    const float* row = g_qkv + (size_t)token * QKV_N;
    const size_t obase = ((size_t)(b * NH + h) * SEQ + sidx) * HD;

    {
        float2 v = *(const float2*)(row + h * HD + lane * 2);
        float ss = v.x * v.x + v.y * v.y;
        #pragma unroll
        for (int o = 16; o > 0; o >>= 1) ss += __shfl_xor_sync(0xffffffffu, ss, o);
        float inv = 1.f / fmaxf(sqrtf(ss), 1e-12f);
        *(float2*)(g_q + obase + lane * 2) = make_float2(v.x * inv, v.y * inv);
    }
    {
        float2 v = *(const float2*)(row + HID + h * HD + lane * 2);
        float ss = v.x * v.x + v.y * v.y;
        #pragma unroll
        for (int o = 16; o > 0; o >>= 1) ss += __shfl_xor_sync(0xffffffffu, ss, o);
        float inv = 1.f / fmaxf(sqrtf(ss), 1e-12f);
        *(float2*)(g_k + obase + lane * 2) = make_float2(v.x * inv, v.y * inv);
    }
    {
        float2 v = *(const float2*)(row + 2 * HID + h * HD + lane * 2);
        *(float2*)(g_v + obase + lane * 2) = v;
    }
}

__global__ void zero_nc_kernel() { g_nc[blockIdx.x * 256 + threadIdx.x] = 0.f; }
__global__ void invnc_kernel()
{
    const int i = blockIdx.x * 256 + threadIdx.x;
    g_invnc[i] = 1.f / g_nc[i];
}

// ---------------------------------------------------------------------------
// Score pass: 128x128 tile of (1+acos(clip(q.k)))^{-3.2} via mma tf32,
// store to g_scores + column sums to g_nc (shfl-reduced + global atomics).
// smem: Qs[128][68], Ks[128][68]
// ---------------------------------------------------------------------------
#define SP 68
__global__ __launch_bounds__(256)
void score_kernel()
{
    extern __shared__ float sm[];
    float* Qs = sm;
    float* Ks = sm + 8704;

    const int bh = blockIdx.z;
    const int s0 = blockIdx.y * 128, t0 = blockIdx.x * 128;
    const int tid = threadIdx.x, wid = tid >> 5, lane = tid & 31;
    const int g = lane >> 2, c = lane & 3;
    const int wm = (wid >> 2) * 64, wn = (wid & 3) * 32;
    const float* Q  = g_q + (size_t)bh * SEQ * HD;
    const float* Kp = g_k + (size_t)bh * SEQ * HD;
    const uint32_t uQ = smem_u32(Qs), uK = smem_u32(Ks);

    #pragma unroll
    for (int it = 0; it < 8; it++) {
        int idx = it * 256 + tid;          // 2048 float4s each
        int r = idx >> 4, c4 = idx & 15;
        cp16(uQ + (uint32_t)(r * SP + c4 * 4) * 4, Q  + (size_t)(s0 + r) * HD + c4 * 4);
        cp16(uK + (uint32_t)(r * SP + c4 * 4) * 4, Kp + (size_t)(t0 + r) * HD + c4 * 4);
    }
    CP_COMMIT(); CP_WAIT0();
    __syncthreads();

    float acc[4][4][4];
    #pragma unroll
    for (int i = 0; i < 4; i++)
        #pragma unroll
        for (int j = 0; j < 4; j++)
            #pragma unroll
            for (int v = 0; v < 4; v++) acc[i][j][v] = 0.f;

    #pragma unroll
    for (int s = 0; s < 8; s++) {
        uint32_t ah[4][4], bb[4][2];
        #pragma unroll
        for (int mt = 0; mt < 4; mt++) {
            #pragma unroll
            for (int i = 0; i < 4; i++) {
                int row = wm + mt * 16 + g + (i & 1) * 8;
                int col = s * 8 + c + (i >> 1) * 4;
                ah[mt][i] = f2tf(Qs[row * SP + col]);
            }
        }
        #pragma unroll
        for (int nt = 0; nt < 4; nt++) {
            int n = wn + nt * 8 + g;
            bb[nt][0] = f2tf(Ks[n * SP + s * 8 + c]);
            bb[nt][1] = f2tf(Ks[n * SP + s * 8 + c + 4]);
        }
        #pragma unroll
        for (int mt = 0; mt < 4; mt++)
            #pragma unroll
            for (int nt = 0; nt < 4; nt++)
                mma8(acc[mt][nt], ah[mt], bb[nt]);
    }

    float cs[8];
    #pragma unroll
    for (int j = 0; j < 8; j++) cs[j] = 0.f;

    float* srow = g_scores + (size_t)bh * SEQ * SEQ;
    #pragma unroll
    for (int mt = 0; mt < 4; mt++) {
        int r0 = s0 + wm + mt * 16 + g;
        #pragma unroll
        for (int nt = 0; nt < 4; nt++) {
            int col = t0 + wn + nt * 8 + 2 * c;
            float o[4];
            #pragma unroll
            for (int v = 0; v < 4; v++) {
                float cc = fminf(fmaxf(acc[mt][nt][v], -1.f + 1e-7f), 1.f - 1e-7f);
                o[v] = __powf(1.f + acosf(cc), -3.2f);
            }
            *(float2*)(srow + (size_t)r0 * SEQ + col)       = make_float2(o[0], o[1]);
            *(float2*)(srow + (size_t)(r0 + 8) * SEQ + col) = make_float2(o[2], o[3]);
            cs[nt * 2]     += o[0] + o[2];
            cs[nt * 2 + 1] += o[1] + o[3];
        }
    }
    #pragma unroll
    for (int j = 0; j < 8; j++) {
        cs[j] += __shfl_xor_sync(0xffffffffu, cs[j], 4);
        cs[j] += __shfl_xor_sync(0xffffffffu, cs[j], 8);
        cs[j] += __shfl_xor_sync(0xffffffffu, cs[j], 16);
    }
    if (lane < 4) {
        #pragma unroll
        for (int nt = 0; nt < 4; nt++) {
            atomicAdd(&g_nc[bh * SEQ + t0 + wn + nt * 8 + 2 * lane],     cs[nt * 2]);
            atomicAdd(&g_nc[bh * SEQ + t0 + wn + nt * 8 + 2 * lane + 1], cs[nt * 2 + 1]);
        }
    }
}

// ---------------------------------------------------------------------------
// PV pass: num = (S .* w_col) @ V, den = row-sum(S .* w_col), out = num/den
// mma tf32, cp.async double-buffered over 64 k-tiles of 32.
// smem: S0[128][36] S1 V0[32][72] V1 w0[32] w1[32] rs[128]
// ---------------------------------------------------------------------------
#define PS 36
#define PVP 72
__global__ __launch_bounds__(256)
void pv_kernel()
{
    extern __shared__ float sm[];
    float* Sbuf[2] = { sm, sm + 4608 };
    float* Vbuf[2] = { sm + 9216, sm + 11520 };
    float* wbuf[2] = { sm + 13824, sm + 13856 };
    float* rs      = sm + 13888;

    const int s0 = blockIdx.x * 128, bh = blockIdx.y;
    const int b = bh >> 4, h = bh & 15;
    const int tid = threadIdx.x, wid = tid >> 5, lane = tid & 31;
    const int g = lane >> 2, c = lane & 3;
    const int wm = (wid >> 1) * 32, wn = (wid & 1) * 32;

    const float* sbase = g_scores + (size_t)bh * SEQ * SEQ + (size_t)s0 * SEQ;
    const float* vbase = g_v + (size_t)bh * SEQ * HD;
    const float* wbase = g_invnc + bh * SEQ;

    const uint32_t uS[2] = { smem_u32(Sbuf[0]), smem_u32(Sbuf[1]) };
    const uint32_t uV[2] = { smem_u32(Vbuf[0]), smem_u32(Vbuf[1]) };
    const uint32_t uW[2] = { smem_u32(wbuf[0]), smem_u32(wbuf[1]) };

    auto load = [&](int it, int bf) {
        const int kt = it * 32;
        #pragma unroll
        for (int q = 0; q < 4; q++) {
            int idx = q * 256 + tid;       // 1024 float4s of S
            int r = idx >> 3, c4 = idx & 7;
            cp16(uS[bf] + (uint32_t)(r * PS + c4 * 4) * 4,
                 sbase + (size_t)r * SEQ + kt + c4 * 4);
        }
        #pragma unroll
        for (int q = 0; q < 2; q++) {
            int idx = q * 256 + tid;       // 512 float4s of V
            int r = idx >> 4, c4 = idx & 15;
            cp16(uV[bf] + (uint32_t)(r * PVP + c4 * 4) * 4,
                 vbase + (size_t)(kt + r) * HD + c4 * 4);
        }
        if (tid < 8) cp16(uW[bf] + tid * 16, wbase + kt + tid * 4);
    };

    float acc[2][4][4];
    #pragma unroll
    for (int i = 0; i < 2; i++)
        #pragma unroll
        for (int j = 0; j < 4; j++)
            #pragma unroll
            for (int v = 0; v < 4; v++) acc[i][j][v] = 0.f;
    float rsum = 0.f;
    const int rrow = tid >> 1, rkh = (tid & 1) * 16;

    load(0, 0); CP_COMMIT();
    load(1, 1); CP_COMMIT();

    for (int it = 0; it < 64; it++) {
        CP_WAIT1();
        __syncthreads();
        const float* S_ = Sbuf[it & 1];
        const float* V_ = Vbuf[it & 1];
        const float* w_ = wbuf[it & 1];

        // denominator partials (float4, conflict-light)
        {
            const float4* Sr = (const float4*)(S_ + rrow * PS + rkh);
            const float4* wr = (const float4*)(w_ + rkh);
            #pragma unroll
            for (int j = 0; j < 4; j++) {
                float4 sv = Sr[j], wv = wr[j];
                rsum += sv.x * wv.x + sv.y * wv.y + sv.z * wv.z + sv.w * wv.w;
            }
        }
        #pragma unroll
        for (int s = 0; s < 4; s++) {
            float w0 = w_[s * 8 + c], w1 = w_[s * 8 + c + 4];
            uint32_t ah[2][4], bb[4][2];
            #pragma unroll
            for (int mt = 0; mt < 2; mt++) {
                int row = wm + mt * 16 + g;
                ah[mt][0] = f2tf(S_[row * PS + s * 8 + c] * w0);
                ah[mt][1] = f2tf(S_[(row + 8) * PS + s * 8 + c] * w0);
                ah[mt][2] = f2tf(S_[row * PS + s * 8 + c + 4] * w1);
                ah[mt][3] = f2tf(S_[(row + 8) * PS + s * 8 + c + 4] * w1);
            }
            #pragma unroll
            for (int nt = 0; nt < 4; nt++) {
                int n = wn + nt * 8 + g;
                bb[nt][0] = f2tf(V_[(s * 8 + c) * PVP + n]);
                bb[nt][1] = f2tf(V_[(s * 8 + c + 4) * PVP + n]);
            }
            #pragma unroll
            for (int mt = 0; mt < 2; mt++)
                #pragma unroll
                for (int nt = 0; nt < 4; nt++)
                    mma8(acc[mt][nt], ah[mt], bb[nt]);
        }
        __syncthreads();
        if (it + 2 < 64) load(it + 2, it & 1);
        CP_COMMIT();
    }

    rsum += __shfl_xor_sync(0xffffffffu, rsum, 1);
    if ((tid & 1) == 0) rs[rrow] = rsum;
    __syncthreads();

    #pragma unroll
    for (int mt = 0; mt < 2; mt++) {
        int row = wm + mt * 16 + g;
        float i0 = 1.f / fmaxf(rs[row], 1e-12f);
        float i1 = 1.f / fmaxf(rs[row + 8], 1e-12f);
        int gr0 = b * SEQ + s0 + row;
        #pragma unroll
        for (int nt = 0; nt < 4; nt++) {
            int col = h * HD + wn + nt * 8 + 2 * c;
            float* p0 = g_oh + (size_t)gr0 * HID + col;
            float* p1 = g_oh + (size_t)(gr0 + 8) * HID + col;
            p0[0] = acc[mt][nt][0] * i0; p0[1] = acc[mt][nt][1] * i0;
            p1[0] = acc[mt][nt][2] * i1; p1[1] = acc[mt][nt][3] * i1;
        }
    }
}

// ---------------------------------------------------------------------------
extern "C" void kernel_launch(void* const* d_in, const int* in_sizes, int n_in,
                              void* d_out, int out_size)
{
    const float* x      = (const float*)d_in[0];
    const float* w_qkv  = (const float*)d_in[1];
    const float* b_qkv  = (const float*)d_in[2];
    const float* w_out  = (const float*)d_in[3];
    const float* b_out  = (const float*)d_in[4];
    float* out = (float*)d_out;

    void* p_qkv = nullptr;
    void* p_oh  = nullptr;
    cudaGetSymbolAddress(&p_qkv, g_qkv);
    cudaGetSymbolAddress(&p_oh,  g_oh);

    const int GEMM_SMEM  = 74240;   // (4*4608 + 128) floats
    const int SCORE_SMEM = 69632;   // 2*128*68 floats
    const int PV_SMEM    = 56064;   // 14016 floats
    static int attr_set = 0;
    if (!attr_set) {
        cudaFuncSetAttribute(mma_gemm_kernel,
                             cudaFuncAttributeMaxDynamicSharedMemorySize, GEMM_SMEM);
        cudaFuncSetAttribute(score_kernel,
                             cudaFuncAttributeMaxDynamicSharedMemorySize, SCORE_SMEM);
        cudaFuncSetAttribute(pv_kernel,
                             cudaFuncAttributeMaxDynamicSharedMemorySize, PV_SMEM);
        attr_set = 1;
    }

    // 1) qkv = x @ w_qkv^T + b_qkv   (tf32x1 for q/k cols, tf32x2 for v cols)
    mma_gemm_kernel<<<dim3(QKV_N/128, MTOK/128), 256, GEMM_SMEM>>>(
        x, w_qkv, b_qkv, (float*)p_qkv, QKV_N, HID, 16);

    // 2) l2norm + head split
    norm_split_kernel<<<MTOK, 512>>>();

    // 3) scores + column sums
    zero_nc_kernel<<<(BH*SEQ)/256, 256>>>();
    score_kernel<<<dim3(SEQ/128, SEQ/128, BH), 256, SCORE_SMEM>>>();

    // 4) invert column sums
    invnc_kernel<<<(BH*SEQ)/256, 256>>>();

    // 5) normalized PV contraction -> out_heads [B,S,H]
    pv_kernel<<<dim3(SEQ/128, BH), 256, PV_SMEM>>>();

    // 6) out = oh @ w_out^T + b_out   (tf32x2)
    mma_gemm_kernel<<<dim3(HID/128, MTOK/128), 256, GEMM_SMEM>>>(
        (const float*)p_oh, w_out, b_out, out, HID, HID, 0);
}

// round 4
// speedup vs baseline: 2.0280x; 1.1357x over previous
#include <cuda_runtime.h>
#include <cuda_fp16.h>
#include <math.h>
#include <stdint.h>

// Problem constants
#define BATCH   2
#define SEQ     2048
#define HID     1024
#define NH      16
#define HD      64
#define BH      (BATCH*NH)     // 32
#define MTOK    (BATCH*SEQ)    // 4096
#define QKV_N   (3*HID)        // 3072

// Scratch (device globals; no allocation allowed)
static __device__ float  g_qkv[MTOK * QKV_N];                  // 50 MB
static __device__ float  g_q[BH * SEQ * HD];                   // 16 MB
static __device__ float  g_k[BH * SEQ * HD];                   // 16 MB
static __device__ float  g_v[BH * SEQ * HD];                   // 16 MB
static __device__ __half g_scores_h[(size_t)BH * SEQ * SEQ];   // 268 MB
static __device__ __half g_vwT[(size_t)BH * 72 * SEQ];         // 9.4 MB
static __device__ float  g_nc[BH * SEQ];
static __device__ float  g_invnc[BH * SEQ];
static __device__ float  g_oh[MTOK * HID];                     // 16 MB

// ---------------------------------------------------------------------------
// mma.sync primitives (legacy HMMA path; works on plain sm_100 target)
// ---------------------------------------------------------------------------
__device__ __forceinline__ uint32_t f2tf(float x) {
    uint32_t r;
    asm("cvt.rna.tf32.f32 %0, %1;" : "=r"(r) : "f"(x));
    return r;
}

// tf32: D += A(16x8) @ B(8x8)
__device__ __forceinline__ void mma8(float* d, const uint32_t* a, const uint32_t* b) {
    asm volatile(
        "mma.sync.aligned.m16n8k8.row.col.f32.tf32.tf32.f32 "
        "{%0,%1,%2,%3}, {%4,%5,%6,%7}, {%8,%9}, {%0,%1,%2,%3};"
        : "+f"(d[0]), "+f"(d[1]), "+f"(d[2]), "+f"(d[3])
        : "r"(a[0]), "r"(a[1]), "r"(a[2]), "r"(a[3]), "r"(b[0]), "r"(b[1]));
}

// f16: D += A(16x16) @ B(16x8), fp32 accum
__device__ __forceinline__ void mma16(float* d, const uint32_t* a, const uint32_t* b) {
    asm volatile(
        "mma.sync.aligned.m16n8k16.row.col.f32.f16.f16.f32 "
        "{%0,%1,%2,%3}, {%4,%5,%6,%7}, {%8,%9}, {%0,%1,%2,%3};"
        : "+f"(d[0]), "+f"(d[1]), "+f"(d[2]), "+f"(d[3])
        : "r"(a[0]), "r"(a[1]), "r"(a[2]), "r"(a[3]), "r"(b[0]), "r"(b[1]));
}

__device__ __forceinline__ uint32_t smem_u32(const void* p) {
    uint32_t a;
    asm("{ .reg .u64 t; cvta.to.shared.u64 t, %1; cvt.u32.u64 %0, t; }"
        : "=r"(a) : "l"(p));
    return a;
}
__device__ __forceinline__ void cp16(uint32_t s, const void* g) {
    asm volatile("cp.async.cg.shared.global [%0], [%1], 16;" :: "r"(s), "l"(g));
}
#define CP_COMMIT() asm volatile("cp.async.commit_group;" ::: "memory")
#define CP_WAIT1()  asm volatile("cp.async.wait_group 1;" ::: "memory")
#define CP_WAIT0()  asm volatile("cp.async.wait_group 0;" ::: "memory")

// Fast (1 + acos(clip(x)))^{-3.2}: Hastings 8-term acos (|err|<=2e-8) + powf
__device__ __forceinline__ float spfns_score(float x) {
    float cc = fminf(fmaxf(x, -1.f + 1e-7f), 1.f - 1e-7f);
    float ax = fabsf(cc);
    float p =              -0.0012624911f;
    p = fmaf(p, ax,         0.0066700901f);
    p = fmaf(p, ax,        -0.0170881256f);
    p = fmaf(p, ax,         0.0308918810f);
    p = fmaf(p, ax,        -0.0501743046f);
    p = fmaf(p, ax,         0.0889789874f);
    p = fmaf(p, ax,        -0.2145988016f);
    p = fmaf(p, ax,         1.5707963050f);
    float s;
    asm("sqrt.approx.f32 %0, %1;" : "=f"(s) : "f"(1.f - ax));
    float r = s * p;
    r = (cc < 0.f) ? (3.14159265358979f - r) : r;
    return __powf(1.f + r, -3.2f);
}

// ---------------------------------------------------------------------------
// Projection GEMM:  C[M,N] = A[M,K] @ B[N,K]^T + bias[N]   (unchanged, passing)
// ---------------------------------------------------------------------------
#define GP 36
__global__ __launch_bounds__(256)
void mma_gemm_kernel(const float* __restrict__ A, const float* __restrict__ B,
                     const float* __restrict__ bias, float* __restrict__ C,
                     int Ndim, int Kdim, int split_from)
{
    extern __shared__ float sm[];
    float* smAbuf[2] = { sm,        sm + 9216 };
    float* smBbuf[2] = { sm + 4608, sm + 13824 };
    float* sbias = sm + 18432;

    const int tid = threadIdx.x, wid = tid >> 5, lane = tid & 31;
    const int g = lane >> 2, c = lane & 3;
    const int wm = (wid >> 2) * 64, wn = (wid & 3) * 32;
    const bool split = (int)blockIdx.x >= split_from;

    if (tid < 128) sbias[tid] = bias[blockIdx.x * 128 + tid];

    const float* Ab = A + (size_t)(blockIdx.y * 128) * Kdim;
    const float* Bb = B + (size_t)(blockIdx.x * 128) * Kdim;
    const uint32_t uA[2] = { smem_u32(smAbuf[0]), smem_u32(smAbuf[1]) };
    const uint32_t uB[2] = { smem_u32(smBbuf[0]), smem_u32(smBbuf[1]) };
    const int nk = Kdim >> 5;

    auto load = [&](int k, int bf) {
        const int k0 = k * 32;
        #pragma unroll
        for (int it = 0; it < 4; it++) {
            int idx = it * 256 + tid;
            int r = idx >> 3, c4 = idx & 7;
            cp16(uA[bf] + (uint32_t)(r * GP + c4 * 4) * 4,
                 Ab + (size_t)r * Kdim + k0 + c4 * 4);
        }
        #pragma unroll
        for (int it = 0; it < 4; it++) {
            int idx = it * 256 + tid;
            int r = idx >> 3, c4 = idx & 7;
            cp16(uB[bf] + (uint32_t)(r * GP + c4 * 4) * 4,
                 Bb + (size_t)r * Kdim + k0 + c4 * 4);
        }
    };

    float acc[4][4][4];
    #pragma unroll
    for (int i = 0; i < 4; i++)
        #pragma unroll
        for (int j = 0; j < 4; j++)
            #pragma unroll
            for (int v = 0; v < 4; v++) acc[i][j][v] = 0.f;

    load(0, 0); CP_COMMIT();
    load(1, 1); CP_COMMIT();

    for (int k = 0; k < nk; k++) {
        CP_WAIT1();
        __syncthreads();
        const float* a_ = smAbuf[k & 1];
        const float* b_ = smBbuf[k & 1];
        #pragma unroll
        for (int s = 0; s < 4; s++) {
            uint32_t ah[4][4], al[4][4], bb[4][2];
            #pragma unroll
            for (int mt = 0; mt < 4; mt++) {
                #pragma unroll
                for (int i = 0; i < 4; i++) {
                    int row = wm + mt * 16 + g + (i & 1) * 8;
                    int col = s * 8 + c + (i >> 1) * 4;
                    float v = a_[row * GP + col];
                    ah[mt][i] = f2tf(v);
                    if (split) al[mt][i] = f2tf(v - __uint_as_float(ah[mt][i]));
                }
            }
            #pragma unroll
            for (int nt = 0; nt < 4; nt++) {
                int n = wn + nt * 8 + g;
                bb[nt][0] = f2tf(b_[n * GP + s * 8 + c]);
                bb[nt][1] = f2tf(b_[n * GP + s * 8 + c + 4]);
            }
            #pragma unroll
            for (int mt = 0; mt < 4; mt++)
                #pragma unroll
                for (int nt = 0; nt < 4; nt++) {
                    mma8(acc[mt][nt], ah[mt], bb[nt]);
                    if (split) mma8(acc[mt][nt], al[mt], bb[nt]);
                }
        }
        __syncthreads();
        if (k + 2 < nk) load(k + 2, k & 1);
        CP_COMMIT();
    }

    #pragma unroll
    for (int mt = 0; mt < 4; mt++) {
        int r0 = blockIdx.y * 128 + wm + mt * 16 + g;
        #pragma unroll
        for (int nt = 0; nt < 4; nt++) {
            int lc = wn + nt * 8 + 2 * c;
            int col = blockIdx.x * 128 + lc;
            float b0 = sbias[lc], b1 = sbias[lc + 1];
            float* p0 = C + (size_t)r0 * Ndim + col;
            float* p1 = C + (size_t)(r0 + 8) * Ndim + col;
            p0[0] = acc[mt][nt][0] + b0; p0[1] = acc[mt][nt][1] + b1;
            p1[0] = acc[mt][nt][2] + b0; p1[1] = acc[mt][nt][3] + b1;
        }
    }
}

// ---------------------------------------------------------------------------
// l2-normalize q,k per (token,head); split to head-major [BH,S,HD]
// ---------------------------------------------------------------------------
__global__ __launch_bounds__(512)
void norm_split_kernel()
{
    const int token = blockIdx.x;
    const int h     = threadIdx.x >> 5;
    const int lane  = threadIdx.x & 31;
    const int b     = token >> 11;
    const int sidx  = token & (SEQ - 1);

    const float* row = g_qkv + (size_t)token * QKV_N;
    const size_t obase = ((size_t)(b * NH + h) * SEQ + sidx) * HD;

    {
        float2 v = *(const float2*)(row + h * HD + lane * 2);
        float ss = v.x * v.x + v.y * v.y;
        #pragma unroll
        for (int o = 16; o > 0; o >>= 1) ss += __shfl_xor_sync(0xffffffffu, ss, o);
        float inv = 1.f / fmaxf(sqrtf(ss), 1e-12f);
        *(float2*)(g_q + obase + lane * 2) = make_float2(v.x * inv, v.y * inv);
    }
    {
        float2 v = *(const float2*)(row + HID + h * HD + lane * 2);
        float ss = v.x * v.x + v.y * v.y;
        #pragma unroll
        for (int o = 16; o > 0; o >>= 1) ss += __shfl_xor_sync(0xffffffffu, ss, o);
        float inv = 1.f / fmaxf(sqrtf(ss), 1e-12f);
        *(float2*)(g_k + obase + lane * 2) = make_float2(v.x * inv, v.y * inv);
    }
    {
        float2 v = *(const float2*)(row + 2 * HID + h * HD + lane * 2);
        *(float2*)(g_v + obase + lane * 2) = v;
    }
}

__global__ void zero_nc_kernel() { g_nc[blockIdx.x * 256 + threadIdx.x] = 0.f; }
__global__ void invnc_kernel()
{
    const int i = blockIdx.x * 256 + threadIdx.x;
    g_invnc[i] = 1.f / g_nc[i];
}

// ---------------------------------------------------------------------------
// Score pass: 128x128 tile, mma tf32 + fast transcendental epilogue,
// fp16 stores + fp32 column sums to g_nc.
// ---------------------------------------------------------------------------
#define SP 68
__global__ __launch_bounds__(256)
void score_kernel()
{
    extern __shared__ float sm[];
    float* Qs = sm;
    float* Ks = sm + 8704;

    const int bh = blockIdx.z;
    const int s0 = blockIdx.y * 128, t0 = blockIdx.x * 128;
    const int tid = threadIdx.x, wid = tid >> 5, lane = tid & 31;
    const int g = lane >> 2, c = lane & 3;
    const int wm = (wid >> 2) * 64, wn = (wid & 3) * 32;
    const float* Q  = g_q + (size_t)bh * SEQ * HD;
    const float* Kp = g_k + (size_t)bh * SEQ * HD;
    const uint32_t uQ = smem_u32(Qs), uK = smem_u32(Ks);

    #pragma unroll
    for (int it = 0; it < 8; it++) {
        int idx = it * 256 + tid;
        int r = idx >> 4, c4 = idx & 15;
        cp16(uQ + (uint32_t)(r * SP + c4 * 4) * 4, Q  + (size_t)(s0 + r) * HD + c4 * 4);
        cp16(uK + (uint32_t)(r * SP + c4 * 4) * 4, Kp + (size_t)(t0 + r) * HD + c4 * 4);
    }
    CP_COMMIT(); CP_WAIT0();
    __syncthreads();

    float acc[4][4][4];
    #pragma unroll
    for (int i = 0; i < 4; i++)
        #pragma unroll
        for (int j = 0; j < 4; j++)
            #pragma unroll
            for (int v = 0; v < 4; v++) acc[i][j][v] = 0.f;

    #pragma unroll
    for (int s = 0; s < 8; s++) {
        uint32_t ah[4][4], bb[4][2];
        #pragma unroll
        for (int mt = 0; mt < 4; mt++) {
            #pragma unroll
            for (int i = 0; i < 4; i++) {
                int row = wm + mt * 16 + g + (i & 1) * 8;
                int col = s * 8 + c + (i >> 1) * 4;
                ah[mt][i] = f2tf(Qs[row * SP + col]);
            }
        }
        #pragma unroll
        for (int nt = 0; nt < 4; nt++) {
            int n = wn + nt * 8 + g;
            bb[nt][0] = f2tf(Ks[n * SP + s * 8 + c]);
            bb[nt][1] = f2tf(Ks[n * SP + s * 8 + c + 4]);
        }
        #pragma unroll
        for (int mt = 0; mt < 4; mt++)
            #pragma unroll
            for (int nt = 0; nt < 4; nt++)
                mma8(acc[mt][nt], ah[mt], bb[nt]);
    }

    float cs[8];
    #pragma unroll
    for (int j = 0; j < 8; j++) cs[j] = 0.f;

    __half* srow = g_scores_h + (size_t)bh * SEQ * SEQ;
    #pragma unroll
    for (int mt = 0; mt < 4; mt++) {
        int r0 = s0 + wm + mt * 16 + g;
        #pragma unroll
        for (int nt = 0; nt < 4; nt++) {
            int col = t0 + wn + nt * 8 + 2 * c;
            float o[4];
            #pragma unroll
            for (int v = 0; v < 4; v++) o[v] = spfns_score(acc[mt][nt][v]);
            *(__half2*)(srow + (size_t)r0 * SEQ + col)       = __floats2half2_rn(o[0], o[1]);
            *(__half2*)(srow + (size_t)(r0 + 8) * SEQ + col) = __floats2half2_rn(o[2], o[3]);
            cs[nt * 2]     += o[0] + o[2];
            cs[nt * 2 + 1] += o[1] + o[3];
        }
    }
    #pragma unroll
    for (int j = 0; j < 8; j++) {
        cs[j] += __shfl_xor_sync(0xffffffffu, cs[j], 4);
        cs[j] += __shfl_xor_sync(0xffffffffu, cs[j], 8);
        cs[j] += __shfl_xor_sync(0xffffffffu, cs[j], 16);
    }
    if (lane < 4) {
        #pragma unroll
        for (int nt = 0; nt < 4; nt++) {
            atomicAdd(&g_nc[bh * SEQ + t0 + wn + nt * 8 + 2 * lane],     cs[nt * 2]);
            atomicAdd(&g_nc[bh * SEQ + t0 + wn + nt * 8 + 2 * lane + 1], cs[nt * 2 + 1]);
        }
    }
}

// ---------------------------------------------------------------------------
// Build V'^T fp16: g_vwT[bh][d][t] = v[bh][t][d]*w[t] (d<64); w[t] (d=64);
// 0 (d=65..71). One block per (bh, 64-t chunk).
// ---------------------------------------------------------------------------
__global__ __launch_bounds__(256)
void build_vw_kernel()
{
    __shared__ float vt[64][65];
    const int bh = blockIdx.y, t0 = blockIdx.x * 64;
    const int tid = threadIdx.x;
    const float* vb = g_v + (size_t)bh * SEQ * HD;
    const float* w  = g_invnc + bh * SEQ;
    __half* outb = g_vwT + (size_t)bh * 72 * SEQ;

    #pragma unroll
    for (int q = 0; q < 4; q++) {
        int idx = q * 256 + tid;          // 1024 float4s
        int t = idx >> 4, d4 = (idx & 15) * 4;
        float4 v = *(const float4*)(vb + (size_t)(t0 + t) * HD + d4);
        vt[t][d4] = v.x; vt[t][d4+1] = v.y; vt[t][d4+2] = v.z; vt[t][d4+3] = v.w;
    }
    __syncthreads();

    #pragma unroll
    for (int q = 0; q < 8; q++) {
        int idx = q * 256 + tid;          // 2048 half2s
        int d = idx >> 5, p = (idx & 31) * 2;
        float w0 = w[t0 + p], w1 = w[t0 + p + 1];
        *(__half2*)(outb + (size_t)d * SEQ + t0 + p) =
            __floats2half2_rn(vt[p][d] * w0, vt[p + 1][d] * w1);
    }
    {
        int d = 64 + (tid >> 5), p = (tid & 31) * 2;
        __half2 h = (d == 64) ? __floats2half2_rn(w[t0 + p], w[t0 + p + 1])
                              : __floats2half2_rn(0.f, 0.f);
        *(__half2*)(outb + (size_t)d * SEQ + t0 + p) = h;
    }
}

// ---------------------------------------------------------------------------
// PV pass (fp16 HMMA): [128 x 2048] S-tile @ [2048 x 72] V' -> 72 cols where
// col 64 = denominator. out = num/den into g_oh.
// smem pitch 72 halves (conflict-free frags). Double-buffered BK=64.
// ---------------------------------------------------------------------------
#define PVP 72
__global__ __launch_bounds__(256)
void pv_kernel()
{
    extern __shared__ float smf[];
    __half* sh = (__half*)smf;
    __half* Sb[2] = { sh,         sh + 9216 };
    __half* Vb[2] = { sh + 18432, sh + 23616 };

    const int s0 = blockIdx.x * 128, bh = blockIdx.y;
    const int b = bh >> 4, h = bh & 15;
    const int tid = threadIdx.x, wid = tid >> 5, lane = tid & 31;
    const int g = lane >> 2, c = lane & 3;
    const int wm = wid * 16;

    const __half* sbase = g_scores_h + (size_t)bh * SEQ * SEQ + (size_t)s0 * SEQ;
    const __half* vwb   = g_vwT + (size_t)bh * 72 * SEQ;
    const uint32_t uS[2] = { smem_u32(Sb[0]), smem_u32(Sb[1]) };
    const uint32_t uV[2] = { smem_u32(Vb[0]), smem_u32(Vb[1]) };

    auto load = [&](int it, int bf) {
        const int kt = it * 64;
        #pragma unroll
        for (int q = 0; q < 4; q++) {
            int idx = q * 256 + tid;      // 1024 chunks of 16B
            int r = idx >> 3, c4 = idx & 7;
            cp16(uS[bf] + (uint32_t)(r * PVP + c4 * 8) * 2,
                 sbase + (size_t)r * SEQ + kt + c4 * 8);
        }
        #pragma unroll
        for (int q = 0; q < 3; q++) {
            int idx = q * 256 + tid;      // 576 chunks
            if (idx < 576) {
                int r = idx >> 3, c4 = idx & 7;
                cp16(uV[bf] + (uint32_t)(r * PVP + c4 * 8) * 2,
                     vwb + (size_t)r * SEQ + kt + c4 * 8);
            }
        }
    };

    float acc[9][4];
    #pragma unroll
    for (int i = 0; i < 9; i++)
        #pragma unroll
        for (int v = 0; v < 4; v++) acc[i][v] = 0.f;

    load(0, 0); CP_COMMIT();
    load(1, 1); CP_COMMIT();

    for (int it = 0; it < 32; it++) {
        CP_WAIT1();
        __syncthreads();
        const __half* S_ = Sb[it & 1];
        const __half* V_ = Vb[it & 1];
        #pragma unroll
        for (int ks = 0; ks < 4; ks++) {
            uint32_t a[4];
            a[0] = *(const uint32_t*)(S_ + (wm + g)     * PVP + ks * 16 + 2 * c);
            a[1] = *(const uint32_t*)(S_ + (wm + g + 8) * PVP + ks * 16 + 2 * c);
            a[2] = *(const uint32_t*)(S_ + (wm + g)     * PVP + ks * 16 + 2 * c + 8);
            a[3] = *(const uint32_t*)(S_ + (wm + g + 8) * PVP + ks * 16 + 2 * c + 8);
            #pragma unroll
            for (int nt = 0; nt < 9; nt++) {
                uint32_t bf[2];
                bf[0] = *(const uint32_t*)(V_ + (nt * 8 + g) * PVP + ks * 16 + 2 * c);
                bf[1] = *(const uint32_t*)(V_ + (nt * 8 + g) * PVP + ks * 16 + 2 * c + 8);
                mma16(acc[nt], a, bf);
            }
        }
        __syncthreads();
        if (it + 2 < 32) load(it + 2, it & 1);
        CP_COMMIT();
    }

    // denominator = n-tile 8, col offset 0 (held by lanes with c==0)
    const int base = lane & ~3;
    float den0 = __shfl_sync(0xffffffffu, acc[8][0], base);
    float den1 = __shfl_sync(0xffffffffu, acc[8][2], base);
    float i0 = 1.f / fmaxf(den0, 1e-12f);
    float i1 = 1.f / fmaxf(den1, 1e-12f);

    const int gr = b * SEQ + s0 + wm + g;
    #pragma unroll
    for (int nt = 0; nt < 8; nt++) {
        float* p0 = g_oh + (size_t)gr * HID + h * HD + nt * 8 + 2 * c;
        float* p1 = g_oh + (size_t)(gr + 8) * HID + h * HD + nt * 8 + 2 * c;
        p0[0] = acc[nt][0] * i0; p0[1] = acc[nt][1] * i0;
        p1[0] = acc[nt][2] * i1; p1[1] = acc[nt][3] * i1;
    }
}

// ---------------------------------------------------------------------------
extern "C" void kernel_launch(void* const* d_in, const int* in_sizes, int n_in,
                              void* d_out, int out_size)
{
    const float* x      = (const float*)d_in[0];
    const float* w_qkv  = (const float*)d_in[1];
    const float* b_qkv  = (const float*)d_in[2];
    const float* w_out  = (const float*)d_in[3];
    const float* b_out  = (const float*)d_in[4];
    float* out = (float*)d_out;

    void* p_qkv = nullptr;
    void* p_oh  = nullptr;
    cudaGetSymbolAddress(&p_qkv, g_qkv);
    cudaGetSymbolAddress(&p_oh,  g_oh);

    const int GEMM_SMEM  = 74240;   // (4*4608 + 128) floats
    const int SCORE_SMEM = 69632;   // 2*128*68 floats
    const int PV_SMEM    = 57600;   // 28800 halves
    static int attr_set = 0;
    if (!attr_set) {
        cudaFuncSetAttribute(mma_gemm_kernel,
                             cudaFuncAttributeMaxDynamicSharedMemorySize, GEMM_SMEM);
        cudaFuncSetAttribute(score_kernel,
                             cudaFuncAttributeMaxDynamicSharedMemorySize, SCORE_SMEM);
        cudaFuncSetAttribute(pv_kernel,
                             cudaFuncAttributeMaxDynamicSharedMemorySize, PV_SMEM);
        attr_set = 1;
    }

    // 1) qkv = x @ w_qkv^T + b_qkv   (tf32x1 for q/k cols, tf32x2 for v cols)
    mma_gemm_kernel<<<dim3(QKV_N/128, MTOK/128), 256, GEMM_SMEM>>>(
        x, w_qkv, b_qkv, (float*)p_qkv, QKV_N, HID, 16);

    // 2) l2norm + head split
    norm_split_kernel<<<MTOK, 512>>>();

    // 3) scores (fp16) + column sums
    zero_nc_kernel<<<(BH*SEQ)/256, 256>>>();
    score_kernel<<<dim3(SEQ/128, SEQ/128, BH), 256, SCORE_SMEM>>>();

    // 4) invert column sums, build V' = [w*V | w | 0] transposed, fp16
    invnc_kernel<<<(BH*SEQ)/256, 256>>>();
    build_vw_kernel<<<dim3(SEQ/64, BH), 256>>>();

    // 5) PV fp16 GEMM with fused denominator -> g_oh
    pv_kernel<<<dim3(SEQ/128, BH), 256, PV_SMEM>>>();

    // 6) out = oh @ w_out^T + b_out   (tf32x2)
    mma_gemm_kernel<<<dim3(HID/128, MTOK/128), 256, GEMM_SMEM>>>(
        (const float*)p_oh, w_out, b_out, out, HID, HID, 0);
}

// round 6
// speedup vs baseline: 4.0063x; 1.9755x over previous
#include <cuda_runtime.h>
#include <cuda_fp16.h>
#include <math.h>
#include <stdint.h>

// Problem constants
#define BATCH   2
#define SEQ     2048
#define HID     1024
#define NH      16
#define HD      64
#define BH      (BATCH*NH)     // 32
#define MTOK    (BATCH*SEQ)    // 4096
#define QKV_N   (3*HID)        // 3072

// Scratch (device globals; no allocation allowed)
static __device__ __half g_xh[MTOK * HID];                     // 8 MB
static __device__ __half g_wqkvh[QKV_N * HID];                 // 6 MB
static __device__ __half g_wouth[HID * HID];                   // 2 MB
static __device__ float  g_qkv[MTOK * QKV_N];                  // 50 MB
static __device__ __half g_qh[BH * SEQ * HD];                  // 8 MB
static __device__ __half g_kh[BH * SEQ * HD];                  // 8 MB
static __device__ float  g_v[BH * SEQ * HD];                   // 16 MB
static __device__ __half g_scores_h[(size_t)BH * SEQ * SEQ];   // 268 MB
static __device__ __half g_vwT[(size_t)BH * 72 * SEQ];         // 9.4 MB
static __device__ float  g_nc[BH * SEQ];
static __device__ __half g_ohh[MTOK * HID];                    // 8 MB

// ---------------------------------------------------------------------------
// mma.sync fp16 primitive (legacy HMMA; valid on plain sm_100 target)
// D(16x8,f32) += A(16x16,f16) @ B(16x8,f16)
// a0=(g,2c..2c+1) a1=(g+8,..) a2=(g,2c+8..) a3=(g+8,2c+8..)
// b0=(k=2c..2c+1,n=g) b1=(k=2c+8..,n=g); d0=(g,2c) d1=(g,2c+1) d2/d3=g+8
// ---------------------------------------------------------------------------
__device__ __forceinline__ void mma16(float* d, const uint32_t* a, const uint32_t* b) {
    asm volatile(
        "mma.sync.aligned.m16n8k16.row.col.f32.f16.f16.f32 "
        "{%0,%1,%2,%3}, {%4,%5,%6,%7}, {%8,%9}, {%0,%1,%2,%3};"
        : "+f"(d[0]), "+f"(d[1]), "+f"(d[2]), "+f"(d[3])
        : "r"(a[0]), "r"(a[1]), "r"(a[2]), "r"(a[3]), "r"(b[0]), "r"(b[1]));
}

__device__ __forceinline__ uint32_t smem_u32(const void* p) {
    uint32_t a;
    asm("{ .reg .u64 t; cvta.to.shared.u64 t, %1; cvt.u32.u64 %0, t; }"
        : "=r"(a) : "l"(p));
    return a;
}
__device__ __forceinline__ void cp16(uint32_t s, const void* g) {
    asm volatile("cp.async.cg.shared.global [%0], [%1], 16;" :: "r"(s), "l"(g));
}
#define CP_COMMIT() asm volatile("cp.async.commit_group;" ::: "memory")
#define CP_WAIT1()  asm volatile("cp.async.wait_group 1;" ::: "memory")
#define CP_WAIT0()  asm volatile("cp.async.wait_group 0;" ::: "memory")

// Fast (1 + acos(clip(x)))^{-3.2}: Hastings 8-term acos (|err|<=2e-8) + powf
__device__ __forceinline__ float spfns_score(float x) {
    float cc = fminf(fmaxf(x, -1.f + 1e-7f), 1.f - 1e-7f);
    float ax = fabsf(cc);
    float p =              -0.0012624911f;
    p = fmaf(p, ax,         0.0066700901f);
    p = fmaf(p, ax,        -0.0170881256f);
    p = fmaf(p, ax,         0.0308918810f);
    p = fmaf(p, ax,        -0.0501743046f);
    p = fmaf(p, ax,         0.0889789874f);
    p = fmaf(p, ax,        -0.2145988016f);
    p = fmaf(p, ax,         1.5707963050f);
    float s;
    asm("sqrt.approx.f32 %0, %1;" : "=f"(s) : "f"(1.f - ax));
    float r = s * p;
    r = (cc < 0.f) ? (3.14159265358979f - r) : r;
    return __powf(1.f + r, -3.2f);
}

// ---------------------------------------------------------------------------
// f32 -> f16 conversion, 8 elems/thread (n must be divisible by 2048)
// ---------------------------------------------------------------------------
__global__ __launch_bounds__(256)
void f2h_kernel(const float* __restrict__ src, __half* __restrict__ dst)
{
    size_t i = ((size_t)blockIdx.x * 256 + threadIdx.x) * 8;
    float4 v0 = *(const float4*)(src + i);
    float4 v1 = *(const float4*)(src + i + 4);
    __half2 h[4] = { __floats2half2_rn(v0.x, v0.y), __floats2half2_rn(v0.z, v0.w),
                     __floats2half2_rn(v1.x, v1.y), __floats2half2_rn(v1.z, v1.w) };
    *(uint4*)(dst + i) = *(uint4*)h;
}

// ---------------------------------------------------------------------------
// fp16 GEMM:  C[M,N](f32) = A[M,K](f16) @ B[N,K](f16)^T + bias[N](f32)
// Block 128x128, BK=64, 8 warps (2x4), warp tile 64x32. smem pitch 72 halves.
// ---------------------------------------------------------------------------
#define HP 72
__global__ __launch_bounds__(256)
void hgemm_kernel(const __half* __restrict__ A, const __half* __restrict__ B,
                  const float* __restrict__ bias, float* __restrict__ C,
                  int Ndim, int Kdim)
{
    extern __shared__ char smraw[];
    __half* sh = (__half*)smraw;
    __half* Ab_[2] = { sh,          sh + 18432 };
    __half* Bb_[2] = { sh + 9216,   sh + 27648 };
    float* sbias = (float*)(smraw + 73728);

    const int tid = threadIdx.x, wid = tid >> 5, lane = tid & 31;
    const int g = lane >> 2, c = lane & 3;
    const int wm = (wid >> 2) * 64, wn = (wid & 3) * 32;

    if (tid < 128) sbias[tid] = bias[blockIdx.x * 128 + tid];

    const __half* Ag = A + (size_t)(blockIdx.y * 128) * Kdim;
    const __half* Bg = B + (size_t)(blockIdx.x * 128) * Kdim;
    const uint32_t uA[2] = { smem_u32(Ab_[0]), smem_u32(Ab_[1]) };
    const uint32_t uB[2] = { smem_u32(Bb_[0]), smem_u32(Bb_[1]) };
    const int nk = Kdim >> 6;

    auto load = [&](int k, int bf) {
        const int k0 = k * 64;
        #pragma unroll
        for (int it = 0; it < 4; it++) {
            int idx = it * 256 + tid;      // 1024 16B chunks
            int r = idx >> 3, c8 = idx & 7;
            cp16(uA[bf] + (uint32_t)(r * HP + c8 * 8) * 2,
                 Ag + (size_t)r * Kdim + k0 + c8 * 8);
        }
        #pragma unroll
        for (int it = 0; it < 4; it++) {
            int idx = it * 256 + tid;
            int r = idx >> 3, c8 = idx & 7;
            cp16(uB[bf] + (uint32_t)(r * HP + c8 * 8) * 2,
                 Bg + (size_t)r * Kdim + k0 + c8 * 8);
        }
    };

    float acc[4][4][4];
    #pragma unroll
    for (int i = 0; i < 4; i++)
        #pragma unroll
        for (int j = 0; j < 4; j++)
            #pragma unroll
            for (int v = 0; v < 4; v++) acc[i][j][v] = 0.f;

    load(0, 0); CP_COMMIT();
    load(1, 1); CP_COMMIT();

    for (int k = 0; k < nk; k++) {
        CP_WAIT1();
        __syncthreads();
        const __half* A_ = Ab_[k & 1];
        const __half* B_ = Bb_[k & 1];
        #pragma unroll
        for (int ks = 0; ks < 4; ks++) {
            uint32_t a[4][4], b[4][2];
            #pragma unroll
            for (int mt = 0; mt < 4; mt++) {
                int row = wm + mt * 16 + g;
                a[mt][0] = *(const uint32_t*)(A_ + row * HP + ks * 16 + 2 * c);
                a[mt][1] = *(const uint32_t*)(A_ + (row + 8) * HP + ks * 16 + 2 * c);
                a[mt][2] = *(const uint32_t*)(A_ + row * HP + ks * 16 + 2 * c + 8);
                a[mt][3] = *(const uint32_t*)(A_ + (row + 8) * HP + ks * 16 + 2 * c + 8);
            }
            #pragma unroll
            for (int nt = 0; nt < 4; nt++) {
                int n = wn + nt * 8 + g;
                b[nt][0] = *(const uint32_t*)(B_ + n * HP + ks * 16 + 2 * c);
                b[nt][1] = *(const uint32_t*)(B_ + n * HP + ks * 16 + 2 * c + 8);
            }
            #pragma unroll
            for (int mt = 0; mt < 4; mt++)
                #pragma unroll
                for (int nt = 0; nt < 4; nt++)
                    mma16(acc[mt][nt], a[mt], b[nt]);
        }
        __syncthreads();
        if (k + 2 < nk) load(k + 2, k & 1);
        CP_COMMIT();
    }

    #pragma unroll
    for (int mt = 0; mt < 4; mt++) {
        int r0 = blockIdx.y * 128 + wm + mt * 16 + g;
        #pragma unroll
        for (int nt = 0; nt < 4; nt++) {
            int lc = wn + nt * 8 + 2 * c;
            int col = blockIdx.x * 128 + lc;
            float b0 = sbias[lc], b1 = sbias[lc + 1];
            float* p0 = C + (size_t)r0 * Ndim + col;
            float* p1 = C + (size_t)(r0 + 8) * Ndim + col;
            p0[0] = acc[mt][nt][0] + b0; p0[1] = acc[mt][nt][1] + b1;
            p1[0] = acc[mt][nt][2] + b0; p1[1] = acc[mt][nt][3] + b1;
        }
    }
}

// ---------------------------------------------------------------------------
// l2-normalize q,k per (token,head) -> fp16 head-major; v -> fp32 head-major
// ---------------------------------------------------------------------------
__global__ __launch_bounds__(512)
void norm_split_kernel()
{
    const int token = blockIdx.x;
    const int h     = threadIdx.x >> 5;
    const int lane  = threadIdx.x & 31;
    const int b     = token >> 11;
    const int sidx  = token & (SEQ - 1);

    const float* row = g_qkv + (size_t)token * QKV_N;
    const size_t obase = ((size_t)(b * NH + h) * SEQ + sidx) * HD;

    {
        float2 v = *(const float2*)(row + h * HD + lane * 2);
        float ss = v.x * v.x + v.y * v.y;
        #pragma unroll
        for (int o = 16; o > 0; o >>= 1) ss += __shfl_xor_sync(0xffffffffu, ss, o);
        float inv = 1.f / fmaxf(sqrtf(ss), 1e-12f);
        *(__half2*)(g_qh + obase + lane * 2) = __floats2half2_rn(v.x * inv, v.y * inv);
    }
    {
        float2 v = *(const float2*)(row + HID + h * HD + lane * 2);
        float ss = v.x * v.x + v.y * v.y;
        #pragma unroll
        for (int o = 16; o > 0; o >>= 1) ss += __shfl_xor_sync(0xffffffffu, ss, o);
        float inv = 1.f / fmaxf(sqrtf(ss), 1e-12f);
        *(__half2*)(g_kh + obase + lane * 2) = __floats2half2_rn(v.x * inv, v.y * inv);
    }
    {
        float2 v = *(const float2*)(row + 2 * HID + h * HD + lane * 2);
        *(float2*)(g_v + obase + lane * 2) = v;
    }
}

__global__ void zero_nc_kernel() { g_nc[blockIdx.x * 256 + threadIdx.x] = 0.f; }

// ---------------------------------------------------------------------------
// Score pass (fp16 MMA): 128x128 tile of (1+acos(clip(q.k)))^{-3.2},
// fp16 stores + fp32 column sums to g_nc.
// ---------------------------------------------------------------------------
__global__ __launch_bounds__(256)
void score_kernel()
{
    extern __shared__ char smraw[];
    __half* Qs = (__half*)smraw;
    __half* Ks = Qs + 9216;

    const int bh = blockIdx.z;
    const int s0 = blockIdx.y * 128, t0 = blockIdx.x * 128;
    const int tid = threadIdx.x, wid = tid >> 5, lane = tid & 31;
    const int g = lane >> 2, c = lane & 3;
    const int wm = (wid >> 2) * 64, wn = (wid & 3) * 32;
    const __half* Q  = g_qh + (size_t)bh * SEQ * HD;
    const __half* Kp = g_kh + (size_t)bh * SEQ * HD;
    const uint32_t uQ = smem_u32(Qs), uK = smem_u32(Ks);

    #pragma unroll
    for (int it = 0; it < 4; it++) {
        int idx = it * 256 + tid;          // 1024 16B chunks each
        int r = idx >> 3, c8 = idx & 7;
        cp16(uQ + (uint32_t)(r * HP + c8 * 8) * 2, Q  + (size_t)(s0 + r) * HD + c8 * 8);
        cp16(uK + (uint32_t)(r * HP + c8 * 8) * 2, Kp + (size_t)(t0 + r) * HD + c8 * 8);
    }
    CP_COMMIT(); CP_WAIT0();
    __syncthreads();

    float acc[4][4][4];
    #pragma unroll
    for (int i = 0; i < 4; i++)
        #pragma unroll
        for (int j = 0; j < 4; j++)
            #pragma unroll
            for (int v = 0; v < 4; v++) acc[i][j][v] = 0.f;

    #pragma unroll
    for (int ks = 0; ks < 4; ks++) {
        uint32_t a[4][4], b[4][2];
        #pragma unroll
        for (int mt = 0; mt < 4; mt++) {
            int row = wm + mt * 16 + g;
            a[mt][0] = *(const uint32_t*)(Qs + row * HP + ks * 16 + 2 * c);
            a[mt][1] = *(const uint32_t*)(Qs + (row + 8) * HP + ks * 16 + 2 * c);
            a[mt][2] = *(const uint32_t*)(Qs + row * HP + ks * 16 + 2 * c + 8);
            a[mt][3] = *(const uint32_t*)(Qs + (row + 8) * HP + ks * 16 + 2 * c + 8);
        }
        #pragma unroll
        for (int nt = 0; nt < 4; nt++) {
            int n = wn + nt * 8 + g;
            b[nt][0] = *(const uint32_t*)(Ks + n * HP + ks * 16 + 2 * c);
            b[nt][1] = *(const uint32_t*)(Ks + n * HP + ks * 16 + 2 * c + 8);
        }
        #pragma unroll
        for (int mt = 0; mt < 4; mt++)
            #pragma unroll
            for (int nt = 0; nt < 4; nt++)
                mma16(acc[mt][nt], a[mt], b[nt]);
    }

    float cs[8];
    #pragma unroll
    for (int j = 0; j < 8; j++) cs[j] = 0.f;

    __half* srow = g_scores_h + (size_t)bh * SEQ * SEQ;
    #pragma unroll
    for (int mt = 0; mt < 4; mt++) {
        int r0 = s0 + wm + mt * 16 + g;
        #pragma unroll
        for (int nt = 0; nt < 4; nt++) {
            int col = t0 + wn + nt * 8 + 2 * c;
            float o[4];
            #pragma unroll
            for (int v = 0; v < 4; v++) o[v] = spfns_score(acc[mt][nt][v]);
            *(__half2*)(srow + (size_t)r0 * SEQ + col)       = __floats2half2_rn(o[0], o[1]);
            *(__half2*)(srow + (size_t)(r0 + 8) * SEQ + col) = __floats2half2_rn(o[2], o[3]);
            cs[nt * 2]     += o[0] + o[2];
            cs[nt * 2 + 1] += o[1] + o[3];
        }
    }
    #pragma unroll
    for (int j = 0; j < 8; j++) {
        cs[j] += __shfl_xor_sync(0xffffffffu, cs[j], 4);
        cs[j] += __shfl_xor_sync(0xffffffffu, cs[j], 8);
        cs[j] += __shfl_xor_sync(0xffffffffu, cs[j], 16);
    }
    if (lane < 4) {
        #pragma unroll
        for (int nt = 0; nt < 4; nt++) {
            atomicAdd(&g_nc[bh * SEQ + t0 + wn + nt * 8 + 2 * lane],     cs[nt * 2]);
            atomicAdd(&g_nc[bh * SEQ + t0 + wn + nt * 8 + 2 * lane + 1], cs[nt * 2 + 1]);
        }
    }
}

// ---------------------------------------------------------------------------
// Build V'^T fp16: g_vwT[bh][d][t] = v[t][d]/nc[t] (d<64); 1/nc[t] (d=64);
// 0 (d=65..71). One block per (bh, 64-t chunk).
// ---------------------------------------------------------------------------
__global__ __launch_bounds__(256)
void build_vw_kernel()
{
    __shared__ float vt[64][65];
    __shared__ float ws[64];
    const int bh = blockIdx.y, t0 = blockIdx.x * 64;
    const int tid = threadIdx.x;
    const float* vb = g_v + (size_t)bh * SEQ * HD;
    __half* outb = g_vwT + (size_t)bh * 72 * SEQ;

    if (tid < 64) ws[tid] = 1.f / g_nc[bh * SEQ + t0 + tid];
    #pragma unroll
    for (int q = 0; q < 4; q++) {
        int idx = q * 256 + tid;          // 1024 float4s
        int t = idx >> 4, d4 = (idx & 15) * 4;
        float4 v = *(const float4*)(vb + (size_t)(t0 + t) * HD + d4);
        vt[t][d4] = v.x; vt[t][d4+1] = v.y; vt[t][d4+2] = v.z; vt[t][d4+3] = v.w;
    }
    __syncthreads();

    #pragma unroll
    for (int q = 0; q < 8; q++) {
        int idx = q * 256 + tid;          // 2048 half2s
        int d = idx >> 5, p = (idx & 31) * 2;
        *(__half2*)(outb + (size_t)d * SEQ + t0 + p) =
            __floats2half2_rn(vt[p][d] * ws[p], vt[p + 1][d] * ws[p + 1]);
    }
    {
        int d = 64 + (tid >> 5), p = (tid & 31) * 2;
        __half2 h = (d == 64) ? __floats2half2_rn(ws[p], ws[p + 1])
                              : __floats2half2_rn(0.f, 0.f);
        *(__half2*)(outb + (size_t)d * SEQ + t0 + p) = h;
    }
}

// ---------------------------------------------------------------------------
// PV pass (fp16 HMMA): [128 x 2048] S-tile @ [2048 x 72] V' -> 72 cols, col
// 64 = denominator. out = num/den -> g_ohh (fp16).
// ---------------------------------------------------------------------------
#define PVP 72
__global__ __launch_bounds__(256)
void pv_kernel()
{
    extern __shared__ float smf[];
    __half* sh = (__half*)smf;
    __half* Sb[2] = { sh,         sh + 9216 };
    __half* Vb[2] = { sh + 18432, sh + 23616 };

    const int s0 = blockIdx.x * 128, bh = blockIdx.y;
    const int b = bh >> 4, h = bh & 15;
    const int tid = threadIdx.x, wid = tid >> 5, lane = tid & 31;
    const int g = lane >> 2, c = lane & 3;
    const int wm = wid * 16;

    const __half* sbase = g_scores_h + (size_t)bh * SEQ * SEQ + (size_t)s0 * SEQ;
    const __half* vwb   = g_vwT + (size_t)bh * 72 * SEQ;
    const uint32_t uS[2] = { smem_u32(Sb[0]), smem_u32(Sb[1]) };
    const uint32_t uV[2] = { smem_u32(Vb[0]), smem_u32(Vb[1]) };

    auto load = [&](int it, int bf) {
        const int kt = it * 64;
        #pragma unroll
        for (int q = 0; q < 4; q++) {
            int idx = q * 256 + tid;
            int r = idx >> 3, c4 = idx & 7;
            cp16(uS[bf] + (uint32_t)(r * PVP + c4 * 8) * 2,
                 sbase + (size_t)r * SEQ + kt + c4 * 8);
        }
        #pragma unroll
        for (int q = 0; q < 3; q++) {
            int idx = q * 256 + tid;
            if (idx < 576) {
                int r = idx >> 3, c4 = idx & 7;
                cp16(uV[bf] + (uint32_t)(r * PVP + c4 * 8) * 2,
                     vwb + (size_t)r * SEQ + kt + c4 * 8);
            }
        }
    };

    float acc[9][4];
    #pragma unroll
    for (int i = 0; i < 9; i++)
        #pragma unroll
        for (int v = 0; v < 4; v++) acc[i][v] = 0.f;

    load(0, 0); CP_COMMIT();
    load(1, 1); CP_COMMIT();

    for (int it = 0; it < 32; it++) {
        CP_WAIT1();
        __syncthreads();
        const __half* S_ = Sb[it & 1];
        const __half* V_ = Vb[it & 1];
        #pragma unroll
        for (int ks = 0; ks < 4; ks++) {
            uint32_t a[4];
            a[0] = *(const uint32_t*)(S_ + (wm + g)     * PVP + ks * 16 + 2 * c);
            a[1] = *(const uint32_t*)(S_ + (wm + g + 8) * PVP + ks * 16 + 2 * c);
            a[2] = *(const uint32_t*)(S_ + (wm + g)     * PVP + ks * 16 + 2 * c + 8);
            a[3] = *(const uint32_t*)(S_ + (wm + g + 8) * PVP + ks * 16 + 2 * c + 8);
            #pragma unroll
            for (int nt = 0; nt < 9; nt++) {
                uint32_t bf[2];
                bf[0] = *(const uint32_t*)(V_ + (nt * 8 + g) * PVP + ks * 16 + 2 * c);
                bf[1] = *(const uint32_t*)(V_ + (nt * 8 + g) * PVP + ks * 16 + 2 * c + 8);
                mma16(acc[nt], a, bf);
            }
        }
        __syncthreads();
        if (it + 2 < 32) load(it + 2, it & 1);
        CP_COMMIT();
    }

    const int base = lane & ~3;
    float den0 = __shfl_sync(0xffffffffu, acc[8][0], base);
    float den1 = __shfl_sync(0xffffffffu, acc[8][2], base);
    float i0 = 1.f / fmaxf(den0, 1e-12f);
    float i1 = 1.f / fmaxf(den1, 1e-12f);

    const int gr = b * SEQ + s0 + wm + g;
    #pragma unroll
    for (int nt = 0; nt < 8; nt++) {
        __half* p0 = g_ohh + (size_t)gr * HID + h * HD + nt * 8 + 2 * c;
        __half* p1 = g_ohh + (size_t)(gr + 8) * HID + h * HD + nt * 8 + 2 * c;
        *(__half2*)p0 = __floats2half2_rn(acc[nt][0] * i0, acc[nt][1] * i0);
        *(__half2*)p1 = __floats2half2_rn(acc[nt][2] * i1, acc[nt][3] * i1);
    }
}

// ---------------------------------------------------------------------------
extern "C" void kernel_launch(void* const* d_in, const int* in_sizes, int n_in,
                              void* d_out, int out_size)
{
    const float* x      = (const float*)d_in[0];
    const float* w_qkv  = (const float*)d_in[1];
    const float* b_qkv  = (const float*)d_in[2];
    const float* w_out  = (const float*)d_in[3];
    const float* b_out  = (const float*)d_in[4];
    float* out = (float*)d_out;

    void *p_xh = nullptr, *p_wqkvh = nullptr, *p_wouth = nullptr;
    void *p_qkv = nullptr, *p_ohh = nullptr;
    cudaGetSymbolAddress(&p_xh,    g_xh);
    cudaGetSymbolAddress(&p_wqkvh, g_wqkvh);
    cudaGetSymbolAddress(&p_wouth, g_wouth);
    cudaGetSymbolAddress(&p_qkv,   g_qkv);
    cudaGetSymbolAddress(&p_ohh,   g_ohh);

    const int GEMM_SMEM  = 74240;   // 4*18432 halves + 128 floats
    const int SCORE_SMEM = 36864;   // 2*128*72 halves
    const int PV_SMEM    = 57600;   // 28800 halves
    static int attr_set = 0;
    if (!attr_set) {
        cudaFuncSetAttribute(hgemm_kernel,
                             cudaFuncAttributeMaxDynamicSharedMemorySize, GEMM_SMEM);
        cudaFuncSetAttribute(score_kernel,
                             cudaFuncAttributeMaxDynamicSharedMemorySize, SCORE_SMEM);
        cudaFuncSetAttribute(pv_kernel,
                             cudaFuncAttributeMaxDynamicSharedMemorySize, PV_SMEM);
        attr_set = 1;
    }

    // 0) fp16 conversions of inputs
    f2h_kernel<<<(MTOK*HID)/2048, 256>>>(x, (__half*)p_xh);
    f2h_kernel<<<(QKV_N*HID)/2048, 256>>>(w_qkv, (__half*)p_wqkvh);
    f2h_kernel<<<(HID*HID)/2048, 256>>>(w_out, (__half*)p_wouth);

    // 1) qkv = x @ w_qkv^T + b_qkv  (fp16 HMMA, fp32 accum/out)
    hgemm_kernel<<<dim3(QKV_N/128, MTOK/128), 256, GEMM_SMEM>>>(
        (const __half*)p_xh, (const __half*)p_wqkvh, b_qkv, (float*)p_qkv,
        QKV_N, HID);

    // 2) l2norm + head split (q,k -> fp16; v -> fp32)
    norm_split_kernel<<<MTOK, 512>>>();

    // 3) scores (fp16 MMA) + column sums
    zero_nc_kernel<<<(BH*SEQ)/256, 256>>>();
    score_kernel<<<dim3(SEQ/128, SEQ/128, BH), 256, SCORE_SMEM>>>();

    // 4) build V' = [V/nc | 1/nc | 0] transposed, fp16
    build_vw_kernel<<<dim3(SEQ/64, BH), 256>>>();

    // 5) PV fp16 GEMM with fused denominator -> g_ohh (fp16)
    pv_kernel<<<dim3(SEQ/128, BH), 256, PV_SMEM>>>();

    // 6) out = oh @ w_out^T + b_out  (fp16 HMMA, fp32 out)
    hgemm_kernel<<<dim3(HID/128, MTOK/128), 256, GEMM_SMEM>>>(
        (const __half*)p_ohh, (const __half*)p_wouth, b_out, out, HID, HID);
}

// round 8
// speedup vs baseline: 4.2180x; 1.0528x over previous
#include <cuda_runtime.h>
#include <cuda_fp16.h>
#include <math.h>
#include <stdint.h>

// Problem constants
#define BATCH   2
#define SEQ     2048
#define HID     1024
#define NH      16
#define HD      64
#define BH      (BATCH*NH)     // 32
#define MTOK    (BATCH*SEQ)    // 4096
#define QKV_N   (3*HID)        // 3072

// Scratch (device globals; no allocation allowed)
static __device__ __half g_xh[MTOK * HID];                     // 8 MB
static __device__ __half g_wqkvh[QKV_N * HID];                 // 6 MB
static __device__ __half g_wouth[HID * HID];                   // 2 MB
static __device__ float  g_qkv[MTOK * QKV_N];                  // 50 MB
static __device__ __half g_qh[BH * SEQ * HD];                  // 8 MB
static __device__ __half g_kh[BH * SEQ * HD];                  // 8 MB
static __device__ float  g_v[BH * SEQ * HD];                   // 16 MB
static __device__ __half g_scores_h[(size_t)BH * SEQ * SEQ];   // 268 MB
static __device__ __half g_vwT[(size_t)BH * 72 * SEQ];         // 9.4 MB
static __device__ float  g_nc[BH * SEQ];
static __device__ __half g_ohh[MTOK * HID];                    // 8 MB

// ---------------------------------------------------------------------------
// mma.sync fp16 primitive (legacy HMMA; valid on plain sm_100 target)
// D(16x8,f32) += A(16x16,f16) @ B(16x8,f16)
// ---------------------------------------------------------------------------
__device__ __forceinline__ void mma16(float* d, const uint32_t* a, const uint32_t* b) {
    asm volatile(
        "mma.sync.aligned.m16n8k16.row.col.f32.f16.f16.f32 "
        "{%0,%1,%2,%3}, {%4,%5,%6,%7}, {%8,%9}, {%0,%1,%2,%3};"
        : "+f"(d[0]), "+f"(d[1]), "+f"(d[2]), "+f"(d[3])
        : "r"(a[0]), "r"(a[1]), "r"(a[2]), "r"(a[3]), "r"(b[0]), "r"(b[1]));
}

__device__ __forceinline__ uint32_t smem_u32(const void* p) {
    uint32_t a;
    asm("{ .reg .u64 t; cvta.to.shared.u64 t, %1; cvt.u32.u64 %0, t; }"
        : "=r"(a) : "l"(p));
    return a;
}
__device__ __forceinline__ void cp16(uint32_t s, const void* g) {
    asm volatile("cp.async.cg.shared.global [%0], [%1], 16;" :: "r"(s), "l"(g));
}
#define CP_COMMIT() asm volatile("cp.async.commit_group;" ::: "memory")
#define CP_WAIT1()  asm volatile("cp.async.wait_group 1;" ::: "memory")
#define CP_WAIT0()  asm volatile("cp.async.wait_group 0;" ::: "memory")

// Fast (1 + acos(clip(x)))^{-3.2}: Hastings 8-term acos (|err|<=2e-8) + powf
__device__ __forceinline__ float spfns_score(float x) {
    float cc = fminf(fmaxf(x, -1.f + 1e-7f), 1.f - 1e-7f);
    float ax = fabsf(cc);
    float p =              -0.0012624911f;
    p = fmaf(p, ax,         0.0066700901f);
    p = fmaf(p, ax,        -0.0170881256f);
    p = fmaf(p, ax,         0.0308918810f);
    p = fmaf(p, ax,        -0.0501743046f);
    p = fmaf(p, ax,         0.0889789874f);
    p = fmaf(p, ax,        -0.2145988016f);
    p = fmaf(p, ax,         1.5707963050f);
    float s;
    asm("sqrt.approx.f32 %0, %1;" : "=f"(s) : "f"(1.f - ax));
    float r = s * p;
    r = (cc < 0.f) ? (3.14159265358979f - r) : r;
    return __powf(1.f + r, -3.2f);
}

// ---------------------------------------------------------------------------
// f32 -> f16 conversion, 8 elems/thread (n must be divisible by 2048)
// ---------------------------------------------------------------------------
__global__ __launch_bounds__(256)
void f2h_kernel(const float* __restrict__ src, __half* __restrict__ dst)
{
    size_t i = ((size_t)blockIdx.x * 256 + threadIdx.x) * 8;
    float4 v0 = *(const float4*)(src + i);
    float4 v1 = *(const float4*)(src + i + 4);
    __half2 h[4] = { __floats2half2_rn(v0.x, v0.y), __floats2half2_rn(v0.z, v0.w),
                     __floats2half2_rn(v1.x, v1.y), __floats2half2_rn(v1.z, v1.w) };
    *(uint4*)(dst + i) = *(uint4*)h;
}

// ---------------------------------------------------------------------------
// fp16 GEMM:  C[M,N](f32) = A[M,K](f16) @ B[N,K](f16)^T + bias[N](f32)
// Block 128x128, BK=64, 8 warps (2x4), warp tile 64x32. smem pitch 72 halves.
// __launch_bounds__(256, 2): force <=128 regs so 2 CTAs co-reside per SM
// (round-6 ncu: regs=144 -> 1 CTA/SM, occ 12.3%, issue 19.7% = latency-bound).
// ---------------------------------------------------------------------------
#define HP 72
__global__ __launch_bounds__(256, 2)
void hgemm_kernel(const __half* __restrict__ A, const __half* __restrict__ B,
                  const float* __restrict__ bias, float* __restrict__ C,
                  int Ndim, int Kdim)
{
    extern __shared__ char smraw[];
    __half* sh = (__half*)smraw;
    __half* Ab_[2] = { sh,          sh + 18432 };
    __half* Bb_[2] = { sh + 9216,   sh + 27648 };
    float* sbias = (float*)(smraw + 73728);

    const int tid = threadIdx.x, wid = tid >> 5, lane = tid & 31;
    const int g = lane >> 2, c = lane & 3;
    const int wm = (wid >> 2) * 64, wn = (wid & 3) * 32;

    if (tid < 128) sbias[tid] = bias[blockIdx.x * 128 + tid];

    const __half* Ag = A + (size_t)(blockIdx.y * 128) * Kdim;
    const __half* Bg = B + (size_t)(blockIdx.x * 128) * Kdim;
    const uint32_t uA[2] = { smem_u32(Ab_[0]), smem_u32(Ab_[1]) };
    const uint32_t uB[2] = { smem_u32(Bb_[0]), smem_u32(Bb_[1]) };
    const int nk = Kdim >> 6;

    auto load = [&](int k, int bf) {
        const int k0 = k * 64;
        #pragma unroll
        for (int it = 0; it < 4; it++) {
            int idx = it * 256 + tid;      // 1024 16B chunks
            int r = idx >> 3, c8 = idx & 7;
            cp16(uA[bf] + (uint32_t)(r * HP + c8 * 8) * 2,
                 Ag + (size_t)r * Kdim + k0 + c8 * 8);
        }
        #pragma unroll
        for (int it = 0; it < 4; it++) {
            int idx = it * 256 + tid;
            int r = idx >> 3, c8 = idx & 7;
            cp16(uB[bf] + (uint32_t)(r * HP + c8 * 8) * 2,
                 Bg + (size_t)r * Kdim + k0 + c8 * 8);
        }
    };

    float acc[4][4][4];
    #pragma unroll
    for (int i = 0; i < 4; i++)
        #pragma unroll
        for (int j = 0; j < 4; j++)
            #pragma unroll
            for (int v = 0; v < 4; v++) acc[i][j][v] = 0.f;

    load(0, 0); CP_COMMIT();
    load(1, 1); CP_COMMIT();

    for (int k = 0; k < nk; k++) {
        CP_WAIT1();
        __syncthreads();
        const __half* A_ = Ab_[k & 1];
        const __half* B_ = Bb_[k & 1];
        #pragma unroll
        for (int ks = 0; ks < 4; ks++) {
            uint32_t a[4][4], b[4][2];
            #pragma unroll
            for (int mt = 0; mt < 4; mt++) {
                int row = wm + mt * 16 + g;
                a[mt][0] = *(const uint32_t*)(A_ + row * HP + ks * 16 + 2 * c);
                a[mt][1] = *(const uint32_t*)(A_ + (row + 8) * HP + ks * 16 + 2 * c);
                a[mt][2] = *(const uint32_t*)(A_ + row * HP + ks * 16 + 2 * c + 8);
                a[mt][3] = *(const uint32_t*)(A_ + (row + 8) * HP + ks * 16 + 2 * c + 8);
            }
            #pragma unroll
            for (int nt = 0; nt < 4; nt++) {
                int n = wn + nt * 8 + g;
                b[nt][0] = *(const uint32_t*)(B_ + n * HP + ks * 16 + 2 * c);
                b[nt][1] = *(const uint32_t*)(B_ + n * HP + ks * 16 + 2 * c + 8);
            }
            #pragma unroll
            for (int mt = 0; mt < 4; mt++)
                #pragma unroll
                for (int nt = 0; nt < 4; nt++)
                    mma16(acc[mt][nt], a[mt], b[nt]);
        }
        __syncthreads();
        if (k + 2 < nk) load(k + 2, k & 1);
        CP_COMMIT();
    }

    #pragma unroll
    for (int mt = 0; mt < 4; mt++) {
        int r0 = blockIdx.y * 128 + wm + mt * 16 + g;
        #pragma unroll
        for (int nt = 0; nt < 4; nt++) {
            int lc = wn + nt * 8 + 2 * c;
            int col = blockIdx.x * 128 + lc;
            float b0 = sbias[lc], b1 = sbias[lc + 1];
            float* p0 = C + (size_t)r0 * Ndim + col;
            float* p1 = C + (size_t)(r0 + 8) * Ndim + col;
            p0[0] = acc[mt][nt][0] + b0; p0[1] = acc[mt][nt][1] + b1;
            p1[0] = acc[mt][nt][2] + b0; p1[1] = acc[mt][nt][3] + b1;
        }
    }
}

// ---------------------------------------------------------------------------
// l2-normalize q,k per (token,head) -> fp16 head-major; v -> fp32 head-major
// ---------------------------------------------------------------------------
__global__ __launch_bounds__(512)
void norm_split_kernel()
{
    const int token = blockIdx.x;
    const int h     = threadIdx.x >> 5;
    const int lane  = threadIdx.x & 31;
    const int b     = token >> 11;
    const int sidx  = token & (SEQ - 1);

    const float* row = g_qkv + (size_t)token * QKV_N;
    const size_t obase = ((size_t)(b * NH + h) * SEQ + sidx) * HD;

    {
        float2 v = *(const float2*)(row + h * HD + lane * 2);
        float ss = v.x * v.x + v.y * v.y;
        #pragma unroll
        for (int o = 16; o > 0; o >>= 1) ss += __shfl_xor_sync(0xffffffffu, ss, o);
        float inv = 1.f / fmaxf(sqrtf(ss), 1e-12f);
        *(__half2*)(g_qh + obase + lane * 2) = __floats2half2_rn(v.x * inv, v.y * inv);
    }
    {
        float2 v = *(const float2*)(row + HID + h * HD + lane * 2);
        float ss = v.x * v.x + v.y * v.y;
        #pragma unroll
        for (int o = 16; o > 0; o >>= 1) ss += __shfl_xor_sync(0xffffffffu, ss, o);
        float inv = 1.f / fmaxf(sqrtf(ss), 1e-12f);
        *(__half2*)(g_kh + obase + lane * 2) = __floats2half2_rn(v.x * inv, v.y * inv);
    }
    {
        float2 v = *(const float2*)(row + 2 * HID + h * HD + lane * 2);
        *(float2*)(g_v + obase + lane * 2) = v;
    }
}

__global__ void zero_nc_kernel() { g_nc[blockIdx.x * 256 + threadIdx.x] = 0.f; }

// ---------------------------------------------------------------------------
// Score pass (fp16 MMA): 128x128 tile of (1+acos(clip(q.k)))^{-3.2},
// fp16 stores + fp32 column sums to g_nc.
// ---------------------------------------------------------------------------
__global__ __launch_bounds__(256)
void score_kernel()
{
    extern __shared__ char smraw[];
    __half* Qs = (__half*)smraw;
    __half* Ks = Qs + 9216;

    const int bh = blockIdx.z;
    const int s0 = blockIdx.y * 128, t0 = blockIdx.x * 128;
    const int tid = threadIdx.x, wid = tid >> 5, lane = tid & 31;
    const int g = lane >> 2, c = lane & 3;
    const int wm = (wid >> 2) * 64, wn = (wid & 3) * 32;
    const __half* Q  = g_qh + (size_t)bh * SEQ * HD;
    const __half* Kp = g_kh + (size_t)bh * SEQ * HD;
    const uint32_t uQ = smem_u32(Qs), uK = smem_u32(Ks);

    #pragma unroll
    for (int it = 0; it < 4; it++) {
        int idx = it * 256 + tid;          // 1024 16B chunks each
        int r = idx >> 3, c8 = idx & 7;
        cp16(uQ + (uint32_t)(r * HP + c8 * 8) * 2, Q  + (size_t)(s0 + r) * HD + c8 * 8);
        cp16(uK + (uint32_t)(r * HP + c8 * 8) * 2, Kp + (size_t)(t0 + r) * HD + c8 * 8);
    }
    CP_COMMIT(); CP_WAIT0();
    __syncthreads();

    float acc[4][4][4];
    #pragma unroll
    for (int i = 0; i < 4; i++)
        #pragma unroll
        for (int j = 0; j < 4; j++)
            #pragma unroll
            for (int v = 0; v < 4; v++) acc[i][j][v] = 0.f;

    #pragma unroll
    for (int ks = 0; ks < 4; ks++) {
        uint32_t a[4][4], b[4][2];
        #pragma unroll
        for (int mt = 0; mt < 4; mt++) {
            int row = wm + mt * 16 + g;
            a[mt][0] = *(const uint32_t*)(Qs + row * HP + ks * 16 + 2 * c);
            a[mt][1] = *(const uint32_t*)(Qs + (row + 8) * HP + ks * 16 + 2 * c);
            a[mt][2] = *(const uint32_t*)(Qs + row * HP + ks * 16 + 2 * c + 8);
            a[mt][3] = *(const uint32_t*)(Qs + (row + 8) * HP + ks * 16 + 2 * c + 8);
        }
        #pragma unroll
        for (int nt = 0; nt < 4; nt++) {
            int n = wn + nt * 8 + g;
            b[nt][0] = *(const uint32_t*)(Ks + n * HP + ks * 16 + 2 * c);
            b[nt][1] = *(const uint32_t*)(Ks + n * HP + ks * 16 + 2 * c + 8);
        }
        #pragma unroll
        for (int mt = 0; mt < 4; mt++)
            #pragma unroll
            for (int nt = 0; nt < 4; nt++)
                mma16(acc[mt][nt], a[mt], b[nt]);
    }

    float cs[8];
    #pragma unroll
    for (int j = 0; j < 8; j++) cs[j] = 0.f;

    __half* srow = g_scores_h + (size_t)bh * SEQ * SEQ;
    #pragma unroll
    for (int mt = 0; mt < 4; mt++) {
        int r0 = s0 + wm + mt * 16 + g;
        #pragma unroll
        for (int nt = 0; nt < 4; nt++) {
            int col = t0 + wn + nt * 8 + 2 * c;
            float o[4];
            #pragma unroll
            for (int v = 0; v < 4; v++) o[v] = spfns_score(acc[mt][nt][v]);
            *(__half2*)(srow + (size_t)r0 * SEQ + col)       = __floats2half2_rn(o[0], o[1]);
            *(__half2*)(srow + (size_t)(r0 + 8) * SEQ + col) = __floats2half2_rn(o[2], o[3]);
            cs[nt * 2]     += o[0] + o[2];
            cs[nt * 2 + 1] += o[1] + o[3];
        }
    }
    #pragma unroll
    for (int j = 0; j < 8; j++) {
        cs[j] += __shfl_xor_sync(0xffffffffu, cs[j], 4);
        cs[j] += __shfl_xor_sync(0xffffffffu, cs[j], 8);
        cs[j] += __shfl_xor_sync(0xffffffffu, cs[j], 16);
    }
    if (lane < 4) {
        #pragma unroll
        for (int nt = 0; nt < 4; nt++) {
            atomicAdd(&g_nc[bh * SEQ + t0 + wn + nt * 8 + 2 * lane],     cs[nt * 2]);
            atomicAdd(&g_nc[bh * SEQ + t0 + wn + nt * 8 + 2 * lane + 1], cs[nt * 2 + 1]);
        }
    }
}

// ---------------------------------------------------------------------------
// Build V'^T fp16: g_vwT[bh][d][t] = v[t][d]/nc[t] (d<64); 1/nc[t] (d=64);
// 0 (d=65..71). One block per (bh, 64-t chunk).
// ---------------------------------------------------------------------------
__global__ __launch_bounds__(256)
void build_vw_kernel()
{
    __shared__ float vt[64][65];
    __shared__ float ws[64];
    const int bh = blockIdx.y, t0 = blockIdx.x * 64;
    const int tid = threadIdx.x;
    const float* vb = g_v + (size_t)bh * SEQ * HD;
    __half* outb = g_vwT + (size_t)bh * 72 * SEQ;

    if (tid < 64) ws[tid] = 1.f / g_nc[bh * SEQ + t0 + tid];
    #pragma unroll
    for (int q = 0; q < 4; q++) {
        int idx = q * 256 + tid;          // 1024 float4s
        int t = idx >> 4, d4 = (idx & 15) * 4;
        float4 v = *(const float4*)(vb + (size_t)(t0 + t) * HD + d4);
        vt[t][d4] = v.x; vt[t][d4+1] = v.y; vt[t][d4+2] = v.z; vt[t][d4+3] = v.w;
    }
    __syncthreads();

    #pragma unroll
    for (int q = 0; q < 8; q++) {
        int idx = q * 256 + tid;          // 2048 half2s
        int d = idx >> 5, p = (idx & 31) * 2;
        *(__half2*)(outb + (size_t)d * SEQ + t0 + p) =
            __floats2half2_rn(vt[p][d] * ws[p], vt[p + 1][d] * ws[p + 1]);
    }
    {
        int d = 64 + (tid >> 5), p = (tid & 31) * 2;
        __half2 h = (d == 64) ? __floats2half2_rn(ws[p], ws[p + 1])
                              : __floats2half2_rn(0.f, 0.f);
        *(__half2*)(outb + (size_t)d * SEQ + t0 + p) = h;
    }
}

// ---------------------------------------------------------------------------
// PV pass (fp16 HMMA): [128 x 2048] S-tile @ [2048 x 72] V' -> 72 cols, col
// 64 = denominator. out = num/den -> g_ohh (fp16).
// ---------------------------------------------------------------------------
#define PVP 72
__global__ __launch_bounds__(256)
void pv_kernel()
{
    extern __shared__ float smf[];
    __half* sh = (__half*)smf;
    __half* Sb[2] = { sh,         sh + 9216 };
    __half* Vb[2] = { sh + 18432, sh + 23616 };

    const int s0 = blockIdx.x * 128, bh = blockIdx.y;
    const int b = bh >> 4, h = bh & 15;
    const int tid = threadIdx.x, wid = tid >> 5, lane = tid & 31;
    const int g = lane >> 2, c = lane & 3;
    const int wm = wid * 16;

    const __half* sbase = g_scores_h + (size_t)bh * SEQ * SEQ + (size_t)s0 * SEQ;
    const __half* vwb   = g_vwT + (size_t)bh * 72 * SEQ;
    const uint32_t uS[2] = { smem_u32(Sb[0]), smem_u32(Sb[1]) };
    const uint32_t uV[2] = { smem_u32(Vb[0]), smem_u32(Vb[1]) };

    auto load = [&](int it, int bf) {
        const int kt = it * 64;
        #pragma unroll
        for (int q = 0; q < 4; q++) {
            int idx = q * 256 + tid;
            int r = idx >> 3, c4 = idx & 7;
            cp16(uS[bf] + (uint32_t)(r * PVP + c4 * 8) * 2,
                 sbase + (size_t)r * SEQ + kt + c4 * 8);
        }
        #pragma unroll
        for (int q = 0; q < 3; q++) {
            int idx = q * 256 + tid;
            if (idx < 576) {
                int r = idx >> 3, c4 = idx & 7;
                cp16(uV[bf] + (uint32_t)(r * PVP + c4 * 8) * 2,
                     vwb + (size_t)r * SEQ + kt + c4 * 8);
            }
        }
    };

    float acc[9][4];
    #pragma unroll
    for (int i = 0; i < 9; i++)
        #pragma unroll
        for (int v = 0; v < 4; v++) acc[i][v] = 0.f;

    load(0, 0); CP_COMMIT();
    load(1, 1); CP_COMMIT();

    for (int it = 0; it < 32; it++) {
        CP_WAIT1();
        __syncthreads();
        const __half* S_ = Sb[it & 1];
        const __half* V_ = Vb[it & 1];
        #pragma unroll
        for (int ks = 0; ks < 4; ks++) {
            uint32_t a[4];
            a[0] = *(const uint32_t*)(S_ + (wm + g)     * PVP + ks * 16 + 2 * c);
            a[1] = *(const uint32_t*)(S_ + (wm + g + 8) * PVP + ks * 16 + 2 * c);
            a[2] = *(const uint32_t*)(S_ + (wm + g)     * PVP + ks * 16 + 2 * c + 8);
            a[3] = *(const uint32_t*)(S_ + (wm + g + 8) * PVP + ks * 16 + 2 * c + 8);
            #pragma unroll
            for (int nt = 0; nt < 9; nt++) {
                uint32_t bf[2];
                bf[0] = *(const uint32_t*)(V_ + (nt * 8 + g) * PVP + ks * 16 + 2 * c);
                bf[1] = *(const uint32_t*)(V_ + (nt * 8 + g) * PVP + ks * 16 + 2 * c + 8);
                mma16(acc[nt], a, bf);
            }
        }
        __syncthreads();
        if (it + 2 < 32) load(it + 2, it & 1);
        CP_COMMIT();
    }

    const int base = lane & ~3;
    float den0 = __shfl_sync(0xffffffffu, acc[8][0], base);
    float den1 = __shfl_sync(0xffffffffu, acc[8][2], base);
    float i0 = 1.f / fmaxf(den0, 1e-12f);
    float i1 = 1.f / fmaxf(den1, 1e-12f);

    const int gr = b * SEQ + s0 + wm + g;
    #pragma unroll
    for (int nt = 0; nt < 8; nt++) {
        __half* p0 = g_ohh + (size_t)gr * HID + h * HD + nt * 8 + 2 * c;
        __half* p1 = g_ohh + (size_t)(gr + 8) * HID + h * HD + nt * 8 + 2 * c;
        *(__half2*)p0 = __floats2half2_rn(acc[nt][0] * i0, acc[nt][1] * i0);
        *(__half2*)p1 = __floats2half2_rn(acc[nt][2] * i1, acc[nt][3] * i1);
    }
}

// ---------------------------------------------------------------------------
extern "C" void kernel_launch(void* const* d_in, const int* in_sizes, int n_in,
                              void* d_out, int out_size)
{
    const float* x      = (const float*)d_in[0];
    const float* w_qkv  = (const float*)d_in[1];
    const float* b_qkv  = (const float*)d_in[2];
    const float* w_out  = (const float*)d_in[3];
    const float* b_out  = (const float*)d_in[4];
    float* out = (float*)d_out;

    void *p_xh = nullptr, *p_wqkvh = nullptr, *p_wouth = nullptr;
    void *p_qkv = nullptr, *p_ohh = nullptr;
    cudaGetSymbolAddress(&p_xh,    g_xh);
    cudaGetSymbolAddress(&p_wqkvh, g_wqkvh);
    cudaGetSymbolAddress(&p_wouth, g_wouth);
    cudaGetSymbolAddress(&p_qkv,   g_qkv);
    cudaGetSymbolAddress(&p_ohh,   g_ohh);

    const int GEMM_SMEM  = 74240;   // 4*18432 halves + 128 floats
    const int SCORE_SMEM = 36864;   // 2*128*72 halves
    const int PV_SMEM    = 57600;   // 28800 halves
    static int attr_set = 0;
    if (!attr_set) {
        cudaFuncSetAttribute(hgemm_kernel,
                             cudaFuncAttributeMaxDynamicSharedMemorySize, GEMM_SMEM);
        cudaFuncSetAttribute(score_kernel,
                             cudaFuncAttributeMaxDynamicSharedMemorySize, SCORE_SMEM);
        cudaFuncSetAttribute(pv_kernel,
                             cudaFuncAttributeMaxDynamicSharedMemorySize, PV_SMEM);
        attr_set = 1;
    }

    // 0) fp16 conversions of inputs
    f2h_kernel<<<(MTOK*HID)/2048, 256>>>(x, (__half*)p_xh);
    f2h_kernel<<<(QKV_N*HID)/2048, 256>>>(w_qkv, (__half*)p_wqkvh);
    f2h_kernel<<<(HID*HID)/2048, 256>>>(w_out, (__half*)p_wouth);

    // 1) qkv = x @ w_qkv^T + b_qkv  (fp16 HMMA, fp32 accum/out)
    hgemm_kernel<<<dim3(QKV_N/128, MTOK/128), 256, GEMM_SMEM>>>(
        (const __half*)p_xh, (const __half*)p_wqkvh, b_qkv, (float*)p_qkv,
        QKV_N, HID);

    // 2) l2norm + head split (q,k -> fp16; v -> fp32)
    norm_split_kernel<<<MTOK, 512>>>();

    // 3) scores (fp16 MMA) + column sums
    zero_nc_kernel<<<(BH*SEQ)/256, 256>>>();
    score_kernel<<<dim3(SEQ/128, SEQ/128, BH), 256, SCORE_SMEM>>>();

    // 4) build V' = [V/nc | 1/nc | 0] transposed, fp16
    build_vw_kernel<<<dim3(SEQ/64, BH), 256>>>();

    // 5) PV fp16 GEMM with fused denominator -> g_ohh (fp16)
    pv_kernel<<<dim3(SEQ/128, BH), 256, PV_SMEM>>>();

    // 6) out = oh @ w_out^T + b_out  (fp16 HMMA, fp32 out)
    hgemm_kernel<<<dim3(HID/128, MTOK/128), 256, GEMM_SMEM>>>(
        (const __half*)p_ohh, (const __half*)p_wouth, b_out, out, HID, HID);
}

// round 9
// speedup vs baseline: 4.7005x; 1.1144x over previous
#include <cuda_runtime.h>
#include <cuda_fp16.h>
#include <math.h>
#include <stdint.h>

// Problem constants
#define BATCH   2
#define SEQ     2048
#define HID     1024
#define NH      16
#define HD      64
#define BH      (BATCH*NH)     // 32
#define MTOK    (BATCH*SEQ)    // 4096
#define QKV_N   (3*HID)        // 3072

// Scratch (device globals; no allocation allowed)
static __device__ __half g_xh[MTOK * HID];                     // 8 MB
static __device__ __half g_wqkvh[QKV_N * HID];                 // 6 MB
static __device__ __half g_wouth[HID * HID];                   // 2 MB
static __device__ float  g_qkv[MTOK * QKV_N];                  // 50 MB
static __device__ __half g_qh[BH * SEQ * HD];                  // 8 MB
static __device__ __half g_kh[BH * SEQ * HD];                  // 8 MB
static __device__ float  g_v[BH * SEQ * HD];                   // 16 MB
static __device__ __half g_scores_h[(size_t)BH * SEQ * SEQ];   // 268 MB
static __device__ __half g_vwT[(size_t)BH * 72 * SEQ];         // 9.4 MB
static __device__ float  g_nc[BH * SEQ];
static __device__ __half g_ohh[MTOK * HID];                    // 8 MB

// ---------------------------------------------------------------------------
// mma.sync fp16 primitive (legacy HMMA; valid on plain sm_100 target)
// D(16x8,f32) += A(16x16,f16) @ B(16x8,f16)
// ---------------------------------------------------------------------------
__device__ __forceinline__ void mma16(float* d, const uint32_t* a, const uint32_t* b) {
    asm volatile(
        "mma.sync.aligned.m16n8k16.row.col.f32.f16.f16.f32 "
        "{%0,%1,%2,%3}, {%4,%5,%6,%7}, {%8,%9}, {%0,%1,%2,%3};"
        : "+f"(d[0]), "+f"(d[1]), "+f"(d[2]), "+f"(d[3])
        : "r"(a[0]), "r"(a[1]), "r"(a[2]), "r"(a[3]), "r"(b[0]), "r"(b[1]));
}

__device__ __forceinline__ uint32_t smem_u32(const void* p) {
    uint32_t a;
    asm("{ .reg .u64 t; cvta.to.shared.u64 t, %1; cvt.u32.u64 %0, t; }"
        : "=r"(a) : "l"(p));
    return a;
}
__device__ __forceinline__ void cp16(uint32_t s, const void* g) {
    asm volatile("cp.async.cg.shared.global [%0], [%1], 16;" :: "r"(s), "l"(g));
}
#define CP_COMMIT() asm volatile("cp.async.commit_group;" ::: "memory")
#define CP_WAIT1()  asm volatile("cp.async.wait_group 1;" ::: "memory")
#define CP_WAIT0()  asm volatile("cp.async.wait_group 0;" ::: "memory")

// Fast (1 + acos(clip(x)))^{-3.2}: Hastings 8-term acos (|err|<=2e-8) + powf
__device__ __forceinline__ float spfns_score(float x) {
    float cc = fminf(fmaxf(x, -1.f + 1e-7f), 1.f - 1e-7f);
    float ax = fabsf(cc);
    float p =              -0.0012624911f;
    p = fmaf(p, ax,         0.0066700901f);
    p = fmaf(p, ax,        -0.0170881256f);
    p = fmaf(p, ax,         0.0308918810f);
    p = fmaf(p, ax,        -0.0501743046f);
    p = fmaf(p, ax,         0.0889789874f);
    p = fmaf(p, ax,        -0.2145988016f);
    p = fmaf(p, ax,         1.5707963050f);
    float s;
    asm("sqrt.approx.f32 %0, %1;" : "=f"(s) : "f"(1.f - ax));
    float r = s * p;
    r = (cc < 0.f) ? (3.14159265358979f - r) : r;
    return __powf(1.f + r, -3.2f);
}

// ---------------------------------------------------------------------------
// f32 -> f16 conversion, 8 elems/thread (n must be divisible by 2048)
// ---------------------------------------------------------------------------
__global__ __launch_bounds__(256)
void f2h_kernel(const float* __restrict__ src, __half* __restrict__ dst)
{
    size_t i = ((size_t)blockIdx.x * 256 + threadIdx.x) * 8;
    float4 v0 = *(const float4*)(src + i);
    float4 v1 = *(const float4*)(src + i + 4);
    __half2 h[4] = { __floats2half2_rn(v0.x, v0.y), __floats2half2_rn(v0.z, v0.w),
                     __floats2half2_rn(v1.x, v1.y), __floats2half2_rn(v1.z, v1.w) };
    *(uint4*)(dst + i) = *(uint4*)h;
}

// ---------------------------------------------------------------------------
// fp16 GEMM:  C[M,N](f32) = A[M,K](f16) @ B[N,K](f16)^T + bias[N](f32)
// Block 128x128, BK=64, 8 warps (2x4), warp tile 64x32. smem pitch 72 halves.
// 3-stage cp.async pipeline, distance-2 prefetch, ONE __syncthreads per
// K-iter (round-8 ncu: 2 CTAs resident but issue only 23% -> barrier-bound).
// ---------------------------------------------------------------------------
#define HP 72
#define HSTG 18432   // halves per stage (A 9216 + B 9216)
__global__ __launch_bounds__(256, 2)
void hgemm_kernel(const __half* __restrict__ A, const __half* __restrict__ B,
                  const float* __restrict__ bias, float* __restrict__ C,
                  int Ndim, int Kdim)
{
    extern __shared__ char smraw[];
    __half* sh = (__half*)smraw;
    float* sbias = (float*)(smraw + 3 * HSTG * 2);   // after 110592 bytes

    const int tid = threadIdx.x, wid = tid >> 5, lane = tid & 31;
    const int g = lane >> 2, c = lane & 3;
    const int wm = (wid >> 2) * 64, wn = (wid & 3) * 32;

    if (tid < 128) sbias[tid] = bias[blockIdx.x * 128 + tid];

    const __half* Ag = A + (size_t)(blockIdx.y * 128) * Kdim;
    const __half* Bg = B + (size_t)(blockIdx.x * 128) * Kdim;
    const uint32_t u0 = smem_u32(sh);
    const int nk = Kdim >> 6;

    auto load = [&](int k, int s) {
        const int k0 = k * 64;
        const uint32_t uA = u0 + (uint32_t)s * (HSTG * 2);
        const uint32_t uB = uA + 9216 * 2;
        #pragma unroll
        for (int it = 0; it < 4; it++) {
            int idx = it * 256 + tid;      // 1024 16B chunks
            int r = idx >> 3, c8 = idx & 7;
            cp16(uA + (uint32_t)(r * HP + c8 * 8) * 2,
                 Ag + (size_t)r * Kdim + k0 + c8 * 8);
        }
        #pragma unroll
        for (int it = 0; it < 4; it++) {
            int idx = it * 256 + tid;
            int r = idx >> 3, c8 = idx & 7;
            cp16(uB + (uint32_t)(r * HP + c8 * 8) * 2,
                 Bg + (size_t)r * Kdim + k0 + c8 * 8);
        }
    };

    float acc[4][4][4];
    #pragma unroll
    for (int i = 0; i < 4; i++)
        #pragma unroll
        for (int j = 0; j < 4; j++)
            #pragma unroll
            for (int v = 0; v < 4; v++) acc[i][j][v] = 0.f;

    load(0, 0); CP_COMMIT();
    load(1, 1); CP_COMMIT();

    int s = 0, sn = 2;                     // current stage, next write stage
    for (int k = 0; k < nk; k++) {
        CP_WAIT1();                        // group k retired -> stage s resident
        __syncthreads();                   // all warps done reading stage sn
        if (k + 2 < nk) load(k + 2, sn);
        CP_COMMIT();                       // one group per iter (maybe empty)

        const __half* A_ = sh + s * HSTG;
        const __half* B_ = A_ + 9216;
        #pragma unroll
        for (int ks = 0; ks < 4; ks++) {
            uint32_t a[4][4], b[4][2];
            #pragma unroll
            for (int mt = 0; mt < 4; mt++) {
                int row = wm + mt * 16 + g;
                a[mt][0] = *(const uint32_t*)(A_ + row * HP + ks * 16 + 2 * c);
                a[mt][1] = *(const uint32_t*)(A_ + (row + 8) * HP + ks * 16 + 2 * c);
                a[mt][2] = *(const uint32_t*)(A_ + row * HP + ks * 16 + 2 * c + 8);
                a[mt][3] = *(const uint32_t*)(A_ + (row + 8) * HP + ks * 16 + 2 * c + 8);
            }
            #pragma unroll
            for (int nt = 0; nt < 4; nt++) {
                int n = wn + nt * 8 + g;
                b[nt][0] = *(const uint32_t*)(B_ + n * HP + ks * 16 + 2 * c);
                b[nt][1] = *(const uint32_t*)(B_ + n * HP + ks * 16 + 2 * c + 8);
            }
            #pragma unroll
            for (int mt = 0; mt < 4; mt++)
                #pragma unroll
                for (int nt = 0; nt < 4; nt++)
                    mma16(acc[mt][nt], a[mt], b[nt]);
        }
        s = (s == 2) ? 0 : s + 1;
        sn = (sn == 2) ? 0 : sn + 1;
    }

    #pragma unroll
    for (int mt = 0; mt < 4; mt++) {
        int r0 = blockIdx.y * 128 + wm + mt * 16 + g;
        #pragma unroll
        for (int nt = 0; nt < 4; nt++) {
            int lc = wn + nt * 8 + 2 * c;
            int col = blockIdx.x * 128 + lc;
            float b0 = sbias[lc], b1 = sbias[lc + 1];
            float* p0 = C + (size_t)r0 * Ndim + col;
            float* p1 = C + (size_t)(r0 + 8) * Ndim + col;
            p0[0] = acc[mt][nt][0] + b0; p0[1] = acc[mt][nt][1] + b1;
            p1[0] = acc[mt][nt][2] + b0; p1[1] = acc[mt][nt][3] + b1;
        }
    }
}

// ---------------------------------------------------------------------------
// l2-normalize q,k per (token,head) -> fp16 head-major; v -> fp32 head-major
// ---------------------------------------------------------------------------
__global__ __launch_bounds__(512)
void norm_split_kernel()
{
    const int token = blockIdx.x;
    const int h     = threadIdx.x >> 5;
    const int lane  = threadIdx.x & 31;
    const int b     = token >> 11;
    const int sidx  = token & (SEQ - 1);

    const float* row = g_qkv + (size_t)token * QKV_N;
    const size_t obase = ((size_t)(b * NH + h) * SEQ + sidx) * HD;

    {
        float2 v = *(const float2*)(row + h * HD + lane * 2);
        float ss = v.x * v.x + v.y * v.y;
        #pragma unroll
        for (int o = 16; o > 0; o >>= 1) ss += __shfl_xor_sync(0xffffffffu, ss, o);
        float inv = 1.f / fmaxf(sqrtf(ss), 1e-12f);
        *(__half2*)(g_qh + obase + lane * 2) = __floats2half2_rn(v.x * inv, v.y * inv);
    }
    {
        float2 v = *(const float2*)(row + HID + h * HD + lane * 2);
        float ss = v.x * v.x + v.y * v.y;
        #pragma unroll
        for (int o = 16; o > 0; o >>= 1) ss += __shfl_xor_sync(0xffffffffu, ss, o);
        float inv = 1.f / fmaxf(sqrtf(ss), 1e-12f);
        *(__half2*)(g_kh + obase + lane * 2) = __floats2half2_rn(v.x * inv, v.y * inv);
    }
    {
        float2 v = *(const float2*)(row + 2 * HID + h * HD + lane * 2);
        *(float2*)(g_v + obase + lane * 2) = v;
    }
}

__global__ void zero_nc_kernel() { g_nc[blockIdx.x * 256 + threadIdx.x] = 0.f; }

// ---------------------------------------------------------------------------
// Score pass (fp16 MMA): 128x128 tile of (1+acos(clip(q.k)))^{-3.2},
// fp16 stores + fp32 column sums to g_nc.
// ---------------------------------------------------------------------------
__global__ __launch_bounds__(256)
void score_kernel()
{
    extern __shared__ char smraw[];
    __half* Qs = (__half*)smraw;
    __half* Ks = Qs + 9216;

    const int bh = blockIdx.z;
    const int s0 = blockIdx.y * 128, t0 = blockIdx.x * 128;
    const int tid = threadIdx.x, wid = tid >> 5, lane = tid & 31;
    const int g = lane >> 2, c = lane & 3;
    const int wm = (wid >> 2) * 64, wn = (wid & 3) * 32;
    const __half* Q  = g_qh + (size_t)bh * SEQ * HD;
    const __half* Kp = g_kh + (size_t)bh * SEQ * HD;
    const uint32_t uQ = smem_u32(Qs), uK = smem_u32(Ks);

    #pragma unroll
    for (int it = 0; it < 4; it++) {
        int idx = it * 256 + tid;          // 1024 16B chunks each
        int r = idx >> 3, c8 = idx & 7;
        cp16(uQ + (uint32_t)(r * HP + c8 * 8) * 2, Q  + (size_t)(s0 + r) * HD + c8 * 8);
        cp16(uK + (uint32_t)(r * HP + c8 * 8) * 2, Kp + (size_t)(t0 + r) * HD + c8 * 8);
    }
    CP_COMMIT(); CP_WAIT0();
    __syncthreads();

    float acc[4][4][4];
    #pragma unroll
    for (int i = 0; i < 4; i++)
        #pragma unroll
        for (int j = 0; j < 4; j++)
            #pragma unroll
            for (int v = 0; v < 4; v++) acc[i][j][v] = 0.f;

    #pragma unroll
    for (int ks = 0; ks < 4; ks++) {
        uint32_t a[4][4], b[4][2];
        #pragma unroll
        for (int mt = 0; mt < 4; mt++) {
            int row = wm + mt * 16 + g;
            a[mt][0] = *(const uint32_t*)(Qs + row * HP + ks * 16 + 2 * c);
            a[mt][1] = *(const uint32_t*)(Qs + (row + 8) * HP + ks * 16 + 2 * c);
            a[mt][2] = *(const uint32_t*)(Qs + row * HP + ks * 16 + 2 * c + 8);
            a[mt][3] = *(const uint32_t*)(Qs + (row + 8) * HP + ks * 16 + 2 * c + 8);
        }
        #pragma unroll
        for (int nt = 0; nt < 4; nt++) {
            int n = wn + nt * 8 + g;
            b[nt][0] = *(const uint32_t*)(Ks + n * HP + ks * 16 + 2 * c);
            b[nt][1] = *(const uint32_t*)(Ks + n * HP + ks * 16 + 2 * c + 8);
        }
        #pragma unroll
        for (int mt = 0; mt < 4; mt++)
            #pragma unroll
            for (int nt = 0; nt < 4; nt++)
                mma16(acc[mt][nt], a[mt], b[nt]);
    }

    float cs[8];
    #pragma unroll
    for (int j = 0; j < 8; j++) cs[j] = 0.f;

    __half* srow = g_scores_h + (size_t)bh * SEQ * SEQ;
    #pragma unroll
    for (int mt = 0; mt < 4; mt++) {
        int r0 = s0 + wm + mt * 16 + g;
        #pragma unroll
        for (int nt = 0; nt < 4; nt++) {
            int col = t0 + wn + nt * 8 + 2 * c;
            float o[4];
            #pragma unroll
            for (int v = 0; v < 4; v++) o[v] = spfns_score(acc[mt][nt][v]);
            *(__half2*)(srow + (size_t)r0 * SEQ + col)       = __floats2half2_rn(o[0], o[1]);
            *(__half2*)(srow + (size_t)(r0 + 8) * SEQ + col) = __floats2half2_rn(o[2], o[3]);
            cs[nt * 2]     += o[0] + o[2];
            cs[nt * 2 + 1] += o[1] + o[3];
        }
    }
    #pragma unroll
    for (int j = 0; j < 8; j++) {
        cs[j] += __shfl_xor_sync(0xffffffffu, cs[j], 4);
        cs[j] += __shfl_xor_sync(0xffffffffu, cs[j], 8);
        cs[j] += __shfl_xor_sync(0xffffffffu, cs[j], 16);
    }
    if (lane < 4) {
        #pragma unroll
        for (int nt = 0; nt < 4; nt++) {
            atomicAdd(&g_nc[bh * SEQ + t0 + wn + nt * 8 + 2 * lane],     cs[nt * 2]);
            atomicAdd(&g_nc[bh * SEQ + t0 + wn + nt * 8 + 2 * lane + 1], cs[nt * 2 + 1]);
        }
    }
}

// ---------------------------------------------------------------------------
// Build V'^T fp16: g_vwT[bh][d][t] = v[t][d]/nc[t] (d<64); 1/nc[t] (d=64);
// 0 (d=65..71). One block per (bh, 64-t chunk).
// ---------------------------------------------------------------------------
__global__ __launch_bounds__(256)
void build_vw_kernel()
{
    __shared__ float vt[64][65];
    __shared__ float ws[64];
    const int bh = blockIdx.y, t0 = blockIdx.x * 64;
    const int tid = threadIdx.x;
    const float* vb = g_v + (size_t)bh * SEQ * HD;
    __half* outb = g_vwT + (size_t)bh * 72 * SEQ;

    if (tid < 64) ws[tid] = 1.f / g_nc[bh * SEQ + t0 + tid];
    #pragma unroll
    for (int q = 0; q < 4; q++) {
        int idx = q * 256 + tid;          // 1024 float4s
        int t = idx >> 4, d4 = (idx & 15) * 4;
        float4 v = *(const float4*)(vb + (size_t)(t0 + t) * HD + d4);
        vt[t][d4] = v.x; vt[t][d4+1] = v.y; vt[t][d4+2] = v.z; vt[t][d4+3] = v.w;
    }
    __syncthreads();

    #pragma unroll
    for (int q = 0; q < 8; q++) {
        int idx = q * 256 + tid;          // 2048 half2s
        int d = idx >> 5, p = (idx & 31) * 2;
        *(__half2*)(outb + (size_t)d * SEQ + t0 + p) =
            __floats2half2_rn(vt[p][d] * ws[p], vt[p + 1][d] * ws[p + 1]);
    }
    {
        int d = 64 + (tid >> 5), p = (tid & 31) * 2;
        __half2 h = (d == 64) ? __floats2half2_rn(ws[p], ws[p + 1])
                              : __floats2half2_rn(0.f, 0.f);
        *(__half2*)(outb + (size_t)d * SEQ + t0 + p) = h;
    }
}

// ---------------------------------------------------------------------------
// PV pass (fp16 HMMA): [128 x 2048] S-tile @ [2048 x 72] V' -> 72 cols, col
// 64 = denominator. out = num/den -> g_ohh (fp16).
// 3-stage cp.async pipeline, distance-2 prefetch, one sync per iter.
// ---------------------------------------------------------------------------
#define PVP 72
#define PSTG 14400   // halves per stage (S 9216 + V 5184)
__global__ __launch_bounds__(256, 2)
void pv_kernel()
{
    extern __shared__ float smf[];
    __half* sh = (__half*)smf;

    const int s0 = blockIdx.x * 128, bh = blockIdx.y;
    const int b = bh >> 4, h = bh & 15;
    const int tid = threadIdx.x, wid = tid >> 5, lane = tid & 31;
    const int g = lane >> 2, c = lane & 3;
    const int wm = wid * 16;

    const __half* sbase = g_scores_h + (size_t)bh * SEQ * SEQ + (size_t)s0 * SEQ;
    const __half* vwb   = g_vwT + (size_t)bh * 72 * SEQ;
    const uint32_t u0 = smem_u32(sh);

    auto load = [&](int it, int st) {
        const int kt = it * 64;
        const uint32_t uS = u0 + (uint32_t)st * (PSTG * 2);
        const uint32_t uV = uS + 9216 * 2;
        #pragma unroll
        for (int q = 0; q < 4; q++) {
            int idx = q * 256 + tid;
            int r = idx >> 3, c4 = idx & 7;
            cp16(uS + (uint32_t)(r * PVP + c4 * 8) * 2,
                 sbase + (size_t)r * SEQ + kt + c4 * 8);
        }
        #pragma unroll
        for (int q = 0; q < 3; q++) {
            int idx = q * 256 + tid;
            if (idx < 576) {
                int r = idx >> 3, c4 = idx & 7;
                cp16(uV + (uint32_t)(r * PVP + c4 * 8) * 2,
                     vwb + (size_t)r * SEQ + kt + c4 * 8);
            }
        }
    };

    float acc[9][4];
    #pragma unroll
    for (int i = 0; i < 9; i++)
        #pragma unroll
        for (int v = 0; v < 4; v++) acc[i][v] = 0.f;

    load(0, 0); CP_COMMIT();
    load(1, 1); CP_COMMIT();

    int st = 0, sn = 2;
    for (int it = 0; it < 32; it++) {
        CP_WAIT1();
        __syncthreads();
        if (it + 2 < 32) load(it + 2, sn);
        CP_COMMIT();

        const __half* S_ = sh + st * PSTG;
        const __half* V_ = S_ + 9216;
        #pragma unroll
        for (int ks = 0; ks < 4; ks++) {
            uint32_t a[4];
            a[0] = *(const uint32_t*)(S_ + (wm + g)     * PVP + ks * 16 + 2 * c);
            a[1] = *(const uint32_t*)(S_ + (wm + g + 8) * PVP + ks * 16 + 2 * c);
            a[2] = *(const uint32_t*)(S_ + (wm + g)     * PVP + ks * 16 + 2 * c + 8);
            a[3] = *(const uint32_t*)(S_ + (wm + g + 8) * PVP + ks * 16 + 2 * c + 8);
            #pragma unroll
            for (int nt = 0; nt < 9; nt++) {
                uint32_t bf[2];
                bf[0] = *(const uint32_t*)(V_ + (nt * 8 + g) * PVP + ks * 16 + 2 * c);
                bf[1] = *(const uint32_t*)(V_ + (nt * 8 + g) * PVP + ks * 16 + 2 * c + 8);
                mma16(acc[nt], a, bf);
            }
        }
        st = (st == 2) ? 0 : st + 1;
        sn = (sn == 2) ? 0 : sn + 1;
    }

    const int base = lane & ~3;
    float den0 = __shfl_sync(0xffffffffu, acc[8][0], base);
    float den1 = __shfl_sync(0xffffffffu, acc[8][2], base);
    float i0 = 1.f / fmaxf(den0, 1e-12f);
    float i1 = 1.f / fmaxf(den1, 1e-12f);

    const int gr = b * SEQ + s0 + wm + g;
    #pragma unroll
    for (int nt = 0; nt < 8; nt++) {
        __half* p0 = g_ohh + (size_t)gr * HID + h * HD + nt * 8 + 2 * c;
        __half* p1 = g_ohh + (size_t)(gr + 8) * HID + h * HD + nt * 8 + 2 * c;
        *(__half2*)p0 = __floats2half2_rn(acc[nt][0] * i0, acc[nt][1] * i0);
        *(__half2*)p1 = __floats2half2_rn(acc[nt][2] * i1, acc[nt][3] * i1);
    }
}

// ---------------------------------------------------------------------------
extern "C" void kernel_launch(void* const* d_in, const int* in_sizes, int n_in,
                              void* d_out, int out_size)
{
    const float* x      = (const float*)d_in[0];
    const float* w_qkv  = (const float*)d_in[1];
    const float* b_qkv  = (const float*)d_in[2];
    const float* w_out  = (const float*)d_in[3];
    const float* b_out  = (const float*)d_in[4];
    float* out = (float*)d_out;

    void *p_xh = nullptr, *p_wqkvh = nullptr, *p_wouth = nullptr;
    void *p_qkv = nullptr, *p_ohh = nullptr;
    cudaGetSymbolAddress(&p_xh,    g_xh);
    cudaGetSymbolAddress(&p_wqkvh, g_wqkvh);
    cudaGetSymbolAddress(&p_wouth, g_wouth);
    cudaGetSymbolAddress(&p_qkv,   g_qkv);
    cudaGetSymbolAddress(&p_ohh,   g_ohh);

    const int GEMM_SMEM  = 111104;  // 3 stages * 36864 B + 128 floats bias
    const int SCORE_SMEM = 36864;   // 2*128*72 halves
    const int PV_SMEM    = 86400;   // 3 stages * 28800 B
    static int attr_set = 0;
    if (!attr_set) {
        cudaFuncSetAttribute(hgemm_kernel,
                             cudaFuncAttributeMaxDynamicSharedMemorySize, GEMM_SMEM);
        cudaFuncSetAttribute(score_kernel,
                             cudaFuncAttributeMaxDynamicSharedMemorySize, SCORE_SMEM);
        cudaFuncSetAttribute(pv_kernel,
                             cudaFuncAttributeMaxDynamicSharedMemorySize, PV_SMEM);
        attr_set = 1;
    }

    // 0) fp16 conversions of inputs
    f2h_kernel<<<(MTOK*HID)/2048, 256>>>(x, (__half*)p_xh);
    f2h_kernel<<<(QKV_N*HID)/2048, 256>>>(w_qkv, (__half*)p_wqkvh);
    f2h_kernel<<<(HID*HID)/2048, 256>>>(w_out, (__half*)p_wouth);

    // 1) qkv = x @ w_qkv^T + b_qkv  (fp16 HMMA, fp32 accum/out)
    hgemm_kernel<<<dim3(QKV_N/128, MTOK/128), 256, GEMM_SMEM>>>(
        (const __half*)p_xh, (const __half*)p_wqkvh, b_qkv, (float*)p_qkv,
        QKV_N, HID);

    // 2) l2norm + head split (q,k -> fp16; v -> fp32)
    norm_split_kernel<<<MTOK, 512>>>();

    // 3) scores (fp16 MMA) + column sums
    zero_nc_kernel<<<(BH*SEQ)/256, 256>>>();
    score_kernel<<<dim3(SEQ/128, SEQ/128, BH), 256, SCORE_SMEM>>>();

    // 4) build V' = [V/nc | 1/nc | 0] transposed, fp16
    build_vw_kernel<<<dim3(SEQ/64, BH), 256>>>();

    // 5) PV fp16 GEMM with fused denominator -> g_ohh (fp16)
    pv_kernel<<<dim3(SEQ/128, BH), 256, PV_SMEM>>>();

    // 6) out = oh @ w_out^T + b_out  (fp16 HMMA, fp32 out)
    hgemm_kernel<<<dim3(HID/128, MTOK/128), 256, GEMM_SMEM>>>(
        (const __half*)p_ohh, (const __half*)p_wouth, b_out, out, HID, HID);
}

// round 10
// speedup vs baseline: 4.8811x; 1.0384x over previous
#include <cuda_runtime.h>
#include <cuda_fp16.h>
#include <math.h>
#include <stdint.h>

// Problem constants
#define BATCH   2
#define SEQ     2048
#define HID     1024
#define NH      16
#define HD      64
#define BH      (BATCH*NH)     // 32
#define MTOK    (BATCH*SEQ)    // 4096
#define QKV_N   (3*HID)        // 3072

// Scratch (device globals; no allocation allowed)
static __device__ __half g_xh[MTOK * HID];                     // 8 MB
static __device__ __half g_wqkvh[QKV_N * HID];                 // 6 MB
static __device__ __half g_wouth[HID * HID];                   // 2 MB
static __device__ float  g_qkv[MTOK * QKV_N];                  // 50 MB
static __device__ __half g_qh[BH * SEQ * HD];                  // 8 MB
static __device__ __half g_kh[BH * SEQ * HD];                  // 8 MB
static __device__ float  g_v[BH * SEQ * HD];                   // 16 MB
static __device__ __half g_scores_h[(size_t)BH * SEQ * SEQ];   // 268 MB
static __device__ __half g_vwT[(size_t)BH * 72 * SEQ];         // 9.4 MB
static __device__ float  g_nc[BH * SEQ];
static __device__ __half g_ohh[MTOK * HID];                    // 8 MB

// ---------------------------------------------------------------------------
// mma.sync fp16 + ldmatrix primitives (legacy path; valid on plain sm_100)
// ---------------------------------------------------------------------------
__device__ __forceinline__ void mma16(float* d, const uint32_t* a, const uint32_t* b) {
    asm volatile(
        "mma.sync.aligned.m16n8k16.row.col.f32.f16.f16.f32 "
        "{%0,%1,%2,%3}, {%4,%5,%6,%7}, {%8,%9}, {%0,%1,%2,%3};"
        : "+f"(d[0]), "+f"(d[1]), "+f"(d[2]), "+f"(d[3])
        : "r"(a[0]), "r"(a[1]), "r"(a[2]), "r"(a[3]), "r"(b[0]), "r"(b[1]));
}

#define LDSM4(R0, R1, R2, R3, ADDR)                                           \
    asm volatile("ldmatrix.sync.aligned.m8n8.x4.shared.b16 {%0,%1,%2,%3}, [%4];" \
        : "=r"(R0), "=r"(R1), "=r"(R2), "=r"(R3) : "r"(ADDR))
#define LDSM2(R0, R1, ADDR)                                                   \
    asm volatile("ldmatrix.sync.aligned.m8n8.x2.shared.b16 {%0,%1}, [%2];"    \
        : "=r"(R0), "=r"(R1) : "r"(ADDR))

__device__ __forceinline__ uint32_t smem_u32(const void* p) {
    uint32_t a;
    asm("{ .reg .u64 t; cvta.to.shared.u64 t, %1; cvt.u32.u64 %0, t; }"
        : "=r"(a) : "l"(p));
    return a;
}
__device__ __forceinline__ void cp16(uint32_t s, const void* g) {
    asm volatile("cp.async.cg.shared.global [%0], [%1], 16;" :: "r"(s), "l"(g));
}
#define CP_COMMIT() asm volatile("cp.async.commit_group;" ::: "memory")
#define CP_WAIT1()  asm volatile("cp.async.wait_group 1;" ::: "memory")
#define CP_WAIT0()  asm volatile("cp.async.wait_group 0;" ::: "memory")

// Fast (1 + acos(clip(x)))^{-3.2}: Hastings 8-term acos (|err|<=2e-8) + powf
__device__ __forceinline__ float spfns_score(float x) {
    float cc = fminf(fmaxf(x, -1.f + 1e-7f), 1.f - 1e-7f);
    float ax = fabsf(cc);
    float p =              -0.0012624911f;
    p = fmaf(p, ax,         0.0066700901f);
    p = fmaf(p, ax,        -0.0170881256f);
    p = fmaf(p, ax,         0.0308918810f);
    p = fmaf(p, ax,        -0.0501743046f);
    p = fmaf(p, ax,         0.0889789874f);
    p = fmaf(p, ax,        -0.2145988016f);
    p = fmaf(p, ax,         1.5707963050f);
    float s;
    asm("sqrt.approx.f32 %0, %1;" : "=f"(s) : "f"(1.f - ax));
    float r = s * p;
    r = (cc < 0.f) ? (3.14159265358979f - r) : r;
    return __powf(1.f + r, -3.2f);
}

// ---------------------------------------------------------------------------
// f32 -> f16 conversion, 8 elems/thread (n must be divisible by 2048)
// ---------------------------------------------------------------------------
__global__ __launch_bounds__(256)
void f2h_kernel(const float* __restrict__ src, __half* __restrict__ dst)
{
    size_t i = ((size_t)blockIdx.x * 256 + threadIdx.x) * 8;
    float4 v0 = *(const float4*)(src + i);
    float4 v1 = *(const float4*)(src + i + 4);
    __half2 h[4] = { __floats2half2_rn(v0.x, v0.y), __floats2half2_rn(v0.z, v0.w),
                     __floats2half2_rn(v1.x, v1.y), __floats2half2_rn(v1.z, v1.w) };
    *(uint4*)(dst + i) = *(uint4*)h;
}

// ---------------------------------------------------------------------------
// fp16 GEMM:  C[M,N](f32) = A[M,K](f16) @ B[N,K](f16)^T + bias[N](f32)
// Block 128x128, BK=64, 8 warps (2x4), warp tile 64x32. smem pitch 72 halves.
// 3-stage cp.async pipeline, distance-2 prefetch, 1 sync/iter, LDSM fragments.
// ---------------------------------------------------------------------------
#define HP 72
#define HSTG 18432   // halves per stage (A 9216 + B 9216)
__global__ __launch_bounds__(256, 2)
void hgemm_kernel(const __half* __restrict__ A, const __half* __restrict__ B,
                  const float* __restrict__ bias, float* __restrict__ C,
                  int Ndim, int Kdim)
{
    extern __shared__ char smraw[];
    __half* sh = (__half*)smraw;
    float* sbias = (float*)(smraw + 3 * HSTG * 2);   // after 110592 bytes

    const int tid = threadIdx.x, wid = tid >> 5, lane = tid & 31;
    const int g = lane >> 2, c = lane & 3;
    const int wm = (wid >> 2) * 64, wn = (wid & 3) * 32;

    if (tid < 128) sbias[tid] = bias[blockIdx.x * 128 + tid];

    const __half* Ag = A + (size_t)(blockIdx.y * 128) * Kdim;
    const __half* Bg = B + (size_t)(blockIdx.x * 128) * Kdim;
    const uint32_t u0 = smem_u32(sh);
    const int nk = Kdim >> 6;

    // per-lane ldmatrix offsets (bytes, relative to stage A / stage B base)
    uint32_t offA[4], offB[2];
    {
        const int rA = lane & 15, kA = (lane >> 4) * 8;
        #pragma unroll
        for (int mt = 0; mt < 4; mt++)
            offA[mt] = (uint32_t)(((wm + mt * 16 + rA) * HP + kA) * 2);
        const int rB = ((lane >> 4) & 1) * 8 + (lane & 7);
        const int kB = ((lane >> 3) & 1) * 8;
        #pragma unroll
        for (int np = 0; np < 2; np++)
            offB[np] = (uint32_t)(((wn + np * 16 + rB) * HP + kB) * 2);
    }

    auto load = [&](int k, int s) {
        const int k0 = k * 64;
        const uint32_t uA = u0 + (uint32_t)s * (HSTG * 2);
        const uint32_t uB = uA + 9216 * 2;
        #pragma unroll
        for (int it = 0; it < 4; it++) {
            int idx = it * 256 + tid;      // 1024 16B chunks
            int r = idx >> 3, c8 = idx & 7;
            cp16(uA + (uint32_t)(r * HP + c8 * 8) * 2,
                 Ag + (size_t)r * Kdim + k0 + c8 * 8);
        }
        #pragma unroll
        for (int it = 0; it < 4; it++) {
            int idx = it * 256 + tid;
            int r = idx >> 3, c8 = idx & 7;
            cp16(uB + (uint32_t)(r * HP + c8 * 8) * 2,
                 Bg + (size_t)r * Kdim + k0 + c8 * 8);
        }
    };

    float acc[4][4][4];
    #pragma unroll
    for (int i = 0; i < 4; i++)
        #pragma unroll
        for (int j = 0; j < 4; j++)
            #pragma unroll
            for (int v = 0; v < 4; v++) acc[i][j][v] = 0.f;

    load(0, 0); CP_COMMIT();
    load(1, 1); CP_COMMIT();

    int s = 0, sn = 2;                     // current stage, next write stage
    for (int k = 0; k < nk; k++) {
        CP_WAIT1();                        // group k retired -> stage s resident
        __syncthreads();                   // all warps done reading stage sn
        if (k + 2 < nk) load(k + 2, sn);
        CP_COMMIT();                       // one group per iter (maybe empty)

        const uint32_t uA = u0 + (uint32_t)s * (HSTG * 2);
        const uint32_t uB = uA + 9216 * 2;
        #pragma unroll
        for (int ks = 0; ks < 4; ks++) {
            uint32_t a[4][4], b[2][4];
            #pragma unroll
            for (int mt = 0; mt < 4; mt++)
                LDSM4(a[mt][0], a[mt][1], a[mt][2], a[mt][3],
                      uA + offA[mt] + ks * 32);
            #pragma unroll
            for (int np = 0; np < 2; np++)
                LDSM4(b[np][0], b[np][1], b[np][2], b[np][3],
                      uB + offB[np] + ks * 32);
            #pragma unroll
            for (int mt = 0; mt < 4; mt++)
                #pragma unroll
                for (int nt = 0; nt < 4; nt++)
                    mma16(acc[mt][nt], a[mt], &b[nt >> 1][(nt & 1) * 2]);
        }
        s = (s == 2) ? 0 : s + 1;
        sn = (sn == 2) ? 0 : sn + 1;
    }

    #pragma unroll
    for (int mt = 0; mt < 4; mt++) {
        int r0 = blockIdx.y * 128 + wm + mt * 16 + g;
        #pragma unroll
        for (int nt = 0; nt < 4; nt++) {
            int lc = wn + nt * 8 + 2 * c;
            int col = blockIdx.x * 128 + lc;
            float b0 = sbias[lc], b1 = sbias[lc + 1];
            float* p0 = C + (size_t)r0 * Ndim + col;
            float* p1 = C + (size_t)(r0 + 8) * Ndim + col;
            p0[0] = acc[mt][nt][0] + b0; p0[1] = acc[mt][nt][1] + b1;
            p1[0] = acc[mt][nt][2] + b0; p1[1] = acc[mt][nt][3] + b1;
        }
    }
}

// ---------------------------------------------------------------------------
// l2-normalize q,k per (token,head) -> fp16 head-major; v -> fp32 head-major
// ---------------------------------------------------------------------------
__global__ __launch_bounds__(512)
void norm_split_kernel()
{
    const int token = blockIdx.x;
    const int h     = threadIdx.x >> 5;
    const int lane  = threadIdx.x & 31;
    const int b     = token >> 11;
    const int sidx  = token & (SEQ - 1);

    const float* row = g_qkv + (size_t)token * QKV_N;
    const size_t obase = ((size_t)(b * NH + h) * SEQ + sidx) * HD;

    {
        float2 v = *(const float2*)(row + h * HD + lane * 2);
        float ss = v.x * v.x + v.y * v.y;
        #pragma unroll
        for (int o = 16; o > 0; o >>= 1) ss += __shfl_xor_sync(0xffffffffu, ss, o);
        float inv = 1.f / fmaxf(sqrtf(ss), 1e-12f);
        *(__half2*)(g_qh + obase + lane * 2) = __floats2half2_rn(v.x * inv, v.y * inv);
    }
    {
        float2 v = *(const float2*)(row + HID + h * HD + lane * 2);
        float ss = v.x * v.x + v.y * v.y;
        #pragma unroll
        for (int o = 16; o > 0; o >>= 1) ss += __shfl_xor_sync(0xffffffffu, ss, o);
        float inv = 1.f / fmaxf(sqrtf(ss), 1e-12f);
        *(__half2*)(g_kh + obase + lane * 2) = __floats2half2_rn(v.x * inv, v.y * inv);
    }
    {
        float2 v = *(const float2*)(row + 2 * HID + h * HD + lane * 2);
        *(float2*)(g_v + obase + lane * 2) = v;
    }
}

__global__ void zero_nc_kernel() { g_nc[blockIdx.x * 256 + threadIdx.x] = 0.f; }

// ---------------------------------------------------------------------------
// Score pass (fp16 MMA + LDSM): 128x128 tile of (1+acos(clip(q.k)))^{-3.2},
// fp16 stores + fp32 column sums to g_nc.
// ---------------------------------------------------------------------------
__global__ __launch_bounds__(256)
void score_kernel()
{
    extern __shared__ char smraw[];
    __half* Qs = (__half*)smraw;
    __half* Ks = Qs + 9216;

    const int bh = blockIdx.z;
    const int s0 = blockIdx.y * 128, t0 = blockIdx.x * 128;
    const int tid = threadIdx.x, wid = tid >> 5, lane = tid & 31;
    const int g = lane >> 2, c = lane & 3;
    const int wm = (wid >> 2) * 64, wn = (wid & 3) * 32;
    const __half* Q  = g_qh + (size_t)bh * SEQ * HD;
    const __half* Kp = g_kh + (size_t)bh * SEQ * HD;
    const uint32_t uQ = smem_u32(Qs), uK = smem_u32(Ks);

    #pragma unroll
    for (int it = 0; it < 4; it++) {
        int idx = it * 256 + tid;          // 1024 16B chunks each
        int r = idx >> 3, c8 = idx & 7;
        cp16(uQ + (uint32_t)(r * HP + c8 * 8) * 2, Q  + (size_t)(s0 + r) * HD + c8 * 8);
        cp16(uK + (uint32_t)(r * HP + c8 * 8) * 2, Kp + (size_t)(t0 + r) * HD + c8 * 8);
    }
    CP_COMMIT(); CP_WAIT0();
    __syncthreads();

    uint32_t offA[4], offB[2];
    {
        const int rA = lane & 15, kA = (lane >> 4) * 8;
        #pragma unroll
        for (int mt = 0; mt < 4; mt++)
            offA[mt] = (uint32_t)(((wm + mt * 16 + rA) * HP + kA) * 2);
        const int rB = ((lane >> 4) & 1) * 8 + (lane & 7);
        const int kB = ((lane >> 3) & 1) * 8;
        #pragma unroll
        for (int np = 0; np < 2; np++)
            offB[np] = (uint32_t)(((wn + np * 16 + rB) * HP + kB) * 2);
    }

    float acc[4][4][4];
    #pragma unroll
    for (int i = 0; i < 4; i++)
        #pragma unroll
        for (int j = 0; j < 4; j++)
            #pragma unroll
            for (int v = 0; v < 4; v++) acc[i][j][v] = 0.f;

    #pragma unroll
    for (int ks = 0; ks < 4; ks++) {
        uint32_t a[4][4], b[2][4];
        #pragma unroll
        for (int mt = 0; mt < 4; mt++)
            LDSM4(a[mt][0], a[mt][1], a[mt][2], a[mt][3], uQ + offA[mt] + ks * 32);
        #pragma unroll
        for (int np = 0; np < 2; np++)
            LDSM4(b[np][0], b[np][1], b[np][2], b[np][3], uK + offB[np] + ks * 32);
        #pragma unroll
        for (int mt = 0; mt < 4; mt++)
            #pragma unroll
            for (int nt = 0; nt < 4; nt++)
                mma16(acc[mt][nt], a[mt], &b[nt >> 1][(nt & 1) * 2]);
    }

    float cs[8];
    #pragma unroll
    for (int j = 0; j < 8; j++) cs[j] = 0.f;

    __half* srow = g_scores_h + (size_t)bh * SEQ * SEQ;
    #pragma unroll
    for (int mt = 0; mt < 4; mt++) {
        int r0 = s0 + wm + mt * 16 + g;
        #pragma unroll
        for (int nt = 0; nt < 4; nt++) {
            int col = t0 + wn + nt * 8 + 2 * c;
            float o[4];
            #pragma unroll
            for (int v = 0; v < 4; v++) o[v] = spfns_score(acc[mt][nt][v]);
            *(__half2*)(srow + (size_t)r0 * SEQ + col)       = __floats2half2_rn(o[0], o[1]);
            *(__half2*)(srow + (size_t)(r0 + 8) * SEQ + col) = __floats2half2_rn(o[2], o[3]);
            cs[nt * 2]     += o[0] + o[2];
            cs[nt * 2 + 1] += o[1] + o[3];
        }
    }
    #pragma unroll
    for (int j = 0; j < 8; j++) {
        cs[j] += __shfl_xor_sync(0xffffffffu, cs[j], 4);
        cs[j] += __shfl_xor_sync(0xffffffffu, cs[j], 8);
        cs[j] += __shfl_xor_sync(0xffffffffu, cs[j], 16);
    }
    if (lane < 4) {
        #pragma unroll
        for (int nt = 0; nt < 4; nt++) {
            atomicAdd(&g_nc[bh * SEQ + t0 + wn + nt * 8 + 2 * lane],     cs[nt * 2]);
            atomicAdd(&g_nc[bh * SEQ + t0 + wn + nt * 8 + 2 * lane + 1], cs[nt * 2 + 1]);
        }
    }
}

// ---------------------------------------------------------------------------
// Build V'^T fp16: g_vwT[bh][d][t] = v[t][d]/nc[t] (d<64); 1/nc[t] (d=64);
// 0 (d=65..71). One block per (bh, 64-t chunk).
// ---------------------------------------------------------------------------
__global__ __launch_bounds__(256)
void build_vw_kernel()
{
    __shared__ float vt[64][65];
    __shared__ float ws[64];
    const int bh = blockIdx.y, t0 = blockIdx.x * 64;
    const int tid = threadIdx.x;
    const float* vb = g_v + (size_t)bh * SEQ * HD;
    __half* outb = g_vwT + (size_t)bh * 72 * SEQ;

    if (tid < 64) ws[tid] = 1.f / g_nc[bh * SEQ + t0 + tid];
    #pragma unroll
    for (int q = 0; q < 4; q++) {
        int idx = q * 256 + tid;          // 1024 float4s
        int t = idx >> 4, d4 = (idx & 15) * 4;
        float4 v = *(const float4*)(vb + (size_t)(t0 + t) * HD + d4);
        vt[t][d4] = v.x; vt[t][d4+1] = v.y; vt[t][d4+2] = v.z; vt[t][d4+3] = v.w;
    }
    __syncthreads();

    #pragma unroll
    for (int q = 0; q < 8; q++) {
        int idx = q * 256 + tid;          // 2048 half2s
        int d = idx >> 5, p = (idx & 31) * 2;
        *(__half2*)(outb + (size_t)d * SEQ + t0 + p) =
            __floats2half2_rn(vt[p][d] * ws[p], vt[p + 1][d] * ws[p + 1]);
    }
    {
        int d = 64 + (tid >> 5), p = (tid & 31) * 2;
        __half2 h = (d == 64) ? __floats2half2_rn(ws[p], ws[p + 1])
                              : __floats2half2_rn(0.f, 0.f);
        *(__half2*)(outb + (size_t)d * SEQ + t0 + p) = h;
    }
}

// ---------------------------------------------------------------------------
// PV pass (fp16 HMMA + LDSM): [128 x 2048] S-tile @ [2048 x 72] V' -> 72
// cols, col 64 = denominator. out = num/den -> g_ohh (fp16).
// 3-stage cp.async pipeline, distance-2 prefetch, one sync per iter.
// ---------------------------------------------------------------------------
#define PVP 72
#define PSTG 14400   // halves per stage (S 9216 + V 5184)
__global__ __launch_bounds__(256, 2)
void pv_kernel()
{
    extern __shared__ float smf[];
    __half* sh = (__half*)smf;

    const int s0 = blockIdx.x * 128, bh = blockIdx.y;
    const int b = bh >> 4, h = bh & 15;
    const int tid = threadIdx.x, wid = tid >> 5, lane = tid & 31;
    const int g = lane >> 2, c = lane & 3;
    const int wm = wid * 16;

    const __half* sbase = g_scores_h + (size_t)bh * SEQ * SEQ + (size_t)s0 * SEQ;
    const __half* vwb   = g_vwT + (size_t)bh * 72 * SEQ;
    const uint32_t u0 = smem_u32(sh);

    uint32_t offA, offB[4], offB8;
    {
        const int rA = lane & 15, kA = (lane >> 4) * 8;
        offA = (uint32_t)(((wm + rA) * PVP + kA) * 2);
        const int rB = ((lane >> 4) & 1) * 8 + (lane & 7);
        const int kB = ((lane >> 3) & 1) * 8;
        #pragma unroll
        for (int np = 0; np < 4; np++)
            offB[np] = (uint32_t)(((np * 16 + rB) * PVP + kB) * 2);
        offB8 = (uint32_t)(((64 + (lane & 7)) * PVP + kB) * 2);
    }

    auto load = [&](int it, int st) {
        const int kt = it * 64;
        const uint32_t uS = u0 + (uint32_t)st * (PSTG * 2);
        const uint32_t uV = uS + 9216 * 2;
        #pragma unroll
        for (int q = 0; q < 4; q++) {
            int idx = q * 256 + tid;
            int r = idx >> 3, c4 = idx & 7;
            cp16(uS + (uint32_t)(r * PVP + c4 * 8) * 2,
                 sbase + (size_t)r * SEQ + kt + c4 * 8);
        }
        #pragma unroll
        for (int q = 0; q < 3; q++) {
            int idx = q * 256 + tid;
            if (idx < 576) {
                int r = idx >> 3, c4 = idx & 7;
                cp16(uV + (uint32_t)(r * PVP + c4 * 8) * 2,
                     vwb + (size_t)r * SEQ + kt + c4 * 8);
            }
        }
    };

    float acc[9][4];
    #pragma unroll
    for (int i = 0; i < 9; i++)
        #pragma unroll
        for (int v = 0; v < 4; v++) acc[i][v] = 0.f;

    load(0, 0); CP_COMMIT();
    load(1, 1); CP_COMMIT();

    int st = 0, sn = 2;
    for (int it = 0; it < 32; it++) {
        CP_WAIT1();
        __syncthreads();
        if (it + 2 < 32) load(it + 2, sn);
        CP_COMMIT();

        const uint32_t uS = u0 + (uint32_t)st * (PSTG * 2);
        const uint32_t uV = uS + 9216 * 2;
        #pragma unroll
        for (int ks = 0; ks < 4; ks++) {
            uint32_t a[4];
            LDSM4(a[0], a[1], a[2], a[3], uS + offA + ks * 32);
            uint32_t bb[4][4], b8[2];
            #pragma unroll
            for (int np = 0; np < 4; np++)
                LDSM4(bb[np][0], bb[np][1], bb[np][2], bb[np][3],
                      uV + offB[np] + ks * 32);
            LDSM2(b8[0], b8[1], uV + offB8 + ks * 32);
            #pragma unroll
            for (int nt = 0; nt < 8; nt++)
                mma16(acc[nt], a, &bb[nt >> 1][(nt & 1) * 2]);
            mma16(acc[8], a, b8);
        }
        st = (st == 2) ? 0 : st + 1;
        sn = (sn == 2) ? 0 : sn + 1;
    }

    const int base = lane & ~3;
    float den0 = __shfl_sync(0xffffffffu, acc[8][0], base);
    float den1 = __shfl_sync(0xffffffffu, acc[8][2], base);
    float i0 = 1.f / fmaxf(den0, 1e-12f);
    float i1 = 1.f / fmaxf(den1, 1e-12f);

    const int gr = b * SEQ + s0 + wm + g;
    #pragma unroll
    for (int nt = 0; nt < 8; nt++) {
        __half* p0 = g_ohh + (size_t)gr * HID + h * HD + nt * 8 + 2 * c;
        __half* p1 = g_ohh + (size_t)(gr + 8) * HID + h * HD + nt * 8 + 2 * c;
        *(__half2*)p0 = __floats2half2_rn(acc[nt][0] * i0, acc[nt][1] * i0);
        *(__half2*)p1 = __floats2half2_rn(acc[nt][2] * i1, acc[nt][3] * i1);
    }
}

// ---------------------------------------------------------------------------
extern "C" void kernel_launch(void* const* d_in, const int* in_sizes, int n_in,
                              void* d_out, int out_size)
{
    const float* x      = (const float*)d_in[0];
    const float* w_qkv  = (const float*)d_in[1];
    const float* b_qkv  = (const float*)d_in[2];
    const float* w_out  = (const float*)d_in[3];
    const float* b_out  = (const float*)d_in[4];
    float* out = (float*)d_out;

    void *p_xh = nullptr, *p_wqkvh = nullptr, *p_wouth = nullptr;
    void *p_qkv = nullptr, *p_ohh = nullptr;
    cudaGetSymbolAddress(&p_xh,    g_xh);
    cudaGetSymbolAddress(&p_wqkvh, g_wqkvh);
    cudaGetSymbolAddress(&p_wouth, g_wouth);
    cudaGetSymbolAddress(&p_qkv,   g_qkv);
    cudaGetSymbolAddress(&p_ohh,   g_ohh);

    const int GEMM_SMEM  = 111104;  // 3 stages * 36864 B + 128 floats bias
    const int SCORE_SMEM = 36864;   // 2*128*72 halves
    const int PV_SMEM    = 86400;   // 3 stages * 28800 B
    static int attr_set = 0;
    if (!attr_set) {
        cudaFuncSetAttribute(hgemm_kernel,
                             cudaFuncAttributeMaxDynamicSharedMemorySize, GEMM_SMEM);
        cudaFuncSetAttribute(score_kernel,
                             cudaFuncAttributeMaxDynamicSharedMemorySize, SCORE_SMEM);
        cudaFuncSetAttribute(pv_kernel,
                             cudaFuncAttributeMaxDynamicSharedMemorySize, PV_SMEM);
        attr_set = 1;
    }

    // 0) fp16 conversions of inputs
    f2h_kernel<<<(MTOK*HID)/2048, 256>>>(x, (__half*)p_xh);
    f2h_kernel<<<(QKV_N*HID)/2048, 256>>>(w_qkv, (__half*)p_wqkvh);
    f2h_kernel<<<(HID*HID)/2048, 256>>>(w_out, (__half*)p_wouth);

    // 1) qkv = x @ w_qkv^T + b_qkv  (fp16 HMMA, fp32 accum/out)
    hgemm_kernel<<<dim3(QKV_N/128, MTOK/128), 256, GEMM_SMEM>>>(
        (const __half*)p_xh, (const __half*)p_wqkvh, b_qkv, (float*)p_qkv,
        QKV_N, HID);

    // 2) l2norm + head split (q,k -> fp16; v -> fp32)
    norm_split_kernel<<<MTOK, 512>>>();

    // 3) scores (fp16 MMA) + column sums
    zero_nc_kernel<<<(BH*SEQ)/256, 256>>>();
    score_kernel<<<dim3(SEQ/128, SEQ/128, BH), 256, SCORE_SMEM>>>();

    // 4) build V' = [V/nc | 1/nc | 0] transposed, fp16
    build_vw_kernel<<<dim3(SEQ/64, BH), 256>>>();

    // 5) PV fp16 GEMM with fused denominator -> g_ohh (fp16)
    pv_kernel<<<dim3(SEQ/128, BH), 256, PV_SMEM>>>();

    // 6) out = oh @ w_out^T + b_out  (fp16 HMMA, fp32 out)
    hgemm_kernel<<<dim3(HID/128, MTOK/128), 256, GEMM_SMEM>>>(
        (const __half*)p_ohh, (const __half*)p_wouth, b_out, out, HID, HID);
}

// round 11
// speedup vs baseline: 5.1040x; 1.0457x over previous
#include <cuda_runtime.h>
#include <cuda_fp16.h>
#include <math.h>
#include <stdint.h>

// Problem constants
#define BATCH   2
#define SEQ     2048
#define HID     1024
#define NH      16
#define HD      64
#define BH      (BATCH*NH)     // 32
#define MTOK    (BATCH*SEQ)    // 4096
#define QKV_N   (3*HID)        // 3072

// Scratch (device globals; no allocation allowed)
static __device__ __half g_xh[MTOK * HID];                     // 8 MB
static __device__ __half g_wqkvh[QKV_N * HID];                 // 6 MB
static __device__ __half g_wouth[HID * HID];                   // 2 MB
static __device__ __half g_qh[BH * SEQ * HD];                  // 8 MB
static __device__ __half g_kh[BH * SEQ * HD];                  // 8 MB
static __device__ float  g_v[BH * SEQ * HD];                   // 16 MB
static __device__ __half g_scores_h[(size_t)BH * SEQ * SEQ];   // 268 MB
static __device__ __half g_vwT[(size_t)BH * 72 * SEQ];         // 9.4 MB
static __device__ float  g_nc[BH * SEQ];
static __device__ __half g_ohh[MTOK * HID];                    // 8 MB

// ---------------------------------------------------------------------------
// mma.sync fp16 + ldmatrix primitives (legacy path; valid on plain sm_100)
// ---------------------------------------------------------------------------
__device__ __forceinline__ void mma16(float* d, const uint32_t* a, const uint32_t* b) {
    asm volatile(
        "mma.sync.aligned.m16n8k16.row.col.f32.f16.f16.f32 "
        "{%0,%1,%2,%3}, {%4,%5,%6,%7}, {%8,%9}, {%0,%1,%2,%3};"
        : "+f"(d[0]), "+f"(d[1]), "+f"(d[2]), "+f"(d[3])
        : "r"(a[0]), "r"(a[1]), "r"(a[2]), "r"(a[3]), "r"(b[0]), "r"(b[1]));
}

#define LDSM4(R0, R1, R2, R3, ADDR)                                           \
    asm volatile("ldmatrix.sync.aligned.m8n8.x4.shared.b16 {%0,%1,%2,%3}, [%4];" \
        : "=r"(R0), "=r"(R1), "=r"(R2), "=r"(R3) : "r"(ADDR))
#define LDSM2(R0, R1, ADDR)                                                   \
    asm volatile("ldmatrix.sync.aligned.m8n8.x2.shared.b16 {%0,%1}, [%2];"    \
        : "=r"(R0), "=r"(R1) : "r"(ADDR))

__device__ __forceinline__ uint32_t smem_u32(const void* p) {
    uint32_t a;
    asm("{ .reg .u64 t; cvta.to.shared.u64 t, %1; cvt.u32.u64 %0, t; }"
        : "=r"(a) : "l"(p));
    return a;
}
__device__ __forceinline__ void cp16(uint32_t s, const void* g) {
    asm volatile("cp.async.cg.shared.global [%0], [%1], 16;" :: "r"(s), "l"(g));
}
#define CP_COMMIT() asm volatile("cp.async.commit_group;" ::: "memory")
#define CP_WAIT1()  asm volatile("cp.async.wait_group 1;" ::: "memory")
#define CP_WAIT0()  asm volatile("cp.async.wait_group 0;" ::: "memory")

// Fast (1 + acos(clip(x)))^{-3.2}: Hastings 8-term acos (|err|<=2e-8) + powf
__device__ __forceinline__ float spfns_score(float x) {
    float cc = fminf(fmaxf(x, -1.f + 1e-7f), 1.f - 1e-7f);
    float ax = fabsf(cc);
    float p =              -0.0012624911f;
    p = fmaf(p, ax,         0.0066700901f);
    p = fmaf(p, ax,        -0.0170881256f);
    p = fmaf(p, ax,         0.0308918810f);
    p = fmaf(p, ax,        -0.0501743046f);
    p = fmaf(p, ax,         0.0889789874f);
    p = fmaf(p, ax,        -0.2145988016f);
    p = fmaf(p, ax,         1.5707963050f);
    float s;
    asm("sqrt.approx.f32 %0, %1;" : "=f"(s) : "f"(1.f - ax));
    float r = s * p;
    r = (cc < 0.f) ? (3.14159265358979f - r) : r;
    return __powf(1.f + r, -3.2f);
}

// ---------------------------------------------------------------------------
// f32 -> f16 conversion, 8 elems/thread (n must be divisible by 2048)
// ---------------------------------------------------------------------------
__global__ __launch_bounds__(256)
void f2h_kernel(const float* __restrict__ src, __half* __restrict__ dst)
{
    size_t i = ((size_t)blockIdx.x * 256 + threadIdx.x) * 8;
    float4 v0 = *(const float4*)(src + i);
    float4 v1 = *(const float4*)(src + i + 4);
    __half2 h[4] = { __floats2half2_rn(v0.x, v0.y), __floats2half2_rn(v0.z, v0.w),
                     __floats2half2_rn(v1.x, v1.y), __floats2half2_rn(v1.z, v1.w) };
    *(uint4*)(dst + i) = *(uint4*)h;
}

#define HP 72
#define HSTG 18432   // halves per stage (A 9216 + B 9216)

// ---------------------------------------------------------------------------
// QKV GEMM with FUSED l2-normalization + head split epilogue.
// A = x[4096,1024] fp16, B = w_qkv[3072,1024] fp16, K=1024.
// Block 128x128, 3-stage cp.async, LDSM. Block bx covers 2 heads worth of
// features: bx<8 -> q (normalize->g_qh), bx<16 -> k (->g_kh), else v (->g_v).
// ---------------------------------------------------------------------------
__global__ __launch_bounds__(256, 2)
void qkv_gemm_kernel(const __half* __restrict__ A, const __half* __restrict__ B,
                     const float* __restrict__ bias)
{
    extern __shared__ char smraw[];
    __half* sh = (__half*)smraw;
    float* sbias = (float*)(smraw + 3 * HSTG * 2);

    const int tid = threadIdx.x, wid = tid >> 5, lane = tid & 31;
    const int g = lane >> 2, c = lane & 3;
    const int wm = (wid >> 2) * 64, wn = (wid & 3) * 32;
    const int bx = blockIdx.x;

    if (tid < 128) sbias[tid] = bias[bx * 128 + tid];

    const __half* Ag = A + (size_t)(blockIdx.y * 128) * HID;
    const __half* Bg = B + (size_t)(bx * 128) * HID;
    const uint32_t u0 = smem_u32(sh);
    const int nk = HID >> 6;   // 16

    uint32_t offA[4], offB[2];
    {
        const int rA = lane & 15, kA = (lane >> 4) * 8;
        #pragma unroll
        for (int mt = 0; mt < 4; mt++)
            offA[mt] = (uint32_t)(((wm + mt * 16 + rA) * HP + kA) * 2);
        const int rB = ((lane >> 4) & 1) * 8 + (lane & 7);
        const int kB = ((lane >> 3) & 1) * 8;
        #pragma unroll
        for (int np = 0; np < 2; np++)
            offB[np] = (uint32_t)(((wn + np * 16 + rB) * HP + kB) * 2);
    }

    auto load = [&](int k, int s) {
        const int k0 = k * 64;
        const uint32_t uA = u0 + (uint32_t)s * (HSTG * 2);
        const uint32_t uB = uA + 9216 * 2;
        #pragma unroll
        for (int it = 0; it < 4; it++) {
            int idx = it * 256 + tid;
            int r = idx >> 3, c8 = idx & 7;
            cp16(uA + (uint32_t)(r * HP + c8 * 8) * 2,
                 Ag + (size_t)r * HID + k0 + c8 * 8);
        }
        #pragma unroll
        for (int it = 0; it < 4; it++) {
            int idx = it * 256 + tid;
            int r = idx >> 3, c8 = idx & 7;
            cp16(uB + (uint32_t)(r * HP + c8 * 8) * 2,
                 Bg + (size_t)r * HID + k0 + c8 * 8);
        }
    };

    float acc[4][4][4];
    #pragma unroll
    for (int i = 0; i < 4; i++)
        #pragma unroll
        for (int j = 0; j < 4; j++)
            #pragma unroll
            for (int v = 0; v < 4; v++) acc[i][j][v] = 0.f;

    load(0, 0); CP_COMMIT();
    load(1, 1); CP_COMMIT();

    int s = 0, sn = 2;
    for (int k = 0; k < nk; k++) {
        CP_WAIT1();
        __syncthreads();
        if (k + 2 < nk) load(k + 2, sn);
        CP_COMMIT();

        const uint32_t uA = u0 + (uint32_t)s * (HSTG * 2);
        const uint32_t uB = uA + 9216 * 2;
        #pragma unroll
        for (int ks = 0; ks < 4; ks++) {
            uint32_t a[4][4], b[2][4];
            #pragma unroll
            for (int mt = 0; mt < 4; mt++)
                LDSM4(a[mt][0], a[mt][1], a[mt][2], a[mt][3],
                      uA + offA[mt] + ks * 32);
            #pragma unroll
            for (int np = 0; np < 2; np++)
                LDSM4(b[np][0], b[np][1], b[np][2], b[np][3],
                      uB + offB[np] + ks * 32);
            #pragma unroll
            for (int mt = 0; mt < 4; mt++)
                #pragma unroll
                for (int nt = 0; nt < 4; nt++)
                    mma16(acc[mt][nt], a[mt], &b[nt >> 1][(nt & 1) * 2]);
        }
        s = (s == 2) ? 0 : s + 1;
        sn = (sn == 2) ? 0 : sn + 1;
    }

    // -------- fused epilogue --------
    // add bias
    #pragma unroll
    for (int mt = 0; mt < 4; mt++)
        #pragma unroll
        for (int nt = 0; nt < 4; nt++) {
            int lc = wn + nt * 8 + 2 * c;
            acc[mt][nt][0] += sbias[lc];     acc[mt][nt][1] += sbias[lc + 1];
            acc[mt][nt][2] += sbias[lc];     acc[mt][nt][3] += sbias[lc + 1];
        }

    const int headin = (wid >> 1) & 1;          // head within block (wn>=64)
    const int dloc = (wid & 1) * 32;            // d base for this warp

    if (bx < 16) {
        // q or k: per-(row, head) l2 norm over 64 cols (2 warps), then write
        // ssum reuses stage-1 smem (dead after the last mainloop barrier).
        float* ssum = (float*)(smraw + HSTG * 2);
        float s0[4], s1[4];
        #pragma unroll
        for (int mt = 0; mt < 4; mt++) {
            s0[mt] = 0.f; s1[mt] = 0.f;
            #pragma unroll
            for (int nt = 0; nt < 4; nt++) {
                s0[mt] += acc[mt][nt][0] * acc[mt][nt][0]
                        + acc[mt][nt][1] * acc[mt][nt][1];
                s1[mt] += acc[mt][nt][2] * acc[mt][nt][2]
                        + acc[mt][nt][3] * acc[mt][nt][3];
            }
            s0[mt] += __shfl_xor_sync(0xffffffffu, s0[mt], 1);
            s0[mt] += __shfl_xor_sync(0xffffffffu, s0[mt], 2);
            s1[mt] += __shfl_xor_sync(0xffffffffu, s1[mt], 1);
            s1[mt] += __shfl_xor_sync(0xffffffffu, s1[mt], 2);
        }
        if (c == 0) {
            #pragma unroll
            for (int mt = 0; mt < 4; mt++) {
                ssum[(wm + mt * 16 + g) * 4 + (wid & 3)]     = s0[mt];
                ssum[(wm + mt * 16 + g + 8) * 4 + (wid & 3)] = s1[mt];
            }
        }
        __syncthreads();

        const int sb = wid & 2;
        __half* dstb = (bx < 8) ? g_qh : g_kh;
        const int hglob = (bx & 7) * 2 + headin;
        #pragma unroll
        for (int mt = 0; mt < 4; mt++) {
            int row0 = wm + mt * 16 + g;
            float t0 = ssum[row0 * 4 + sb] + ssum[row0 * 4 + sb + 1];
            float t1 = ssum[(row0 + 8) * 4 + sb] + ssum[(row0 + 8) * 4 + sb + 1];
            float inv0 = 1.f / fmaxf(sqrtf(t0), 1e-12f);
            float inv1 = 1.f / fmaxf(sqrtf(t1), 1e-12f);
            int tok0 = blockIdx.y * 128 + row0;
            int tok1 = tok0 + 8;
            size_t r0 = ((size_t)((tok0 >> 11) * NH + hglob) * SEQ + (tok0 & (SEQ - 1))) * HD;
            size_t r1 = ((size_t)((tok1 >> 11) * NH + hglob) * SEQ + (tok1 & (SEQ - 1))) * HD;
            #pragma unroll
            for (int nt = 0; nt < 4; nt++) {
                int d = dloc + nt * 8 + 2 * c;
                *(__half2*)(dstb + r0 + d) =
                    __floats2half2_rn(acc[mt][nt][0] * inv0, acc[mt][nt][1] * inv0);
                *(__half2*)(dstb + r1 + d) =
                    __floats2half2_rn(acc[mt][nt][2] * inv1, acc[mt][nt][3] * inv1);
            }
        }
    } else {
        // v: write fp32 head-major
        const int hglob = (bx - 16) * 2 + headin;
        #pragma unroll
        for (int mt = 0; mt < 4; mt++) {
            int row0 = wm + mt * 16 + g;
            int tok0 = blockIdx.y * 128 + row0;
            int tok1 = tok0 + 8;
            size_t r0 = ((size_t)((tok0 >> 11) * NH + hglob) * SEQ + (tok0 & (SEQ - 1))) * HD;
            size_t r1 = ((size_t)((tok1 >> 11) * NH + hglob) * SEQ + (tok1 & (SEQ - 1))) * HD;
            #pragma unroll
            for (int nt = 0; nt < 4; nt++) {
                int d = dloc + nt * 8 + 2 * c;
                *(float2*)(g_v + r0 + d) = make_float2(acc[mt][nt][0], acc[mt][nt][1]);
                *(float2*)(g_v + r1 + d) = make_float2(acc[mt][nt][2], acc[mt][nt][3]);
            }
        }
    }
}

// ---------------------------------------------------------------------------
// fp16 GEMM (generic, fp32 out + bias):  C = A @ B^T + bias  (out projection)
// ---------------------------------------------------------------------------
__global__ __launch_bounds__(256, 2)
void hgemm_kernel(const __half* __restrict__ A, const __half* __restrict__ B,
                  const float* __restrict__ bias, float* __restrict__ C,
                  int Ndim, int Kdim)
{
    extern __shared__ char smraw[];
    __half* sh = (__half*)smraw;
    float* sbias = (float*)(smraw + 3 * HSTG * 2);

    const int tid = threadIdx.x, wid = tid >> 5, lane = tid & 31;
    const int g = lane >> 2, c = lane & 3;
    const int wm = (wid >> 2) * 64, wn = (wid & 3) * 32;

    if (tid < 128) sbias[tid] = bias[blockIdx.x * 128 + tid];

    const __half* Ag = A + (size_t)(blockIdx.y * 128) * Kdim;
    const __half* Bg = B + (size_t)(blockIdx.x * 128) * Kdim;
    const uint32_t u0 = smem_u32(sh);
    const int nk = Kdim >> 6;

    uint32_t offA[4], offB[2];
    {
        const int rA = lane & 15, kA = (lane >> 4) * 8;
        #pragma unroll
        for (int mt = 0; mt < 4; mt++)
            offA[mt] = (uint32_t)(((wm + mt * 16 + rA) * HP + kA) * 2);
        const int rB = ((lane >> 4) & 1) * 8 + (lane & 7);
        const int kB = ((lane >> 3) & 1) * 8;
        #pragma unroll
        for (int np = 0; np < 2; np++)
            offB[np] = (uint32_t)(((wn + np * 16 + rB) * HP + kB) * 2);
    }

    auto load = [&](int k, int s) {
        const int k0 = k * 64;
        const uint32_t uA = u0 + (uint32_t)s * (HSTG * 2);
        const uint32_t uB = uA + 9216 * 2;
        #pragma unroll
        for (int it = 0; it < 4; it++) {
            int idx = it * 256 + tid;
            int r = idx >> 3, c8 = idx & 7;
            cp16(uA + (uint32_t)(r * HP + c8 * 8) * 2,
                 Ag + (size_t)r * Kdim + k0 + c8 * 8);
        }
        #pragma unroll
        for (int it = 0; it < 4; it++) {
            int idx = it * 256 + tid;
            int r = idx >> 3, c8 = idx & 7;
            cp16(uB + (uint32_t)(r * HP + c8 * 8) * 2,
                 Bg + (size_t)r * Kdim + k0 + c8 * 8);
        }
    };

    float acc[4][4][4];
    #pragma unroll
    for (int i = 0; i < 4; i++)
        #pragma unroll
        for (int j = 0; j < 4; j++)
            #pragma unroll
            for (int v = 0; v < 4; v++) acc[i][j][v] = 0.f;

    load(0, 0); CP_COMMIT();
    load(1, 1); CP_COMMIT();

    int s = 0, sn = 2;
    for (int k = 0; k < nk; k++) {
        CP_WAIT1();
        __syncthreads();
        if (k + 2 < nk) load(k + 2, sn);
        CP_COMMIT();

        const uint32_t uA = u0 + (uint32_t)s * (HSTG * 2);
        const uint32_t uB = uA + 9216 * 2;
        #pragma unroll
        for (int ks = 0; ks < 4; ks++) {
            uint32_t a[4][4], b[2][4];
            #pragma unroll
            for (int mt = 0; mt < 4; mt++)
                LDSM4(a[mt][0], a[mt][1], a[mt][2], a[mt][3],
                      uA + offA[mt] + ks * 32);
            #pragma unroll
            for (int np = 0; np < 2; np++)
                LDSM4(b[np][0], b[np][1], b[np][2], b[np][3],
                      uB + offB[np] + ks * 32);
            #pragma unroll
            for (int mt = 0; mt < 4; mt++)
                #pragma unroll
                for (int nt = 0; nt < 4; nt++)
                    mma16(acc[mt][nt], a[mt], &b[nt >> 1][(nt & 1) * 2]);
        }
        s = (s == 2) ? 0 : s + 1;
        sn = (sn == 2) ? 0 : sn + 1;
    }

    #pragma unroll
    for (int mt = 0; mt < 4; mt++) {
        int r0 = blockIdx.y * 128 + wm + mt * 16 + g;
        #pragma unroll
        for (int nt = 0; nt < 4; nt++) {
            int lc = wn + nt * 8 + 2 * c;
            int col = blockIdx.x * 128 + lc;
            float b0 = sbias[lc], b1 = sbias[lc + 1];
            float* p0 = C + (size_t)r0 * Ndim + col;
            float* p1 = C + (size_t)(r0 + 8) * Ndim + col;
            p0[0] = acc[mt][nt][0] + b0; p0[1] = acc[mt][nt][1] + b1;
            p1[0] = acc[mt][nt][2] + b0; p1[1] = acc[mt][nt][3] + b1;
        }
    }
}

__global__ void zero_nc_kernel() { g_nc[blockIdx.x * 256 + threadIdx.x] = 0.f; }

// ---------------------------------------------------------------------------
// Score pass (fp16 MMA + LDSM): 128x128 tile of (1+acos(clip(q.k)))^{-3.2},
// fp16 stores + fp32 column sums to g_nc.
// ---------------------------------------------------------------------------
__global__ __launch_bounds__(256)
void score_kernel()
{
    extern __shared__ char smraw[];
    __half* Qs = (__half*)smraw;
    __half* Ks = Qs + 9216;

    const int bh = blockIdx.z;
    const int s0 = blockIdx.y * 128, t0 = blockIdx.x * 128;
    const int tid = threadIdx.x, wid = tid >> 5, lane = tid & 31;
    const int g = lane >> 2, c = lane & 3;
    const int wm = (wid >> 2) * 64, wn = (wid & 3) * 32;
    const __half* Q  = g_qh + (size_t)bh * SEQ * HD;
    const __half* Kp = g_kh + (size_t)bh * SEQ * HD;
    const uint32_t uQ = smem_u32(Qs), uK = smem_u32(Ks);

    #pragma unroll
    for (int it = 0; it < 4; it++) {
        int idx = it * 256 + tid;
        int r = idx >> 3, c8 = idx & 7;
        cp16(uQ + (uint32_t)(r * HP + c8 * 8) * 2, Q  + (size_t)(s0 + r) * HD + c8 * 8);
        cp16(uK + (uint32_t)(r * HP + c8 * 8) * 2, Kp + (size_t)(t0 + r) * HD + c8 * 8);
    }
    CP_COMMIT(); CP_WAIT0();
    __syncthreads();

    uint32_t offA[4], offB[2];
    {
        const int rA = lane & 15, kA = (lane >> 4) * 8;
        #pragma unroll
        for (int mt = 0; mt < 4; mt++)
            offA[mt] = (uint32_t)(((wm + mt * 16 + rA) * HP + kA) * 2);
        const int rB = ((lane >> 4) & 1) * 8 + (lane & 7);
        const int kB = ((lane >> 3) & 1) * 8;
        #pragma unroll
        for (int np = 0; np < 2; np++)
            offB[np] = (uint32_t)(((wn + np * 16 + rB) * HP + kB) * 2);
    }

    float acc[4][4][4];
    #pragma unroll
    for (int i = 0; i < 4; i++)
        #pragma unroll
        for (int j = 0; j < 4; j++)
            #pragma unroll
            for (int v = 0; v < 4; v++) acc[i][j][v] = 0.f;

    #pragma unroll
    for (int ks = 0; ks < 4; ks++) {
        uint32_t a[4][4], b[2][4];
        #pragma unroll
        for (int mt = 0; mt < 4; mt++)
            LDSM4(a[mt][0], a[mt][1], a[mt][2], a[mt][3], uQ + offA[mt] + ks * 32);
        #pragma unroll
        for (int np = 0; np < 2; np++)
            LDSM4(b[np][0], b[np][1], b[np][2], b[np][3], uK + offB[np] + ks * 32);
        #pragma unroll
        for (int mt = 0; mt < 4; mt++)
            #pragma unroll
            for (int nt = 0; nt < 4; nt++)
                mma16(acc[mt][nt], a[mt], &b[nt >> 1][(nt & 1) * 2]);
    }

    float cs[8];
    #pragma unroll
    for (int j = 0; j < 8; j++) cs[j] = 0.f;

    __half* srow = g_scores_h + (size_t)bh * SEQ * SEQ;
    #pragma unroll
    for (int mt = 0; mt < 4; mt++) {
        int r0 = s0 + wm + mt * 16 + g;
        #pragma unroll
        for (int nt = 0; nt < 4; nt++) {
            int col = t0 + wn + nt * 8 + 2 * c;
            float o[4];
            #pragma unroll
            for (int v = 0; v < 4; v++) o[v] = spfns_score(acc[mt][nt][v]);
            *(__half2*)(srow + (size_t)r0 * SEQ + col)       = __floats2half2_rn(o[0], o[1]);
            *(__half2*)(srow + (size_t)(r0 + 8) * SEQ + col) = __floats2half2_rn(o[2], o[3]);
            cs[nt * 2]     += o[0] + o[2];
            cs[nt * 2 + 1] += o[1] + o[3];
        }
    }
    #pragma unroll
    for (int j = 0; j < 8; j++) {
        cs[j] += __shfl_xor_sync(0xffffffffu, cs[j], 4);
        cs[j] += __shfl_xor_sync(0xffffffffu, cs[j], 8);
        cs[j] += __shfl_xor_sync(0xffffffffu, cs[j], 16);
    }
    if (lane < 4) {
        #pragma unroll
        for (int nt = 0; nt < 4; nt++) {
            atomicAdd(&g_nc[bh * SEQ + t0 + wn + nt * 8 + 2 * lane],     cs[nt * 2]);
            atomicAdd(&g_nc[bh * SEQ + t0 + wn + nt * 8 + 2 * lane + 1], cs[nt * 2 + 1]);
        }
    }
}

// ---------------------------------------------------------------------------
// Build V'^T fp16: g_vwT[bh][d][t] = v[t][d]/nc[t] (d<64); 1/nc[t] (d=64);
// 0 (d=65..71). One block per (bh, 64-t chunk).
// ---------------------------------------------------------------------------
__global__ __launch_bounds__(256)
void build_vw_kernel()
{
    __shared__ float vt[64][65];
    __shared__ float ws[64];
    const int bh = blockIdx.y, t0 = blockIdx.x * 64;
    const int tid = threadIdx.x;
    const float* vb = g_v + (size_t)bh * SEQ * HD;
    __half* outb = g_vwT + (size_t)bh * 72 * SEQ;

    if (tid < 64) ws[tid] = 1.f / g_nc[bh * SEQ + t0 + tid];
    #pragma unroll
    for (int q = 0; q < 4; q++) {
        int idx = q * 256 + tid;
        int t = idx >> 4, d4 = (idx & 15) * 4;
        float4 v = *(const float4*)(vb + (size_t)(t0 + t) * HD + d4);
        vt[t][d4] = v.x; vt[t][d4+1] = v.y; vt[t][d4+2] = v.z; vt[t][d4+3] = v.w;
    }
    __syncthreads();

    #pragma unroll
    for (int q = 0; q < 8; q++) {
        int idx = q * 256 + tid;
        int d = idx >> 5, p = (idx & 31) * 2;
        *(__half2*)(outb + (size_t)d * SEQ + t0 + p) =
            __floats2half2_rn(vt[p][d] * ws[p], vt[p + 1][d] * ws[p + 1]);
    }
    {
        int d = 64 + (tid >> 5), p = (tid & 31) * 2;
        __half2 h = (d == 64) ? __floats2half2_rn(ws[p], ws[p + 1])
                              : __floats2half2_rn(0.f, 0.f);
        *(__half2*)(outb + (size_t)d * SEQ + t0 + p) = h;
    }
}

// ---------------------------------------------------------------------------
// PV pass (fp16 HMMA + LDSM): [128 x 2048] S-tile @ [2048 x 72] V' -> 72
// cols, col 64 = denominator. out = num/den -> g_ohh (fp16).
// 3-stage cp.async pipeline, distance-2 prefetch, one sync per iter.
// ---------------------------------------------------------------------------
#define PVP 72
#define PSTG 14400   // halves per stage (S 9216 + V 5184)
__global__ __launch_bounds__(256, 2)
void pv_kernel()
{
    extern __shared__ float smf[];
    __half* sh = (__half*)smf;

    const int s0 = blockIdx.x * 128, bh = blockIdx.y;
    const int b = bh >> 4, h = bh & 15;
    const int tid = threadIdx.x, wid = tid >> 5, lane = tid & 31;
    const int g = lane >> 2, c = lane & 3;
    const int wm = wid * 16;

    const __half* sbase = g_scores_h + (size_t)bh * SEQ * SEQ + (size_t)s0 * SEQ;
    const __half* vwb   = g_vwT + (size_t)bh * 72 * SEQ;
    const uint32_t u0 = smem_u32(sh);

    uint32_t offA, offB[4], offB8;
    {
        const int rA = lane & 15, kA = (lane >> 4) * 8;
        offA = (uint32_t)(((wm + rA) * PVP + kA) * 2);
        const int rB = ((lane >> 4) & 1) * 8 + (lane & 7);
        const int kB = ((lane >> 3) & 1) * 8;
        #pragma unroll
        for (int np = 0; np < 4; np++)
            offB[np] = (uint32_t)(((np * 16 + rB) * PVP + kB) * 2);
        offB8 = (uint32_t)(((64 + (lane & 7)) * PVP + kB) * 2);
    }

    auto load = [&](int it, int st) {
        const int kt = it * 64;
        const uint32_t uS = u0 + (uint32_t)st * (PSTG * 2);
        const uint32_t uV = uS + 9216 * 2;
        #pragma unroll
        for (int q = 0; q < 4; q++) {
            int idx = q * 256 + tid;
            int r = idx >> 3, c4 = idx & 7;
            cp16(uS + (uint32_t)(r * PVP + c4 * 8) * 2,
                 sbase + (size_t)r * SEQ + kt + c4 * 8);
        }
        #pragma unroll
        for (int q = 0; q < 3; q++) {
            int idx = q * 256 + tid;
            if (idx < 576) {
                int r = idx >> 3, c4 = idx & 7;
                cp16(uV + (uint32_t)(r * PVP + c4 * 8) * 2,
                     vwb + (size_t)r * SEQ + kt + c4 * 8);
            }
        }
    };

    float acc[9][4];
    #pragma unroll
    for (int i = 0; i < 9; i++)
        #pragma unroll
        for (int v = 0; v < 4; v++) acc[i][v] = 0.f;

    load(0, 0); CP_COMMIT();
    load(1, 1); CP_COMMIT();

    int st = 0, sn = 2;
    for (int it = 0; it < 32; it++) {
        CP_WAIT1();
        __syncthreads();
        if (it + 2 < 32) load(it + 2, sn);
        CP_COMMIT();

        const uint32_t uS = u0 + (uint32_t)st * (PSTG * 2);
        const uint32_t uV = uS + 9216 * 2;
        #pragma unroll
        for (int ks = 0; ks < 4; ks++) {
            uint32_t a[4];
            LDSM4(a[0], a[1], a[2], a[3], uS + offA + ks * 32);
            uint32_t bb[4][4], b8[2];
            #pragma unroll
            for (int np = 0; np < 4; np++)
                LDSM4(bb[np][0], bb[np][1], bb[np][2], bb[np][3],
                      uV + offB[np] + ks * 32);
            LDSM2(b8[0], b8[1], uV + offB8 + ks * 32);
            #pragma unroll
            for (int nt = 0; nt < 8; nt++)
                mma16(acc[nt], a, &bb[nt >> 1][(nt & 1) * 2]);
            mma16(acc[8], a, b8);
        }
        st = (st == 2) ? 0 : st + 1;
        sn = (sn == 2) ? 0 : sn + 1;
    }

    const int base = lane & ~3;
    float den0 = __shfl_sync(0xffffffffu, acc[8][0], base);
    float den1 = __shfl_sync(0xffffffffu, acc[8][2], base);
    float i0 = 1.f / fmaxf(den0, 1e-12f);
    float i1 = 1.f / fmaxf(den1, 1e-12f);

    const int gr = b * SEQ + s0 + wm + g;
    #pragma unroll
    for (int nt = 0; nt < 8; nt++) {
        __half* p0 = g_ohh + (size_t)gr * HID + h * HD + nt * 8 + 2 * c;
        __half* p1 = g_ohh + (size_t)(gr + 8) * HID + h * HD + nt * 8 + 2 * c;
        *(__half2*)p0 = __floats2half2_rn(acc[nt][0] * i0, acc[nt][1] * i0);
        *(__half2*)p1 = __floats2half2_rn(acc[nt][2] * i1, acc[nt][3] * i1);
    }
}

// ---------------------------------------------------------------------------
extern "C" void kernel_launch(void* const* d_in, const int* in_sizes, int n_in,
                              void* d_out, int out_size)
{
    const float* x      = (const float*)d_in[0];
    const float* w_qkv  = (const float*)d_in[1];
    const float* b_qkv  = (const float*)d_in[2];
    const float* w_out  = (const float*)d_in[3];
    const float* b_out  = (const float*)d_in[4];
    float* out = (float*)d_out;

    void *p_xh = nullptr, *p_wqkvh = nullptr, *p_wouth = nullptr, *p_ohh = nullptr;
    cudaGetSymbolAddress(&p_xh,    g_xh);
    cudaGetSymbolAddress(&p_wqkvh, g_wqkvh);
    cudaGetSymbolAddress(&p_wouth, g_wouth);
    cudaGetSymbolAddress(&p_ohh,   g_ohh);

    const int GEMM_SMEM  = 111104;  // 3 stages * 36864 B + 128 floats bias
    const int SCORE_SMEM = 36864;   // 2*128*72 halves
    const int PV_SMEM    = 86400;   // 3 stages * 28800 B
    static int attr_set = 0;
    if (!attr_set) {
        cudaFuncSetAttribute(qkv_gemm_kernel,
                             cudaFuncAttributeMaxDynamicSharedMemorySize, GEMM_SMEM);
        cudaFuncSetAttribute(hgemm_kernel,
                             cudaFuncAttributeMaxDynamicSharedMemorySize, GEMM_SMEM);
        cudaFuncSetAttribute(score_kernel,
                             cudaFuncAttributeMaxDynamicSharedMemorySize, SCORE_SMEM);
        cudaFuncSetAttribute(pv_kernel,
                             cudaFuncAttributeMaxDynamicSharedMemorySize, PV_SMEM);
        attr_set = 1;
    }

    // 0) fp16 conversions of inputs
    f2h_kernel<<<(MTOK*HID)/2048, 256>>>(x, (__half*)p_xh);
    f2h_kernel<<<(QKV_N*HID)/2048, 256>>>(w_qkv, (__half*)p_wqkvh);
    f2h_kernel<<<(HID*HID)/2048, 256>>>(w_out, (__half*)p_wouth);

    // 1) qkv GEMM with fused l2norm + head split (q,k -> fp16; v -> fp32)
    qkv_gemm_kernel<<<dim3(QKV_N/128, MTOK/128), 256, GEMM_SMEM>>>(
        (const __half*)p_xh, (const __half*)p_wqkvh, b_qkv);

    // 2) scores (fp16 MMA) + column sums
    zero_nc_kernel<<<(BH*SEQ)/256, 256>>>();
    score_kernel<<<dim3(SEQ/128, SEQ/128, BH), 256, SCORE_SMEM>>>();

    // 3) build V' = [V/nc | 1/nc | 0] transposed, fp16
    build_vw_kernel<<<dim3(SEQ/64, BH), 256>>>();

    // 4) PV fp16 GEMM with fused denominator -> g_ohh (fp16)
    pv_kernel<<<dim3(SEQ/128, BH), 256, PV_SMEM>>>();

    // 5) out = oh @ w_out^T + b_out  (fp16 HMMA, fp32 out)
    hgemm_kernel<<<dim3(HID/128, MTOK/128), 256, GEMM_SMEM>>>(
        (const __half*)p_ohh, (const __half*)p_wouth, b_out, out, HID, HID);
}